// round 1
// baseline (speedup 1.0000x reference)
#include <cuda_runtime.h>
#include <math.h>

#define BB 16
#define NN 1024
#define FIN 128
#define HH 32
#define KC 64
#define K2C 16
#define EPSF 1e-15f

// ---------------- device scratch (static, no allocation) ----------------
__device__ float g_x1[BB*NN*HH];          // lin1 output
__device__ float g_s [BB*NN*KC];          // tanh(s1)
__device__ float g_qn[BB*NN];             // ||s_n||^2
__device__ float g_colsum[BB*KC];         // sum_n s[n,k]
__device__ float g_dflat[BB*NN];          // rowsum(adj)
__device__ float g_vol[BB];
__device__ float g_tda[BB];               // sum adj*G
__device__ float g_tdd[BB];               // sum dflat*qn
__device__ float g_adjn[(size_t)BB*NN*NN];// adj_new (64MB)
__device__ float g_Y[BB*NN*HH];           // adj_new @ x1
__device__ float g_x2[BB*NN*HH];          // conv1 output
__device__ float g_s2[BB*NN*K2C];         // softmax(s2)
__device__ float g_s2e[BB*NN*32];         // [s2 | 1 | 0...]
__device__ float g_qs2[BB*NN];            // ||s2_n||^2
__device__ float g_P[BB*NN*32];           // adj_new @ s2e
__device__ float g_ss[BB*KC*KC];          // s^T s
__device__ float g_ss2[BB*K2C*K2C];       // s2^T s2
__device__ float g_oadj[BB*K2C*K2C];      // s2^T A s2
__device__ float g_outx[BB*K2C*HH];       // s2^T x2
__device__ float g_den2[BB];              // mincut denominator

// ---------------- helpers ----------------
__device__ __forceinline__ float blockReduceSum(float v){
    __shared__ float sh[32];
    int tid = threadIdx.x + threadIdx.y*blockDim.x;
    int nth = blockDim.x*blockDim.y;
    int lane = tid & 31, wid = tid >> 5;
    __syncthreads();
    #pragma unroll
    for(int o=16;o;o>>=1) v += __shfl_down_sync(0xffffffffu, v, o);
    if(lane==0) sh[wid] = v;
    __syncthreads();
    float r = (tid < (nth>>5)) ? sh[tid] : 0.f;
    if(wid==0){
        #pragma unroll
        for(int o=16;o;o>>=1) r += __shfl_down_sync(0xffffffffu, r, o);
        if(lane==0) sh[0] = r;
    }
    __syncthreads();
    return sh[0];
}

// ---------------- kernels ----------------
__global__ void zero_kernel(){
    int t = threadIdx.x;
    for(int i=t;i<BB*KC;i+=256) g_colsum[i]=0.f;
    if(t<BB) g_tda[t]=0.f;
}

// warp per row: d_flat = rowsum(adj)
__global__ void rowsum_kernel(const float* __restrict__ adj){
    int warp = threadIdx.x>>5, lane = threadIdx.x&31;
    int row = blockIdx.x*8 + warp;              // row in [0, B*N)
    const float* p = adj + (size_t)row*NN;
    float s = 0.f;
    for(int m=lane;m<NN;m+=32) s += p[m];
    #pragma unroll
    for(int o=16;o;o>>=1) s += __shfl_down_sync(0xffffffffu, s, o);
    if(lane==0) g_dflat[row] = s;
}

__global__ void vol_kernel(){
    int b = blockIdx.x;
    float s = 0.f;
    for(int n=threadIdx.x;n<NN;n+=256) s += g_dflat[b*NN+n];
    s = blockReduceSum(s);
    if(threadIdx.x==0) g_vol[b] = s + (float)NN*EPSF;
}

// x1 = x @ W_lin1 + b  ([B*N,128]@[128,32])
__global__ void lin1_kernel(const float* __restrict__ x, const float* __restrict__ W,
                            const float* __restrict__ bias){
    __shared__ float Ws[FIN*HH];
    __shared__ float xs[8][FIN];
    int tid = threadIdx.x + threadIdx.y*32;
    for(int i=tid;i<FIN*HH;i+=256) Ws[i] = W[i];
    int rowbase = blockIdx.x*8;
    for(int i=tid;i<8*FIN;i+=256){ int r=i>>7,k=i&127; xs[r][k]=x[(size_t)(rowbase+r)*FIN+k]; }
    __syncthreads();
    int c = threadIdx.x, r = threadIdx.y;
    float acc = bias[c];
    #pragma unroll 8
    for(int k=0;k<FIN;k++) acc += xs[r][k]*Ws[k*HH+c];
    g_x1[(rowbase+r)*HH+c] = acc;
}

// s = tanh(x1@W_pool1+b); qn; colsum (atomic)
__global__ void pool1_kernel(const float* __restrict__ W, const float* __restrict__ bias){
    __shared__ float Ws[HH*KC];
    __shared__ float xs[4][HH];
    __shared__ float ssm[4][KC];
    __shared__ float qpart[8];
    int tid = threadIdx.x + threadIdx.y*64;
    for(int i=tid;i<HH*KC;i+=256) Ws[i]=W[i];
    int rowbase = blockIdx.x*4;
    for(int i=tid;i<4*HH;i+=256){ int r=i>>5,k=i&31; xs[r][k]=g_x1[(rowbase+r)*HH+k]; }
    __syncthreads();
    int c = threadIdx.x, r = threadIdx.y;
    float acc = bias[c];
    #pragma unroll 8
    for(int k=0;k<HH;k++) acc += xs[r][k]*Ws[k*KC+c];
    float s = tanhf(acc);
    int grow = rowbase + r;
    g_s[grow*KC + c] = s;
    ssm[r][c] = s;
    float q = s*s;
    #pragma unroll
    for(int o=16;o;o>>=1) q += __shfl_down_sync(0xffffffffu, q, o);
    int lane = tid & 31;
    if(lane==0) qpart[tid>>5] = q;
    __syncthreads();
    if(tid<4) g_qn[rowbase+tid] = qpart[2*tid] + qpart[2*tid+1];
    if(r==0){
        float cs = ssm[0][c]+ssm[1][c]+ssm[2][c]+ssm[3][c];
        int b = grow >> 10;
        atomicAdd(&g_colsum[b*KC + c], cs);
    }
}

// ss = s^T s [B,64,64]
__global__ void ss1_kernel(){
    int b = blockIdx.x, tid = threadIdx.x;     // 1024 threads
    __shared__ float sc[32][KC+1];
    int l = tid & 63, kg = tid >> 6;
    float acc[4] = {0,0,0,0};
    const float* Sb = g_s + b*NN*KC;
    for(int ch=0;ch<NN/32;ch++){
        for(int i=tid;i<32*KC;i+=1024){ int r=i>>6,k=i&63; sc[r][k]=Sb[(ch*32+r)*KC+k]; }
        __syncthreads();
        for(int r=0;r<32;r++){
            float sl = sc[r][l];
            #pragma unroll
            for(int i=0;i<4;i++) acc[i] += sc[r][kg*4+i]*sl;
        }
        __syncthreads();
    }
    #pragma unroll
    for(int i=0;i<4;i++) g_ss[(b*KC + kg*4+i)*KC + l] = acc[i];
}

__global__ void tdd_kernel(){
    int b = blockIdx.x;
    float s = 0.f;
    for(int n=threadIdx.x;n<NN;n+=256) s += g_dflat[b*NN+n]*g_qn[b*NN+n];
    s = blockReduceSum(s);
    if(threadIdx.x==0) g_tdd[b] = s;
}

// Fused: Gram tile -> cdist -> adj_new; accumulate sum(adj*G)
__global__ void ct_main_kernel(const float* __restrict__ adj){
    __shared__ float bufA[64][68];
    __shared__ float bufB[64][68];
    __shared__ float qa[64], qb[64];
    int b = blockIdx.z;
    int rowbase = blockIdx.y*64, colbase = blockIdx.x*64;
    int tx = threadIdx.x, ty = threadIdx.y;     // (16,16)
    int tid = tx + ty*16;
    const float* Sp = g_s + b*NN*KC;
    for(int i=tid;i<64*64;i+=256){ int r=i>>6,k=i&63; bufA[k][r]=Sp[(rowbase+r)*KC+k]; }
    for(int i=tid;i<64*64;i+=256){ int r=i>>6,k=i&63; bufB[k][r]=Sp[(colbase+r)*KC+k]; }
    if(tid<64) qa[tid] = g_qn[b*NN+rowbase+tid];
    else if(tid<128) qb[tid-64] = g_qn[b*NN+colbase+(tid-64)];
    __syncthreads();
    float acc[4][4] = {};
    for(int k=0;k<64;k++){
        float4 av = *(const float4*)&bufA[k][ty*4];
        float4 bv = *(const float4*)&bufB[k][tx*4];
        float a[4] = {av.x,av.y,av.z,av.w};
        float c[4] = {bv.x,bv.y,bv.z,bv.w};
        #pragma unroll
        for(int i=0;i<4;i++)
            #pragma unroll
            for(int j=0;j<4;j++) acc[i][j] += a[i]*c[j];
    }
    __syncthreads();
    // reuse bufA for adj tile (row-major)
    const float* Ap = adj + ((size_t)b*NN)*NN;
    for(int i=tid;i<64*64;i+=256){ int r=i>>6,c=i&63; bufA[r][c]=Ap[(size_t)(rowbase+r)*NN + colbase + c]; }
    __syncthreads();
    float invvol = 1.0f / g_vol[b];
    float tda = 0.f;
    float* Onp = g_adjn + ((size_t)b*NN)*NN;
    #pragma unroll
    for(int i=0;i<4;i++){
        int r = ty*4 + i;
        float4 aj = *(const float4*)&bufA[r][tx*4];
        float ajv[4] = {aj.x,aj.y,aj.z,aj.w};
        float qai = qa[r];
        float rr[4];
        #pragma unroll
        for(int j=0;j<4;j++){
            float g = acc[i][j];
            float d2 = qai + qb[tx*4+j] - 2.0f*g;
            rr[j] = sqrtf(fmaxf(d2, 0.f)) * invvol * ajv[j];
            tda += ajv[j]*g;
        }
        float4 res = {rr[0],rr[1],rr[2],rr[3]};
        *(float4*)&Onp[(size_t)(rowbase+r)*NN + colbase + tx*4] = res;
    }
    tda = blockReduceSum(tda);
    if(tid==0) atomicAdd(&g_tda[b], tda);
}

// O[b] = A[b] @ X[b]  with A [N,N], X [N,32]
__device__ __forceinline__ void bmm_ax_body(const float* __restrict__ A,
                                            const float* __restrict__ X,
                                            float* __restrict__ O){
    __shared__ float adjS[64][68];
    __shared__ float xST[32][68];
    int b = blockIdx.y, rowbase = blockIdx.x*64;
    int tx = threadIdx.x, ty = threadIdx.y;     // (32,8)
    int tid = tx + ty*32;
    const float* Ab = A + ((size_t)b*NN)*NN;
    const float* Xb = X + (size_t)b*NN*32;
    float acc[8] = {};
    for(int kt=0;kt<16;kt++){
        for(int i=tid;i<64*64;i+=256){ int r=i>>6,k=i&63; adjS[r][k]=Ab[(size_t)(rowbase+r)*NN + kt*64 + k]; }
        for(int i=tid;i<64*32;i+=256){ int r=i>>5,c=i&31; xST[c][r]=Xb[(kt*64+r)*32 + c]; }
        __syncthreads();
        for(int kk=0;kk<64;kk+=4){
            float4 xv = *(const float4*)&xST[tx][kk];
            #pragma unroll
            for(int i=0;i<8;i++){
                float4 av = *(const float4*)&adjS[ty*8+i][kk];
                acc[i] += av.x*xv.x + av.y*xv.y + av.z*xv.z + av.w*xv.w;
            }
        }
        __syncthreads();
    }
    float* Ob = O + (size_t)b*NN*32;
    #pragma unroll
    for(int i=0;i<8;i++) Ob[(rowbase+ty*8+i)*32 + tx] = acc[i];
}

__global__ void bmm_Y_kernel(){ bmm_ax_body(g_adjn, g_x1, g_Y); }
__global__ void bmm_P_kernel(){ bmm_ax_body(g_adjn, g_s2e, g_P); }

// x2 = (Y@Wrel + brel) + x1@Wroot ; s2 = softmax(x2@Wp2+bp2); qs2; s2e
__global__ void k4_kernel(const float* __restrict__ Wrel, const float* __restrict__ brel,
                          const float* __restrict__ Wroot, const float* __restrict__ Wp2,
                          const float* __restrict__ bp2){
    __shared__ float Wr[32*32], Wo[32*32], Wp[32*16];
    __shared__ float brs[32], bps[16];
    __shared__ float Ys[8][33], Xs[8][33], x2s[8][33];
    int tx = threadIdx.x, ty = threadIdx.y;
    int tid = tx + ty*32;
    for(int i=tid;i<1024;i+=256){ Wr[i]=Wrel[i]; Wo[i]=Wroot[i]; }
    for(int i=tid;i<512;i+=256) Wp[i]=Wp2[i];
    if(tid<32) brs[tid]=brel[tid];
    if(tid<16) bps[tid]=bp2[tid];
    int rowbase = blockIdx.x*8;
    for(int i=tid;i<8*32;i+=256){ int r=i>>5,c=i&31; Ys[r][c]=g_Y[(rowbase+r)*32+c]; Xs[r][c]=g_x1[(rowbase+r)*32+c]; }
    __syncthreads();
    float acc = brs[tx];
    #pragma unroll 8
    for(int k=0;k<32;k++) acc += Ys[ty][k]*Wr[k*32+tx] + Xs[ty][k]*Wo[k*32+tx];
    int grow = rowbase + ty;
    g_x2[grow*32+tx] = acc;
    x2s[ty][tx] = acc;
    __syncthreads();
    int cc = tx & 15;
    float lg = bps[cc];
    #pragma unroll 8
    for(int k=0;k<32;k++) lg += x2s[ty][k]*Wp[k*16+cc];
    float m = lg;
    #pragma unroll
    for(int o=8;o;o>>=1) m = fmaxf(m, __shfl_xor_sync(0xffffffffu, m, o));
    float e = expf(lg - m);
    float ssum = e;
    #pragma unroll
    for(int o=8;o;o>>=1) ssum += __shfl_xor_sync(0xffffffffu, ssum, o);
    float p = e/ssum;
    if(tx<16){ g_s2[grow*16+tx]=p; g_s2e[grow*32+tx]=p; }
    else g_s2e[grow*32+tx] = (tx==16) ? 1.0f : 0.0f;
    float q = p*p;
    #pragma unroll
    for(int o=8;o;o>>=1) q += __shfl_xor_sync(0xffffffffu, q, o);
    if(tx==0) g_qs2[grow] = q;
}

// per-batch reductions: oadj = s2^T P, ss2 = s2^T s2, outx = s2^T x2
__global__ void k6a_kernel(){
    int b = blockIdx.x, tid = threadIdx.x;      // 1024 threads
    __shared__ float s2c[32][17], x2c[32][33], Pc[32][17];
    float acc = 0.f;
    for(int ch=0;ch<32;ch++){
        int nb = ch*32;
        if(tid<512){ int r=tid>>4,c=tid&15; s2c[r][c]=g_s2[(b*NN+nb+r)*16+c]; }
        { int r=tid>>5,c=tid&31; x2c[r][c]=g_x2[(b*NN+nb+r)*32+c]; }
        if(tid<544){ int r=tid/17,c=tid%17; Pc[r][c]=g_P[(b*NN+nb+r)*32+c]; }
        __syncthreads();
        if(tid<256){
            int k=tid>>4, l=tid&15;
            for(int r=0;r<32;r++) acc += s2c[r][k]*Pc[r][l];
        } else if(tid<512){
            int t=tid-256; int k=t>>4, l=t&15;
            for(int r=0;r<32;r++) acc += s2c[r][k]*s2c[r][l];
        } else {
            int t=tid-512; int k=t>>5, f=t&31;
            for(int r=0;r<32;r++) acc += s2c[r][k]*x2c[r][f];
        }
        __syncthreads();
    }
    if(tid<256) g_oadj[b*256+tid] = acc;
    else if(tid<512) g_ss2[b*256+(tid-256)] = acc;
    else g_outx[b*512+(tid-512)] = acc;
}

__global__ void den2_kernel(){
    int b = blockIdx.x;
    float s = 0.f;
    for(int n=threadIdx.x;n<NN;n+=256)
        s += (g_P[(b*NN+n)*32+16] + EPSF)*g_qs2[b*NN+n];
    s = blockReduceSum(s);
    if(threadIdx.x==0) g_den2[b] = s;
}

// single block: all losses, mincut normalize, conv2, MLP, log_softmax
__global__ void final_kernel(const float* __restrict__ Wrel2, const float* __restrict__ brel2,
                             const float* __restrict__ Wroot2,
                             const float* __restrict__ W2, const float* __restrict__ b2,
                             const float* __restrict__ W3, const float* __restrict__ b3,
                             float* __restrict__ out){
    int tid = threadIdx.x;                       // 256
    // ct_loss
    float v = 0.f;
    if(tid<BB){
        float cs2 = 0.f;
        for(int k=0;k<KC;k++){ float c=g_colsum[tid*KC+k]; cs2 += c*c; }
        float tddf = g_tdd[tid] + EPSF*cs2;
        float num = tddf - g_tda[tid];
        float den = tddf + EPSF;
        v = num/den;
    }
    float ct_loss = blockReduceSum(v)*(1.0f/BB);
    // ortho1 (global Frobenius)
    float accO1 = 0.f;
    for(int b=0;b<BB;b++){
        const float* ssb = g_ss + b*KC*KC;
        float p = 0.f;
        for(int i=tid;i<KC*KC;i+=256){ float x=ssb[i]; p += x*x; }
        float ssn = sqrtf(blockReduceSum(p));
        float inv = 1.0f/ssn;
        p = 0.f;
        for(int i=tid;i<KC*KC;i+=256){
            float d = ssb[i]*inv - ((i%(KC+1))==0 ? 1.0f : 0.0f);
            p += d*d;
        }
        accO1 += blockReduceSum(p);
    }
    float ortho1 = sqrtf(accO1);
    // mincut loss
    v = 0.f;
    if(tid<BB){
        float num = 0.f;
        for(int k=0;k<K2C;k++) num += g_oadj[tid*256 + k*17];
        v = -num/g_den2[tid];
    }
    float mc_loss = blockReduceSum(v)*(1.0f/BB);
    // ortho2 (per-batch mean)
    float accO2 = 0.f;
    for(int b=0;b<BB;b++){
        float x = g_ss2[b*256 + tid];
        float ssn2 = sqrtf(blockReduceSum(x*x));
        float d = x/ssn2 - ((tid%17)==0 ? 0.25f : 0.0f);
        float fb = sqrtf(blockReduceSum(d*d));
        accO2 += fb;
    }
    float ortho2 = accO2*(1.0f/BB);
    // per-batch head
    __shared__ float oa[16][17];
    __shared__ float dk[16], ca[16], mS[32], oS[32], xsum[32], hsh[32], lsh[16];
    for(int b=0;b<BB;b++){
        { int k=tid>>4, l=tid&15; float x=g_oadj[b*256+tid]; if(k==l) x=0.f; oa[k][l]=x; }
        __syncthreads();
        if(tid<16){
            float rs=0.f; for(int l=0;l<16;l++) rs += oa[tid][l];
            dk[tid] = sqrtf(rs + EPSF) + EPSF;
        }
        __syncthreads();
        { int k=tid>>4, l=tid&15; oa[k][l] = oa[k][l]/(dk[k]*dk[l]); }
        __syncthreads();
        if(tid<16){ float c=0.f; for(int k=0;k<16;k++) c += oa[k][tid]; ca[tid]=c; }
        __syncthreads();
        if(tid<32){
            float m=0.f, o=0.f;
            for(int l=0;l<16;l++){ float ox=g_outx[(b*16+l)*32+tid]; m += ca[l]*ox; o += ox; }
            mS[tid]=m; oS[tid]=o;
        }
        __syncthreads();
        if(tid<32){
            float x = 16.0f*brel2[tid];
            for(int g=0;g<32;g++) x += mS[g]*Wrel2[g*32+tid] + oS[g]*Wroot2[g*32+tid];
            xsum[tid] = x;
        }
        __syncthreads();
        if(tid<32){
            float h = b2[tid];
            for(int g=0;g<32;g++) h += xsum[g]*W2[g*32+tid];
            hsh[tid] = fmaxf(h, 0.f);
        }
        __syncthreads();
        if(tid<10){
            float lg = b3[tid];
            for(int g=0;g<32;g++) lg += hsh[g]*W3[g*10+tid];
            lsh[tid] = lg;
        }
        __syncthreads();
        if(tid==0){
            float m = lsh[0];
            for(int o=1;o<10;o++) m = fmaxf(m, lsh[o]);
            float s = 0.f;
            for(int o=0;o<10;o++) s += expf(lsh[o]-m);
            float lse = m + logf(s);
            for(int o=0;o<10;o++) out[b*10+o] = lsh[o]-lse;
        }
        __syncthreads();
    }
    if(tid==0){ out[160] = ct_loss + ortho1; out[161] = mc_loss + ortho2; }
}

// ---------------- launch ----------------
extern "C" void kernel_launch(void* const* d_in, const int* in_sizes, int n_in,
                              void* d_out, int out_size){
    const float* x       = (const float*)d_in[0];
    const float* adj     = (const float*)d_in[1];
    // d_in[2] = mask (all true; unused)
    const float* W_lin1  = (const float*)d_in[3];
    const float* b_lin1  = (const float*)d_in[4];
    const float* W_pool1 = (const float*)d_in[5];
    const float* b_pool1 = (const float*)d_in[6];
    const float* W_pool2 = (const float*)d_in[7];
    const float* b_pool2 = (const float*)d_in[8];
    const float* Wrel1   = (const float*)d_in[9];
    const float* brel1   = (const float*)d_in[10];
    const float* Wroot1  = (const float*)d_in[11];
    const float* Wrel2   = (const float*)d_in[12];
    const float* brel2   = (const float*)d_in[13];
    const float* Wroot2  = (const float*)d_in[14];
    const float* W_lin2  = (const float*)d_in[15];
    const float* b_lin2  = (const float*)d_in[16];
    const float* W_lin3  = (const float*)d_in[17];
    const float* b_lin3  = (const float*)d_in[18];
    float* out = (float*)d_out;

    zero_kernel<<<1,256>>>();
    rowsum_kernel<<<BB*NN/8, 256>>>(adj);
    vol_kernel<<<BB, 256>>>();
    lin1_kernel<<<BB*NN/8, dim3(32,8)>>>(x, W_lin1, b_lin1);
    pool1_kernel<<<BB*NN/4, dim3(64,4)>>>(W_pool1, b_pool1);
    ss1_kernel<<<BB, 1024>>>();
    tdd_kernel<<<BB, 256>>>();
    ct_main_kernel<<<dim3(16,16,BB), dim3(16,16)>>>(adj);
    bmm_Y_kernel<<<dim3(16,BB), dim3(32,8)>>>();
    k4_kernel<<<BB*NN/8, dim3(32,8)>>>(Wrel1, brel1, Wroot1, W_pool2, b_pool2);
    bmm_P_kernel<<<dim3(16,BB), dim3(32,8)>>>();
    k6a_kernel<<<BB, 1024>>>();
    den2_kernel<<<BB, 256>>>();
    final_kernel<<<1, 256>>>(Wrel2, brel2, Wroot2, W_lin2, b_lin2, W_lin3, b_lin3, out);
}

// round 2
// speedup vs baseline: 1.0322x; 1.0322x over previous
#include <cuda_runtime.h>
#include <math.h>

#define BB 16
#define NN 1024
#define FIN 128
#define HH 32
#define KC 64
#define K2C 16
#define EPSF 1e-15f

// ---------------- device scratch (static, no allocation) ----------------
__device__ float g_x1[BB*NN*HH];          // lin1 output
__device__ float g_s [BB*NN*KC];          // tanh(s1)
__device__ float g_qn[BB*NN];             // ||s_n||^2
__device__ float g_colsum[BB*KC];         // sum_n s[n,k]
__device__ float g_dflat[BB*NN];          // rowsum(adj)
__device__ float g_vol[BB];
__device__ float g_tda[BB];               // sum adj*G
__device__ float g_tdd[BB];               // sum dflat*qn
__device__ float g_adjn[(size_t)BB*NN*NN];// adj_new (64MB)
__device__ float g_Y[BB*NN*HH];           // adj_new @ x1
__device__ float g_x2[BB*NN*HH];          // conv1 output
__device__ float g_s2[BB*NN*K2C];         // softmax(s2)
__device__ float g_s2e[BB*NN*32];         // [s2 | 1 | 0...]
__device__ float g_qs2[BB*NN];            // ||s2_n||^2
__device__ float g_P[BB*NN*32];           // adj_new @ s2e
__device__ float g_ss[BB*KC*KC];          // s^T s
__device__ float g_ss2[BB*K2C*K2C];       // s2^T s2
__device__ float g_oadj[BB*K2C*K2C];      // s2^T A s2
__device__ float g_outx[BB*K2C*HH];       // s2^T x2
__device__ float g_den2[BB];              // mincut denominator
__device__ float g_o1b[BB];               // per-batch ortho1 partial (sum diff^2)
__device__ float g_o2b[BB];               // per-batch ortho2 frobenius

// ---------------- helpers ----------------
__device__ __forceinline__ float blockReduceSum(float v){
    __shared__ float sh[32];
    int tid = threadIdx.x + threadIdx.y*blockDim.x;
    int nth = blockDim.x*blockDim.y;
    int lane = tid & 31, wid = tid >> 5;
    __syncthreads();
    #pragma unroll
    for(int o=16;o;o>>=1) v += __shfl_down_sync(0xffffffffu, v, o);
    if(lane==0) sh[wid] = v;
    __syncthreads();
    float r = (tid < (nth>>5)) ? sh[tid] : 0.f;
    if(wid==0){
        #pragma unroll
        for(int o=16;o;o>>=1) r += __shfl_down_sync(0xffffffffu, r, o);
        if(lane==0) sh[0] = r;
    }
    __syncthreads();
    return sh[0];
}

// ---------------- kernels ----------------
__global__ void zero_kernel(){
    int t = threadIdx.x;
    for(int i=t;i<BB*KC;i+=256) g_colsum[i]=0.f;
    if(t<BB) g_tda[t]=0.f;
}

// warp per row: d_flat = rowsum(adj), vectorized
__global__ void rowsum_kernel(const float* __restrict__ adj){
    int warp = threadIdx.x>>5, lane = threadIdx.x&31;
    int row = blockIdx.x*8 + warp;              // row in [0, B*N)
    const float4* p = (const float4*)(adj + (size_t)row*NN);
    float s = 0.f;
    #pragma unroll
    for(int m=lane;m<NN/4;m+=32){ float4 v=p[m]; s += v.x+v.y+v.z+v.w; }
    #pragma unroll
    for(int o=16;o;o>>=1) s += __shfl_down_sync(0xffffffffu, s, o);
    if(lane==0) g_dflat[row] = s;
}

__global__ void vol_kernel(){
    int b = blockIdx.x;
    float s = 0.f;
    for(int n=threadIdx.x;n<NN;n+=256) s += g_dflat[b*NN+n];
    s = blockReduceSum(s);
    if(threadIdx.x==0) g_vol[b] = s + (float)NN*EPSF;
}

// x1 = x @ W_lin1 + b  ([B*N,128]@[128,32]) — 128x32 tile, 4x4/thread
__global__ void lin1_kernel(const float* __restrict__ x, const float* __restrict__ W,
                            const float* __restrict__ bias){
    __shared__ float Ws[FIN][36];
    __shared__ float xt[32][132];
    int tid = threadIdx.x;
    int colg = tid & 7, rowg = tid >> 3;   // 8 col groups x4, 32 row groups x4
    for(int i=tid;i<FIN*32;i+=256){ int k=i>>5,c=i&31; Ws[k][c]=W[k*HH+c]; }
    int rowbase = blockIdx.x*128;
    float acc[4][4] = {};
    #pragma unroll
    for(int kc=0;kc<4;kc++){
        __syncthreads();
        for(int i=tid;i<4096;i+=256){ int r=i>>5,k=i&31; xt[k][r]=x[(size_t)(rowbase+r)*FIN + kc*32 + k]; }
        __syncthreads();
        #pragma unroll 8
        for(int k=0;k<32;k++){
            float4 a = *(const float4*)&xt[k][rowg*4];
            float4 w = *(const float4*)&Ws[kc*32+k][colg*4];
            float av[4]={a.x,a.y,a.z,a.w}, wv[4]={w.x,w.y,w.z,w.w};
            #pragma unroll
            for(int i=0;i<4;i++)
                #pragma unroll
                for(int j=0;j<4;j++) acc[i][j] += av[i]*wv[j];
        }
    }
    float4 bb = *(const float4*)&bias[colg*4];
    float bv[4]={bb.x,bb.y,bb.z,bb.w};
    #pragma unroll
    for(int i=0;i<4;i++){
        float4 res = make_float4(acc[i][0]+bv[0],acc[i][1]+bv[1],acc[i][2]+bv[2],acc[i][3]+bv[3]);
        *(float4*)&g_x1[(rowbase+rowg*4+i)*HH + colg*4] = res;
    }
}

// s = tanh(x1@W_pool1+b); qn; colsum (atomic)
__global__ void pool1_kernel(const float* __restrict__ W, const float* __restrict__ bias){
    __shared__ float Ws[HH*KC];
    __shared__ float xs[4][HH];
    __shared__ float ssm[4][KC];
    __shared__ float qpart[8];
    int tid = threadIdx.x + threadIdx.y*64;
    for(int i=tid;i<HH*KC;i+=256) Ws[i]=W[i];
    int rowbase = blockIdx.x*4;
    for(int i=tid;i<4*HH;i+=256){ int r=i>>5,k=i&31; xs[r][k]=g_x1[(rowbase+r)*HH+k]; }
    __syncthreads();
    int c = threadIdx.x, r = threadIdx.y;
    float acc = bias[c];
    #pragma unroll 8
    for(int k=0;k<HH;k++) acc += xs[r][k]*Ws[k*KC+c];
    float s = tanhf(acc);
    int grow = rowbase + r;
    g_s[grow*KC + c] = s;
    ssm[r][c] = s;
    float q = s*s;
    #pragma unroll
    for(int o=16;o;o>>=1) q += __shfl_down_sync(0xffffffffu, q, o);
    int lane = tid & 31;
    if(lane==0) qpart[tid>>5] = q;
    __syncthreads();
    if(tid<4) g_qn[rowbase+tid] = qpart[2*tid] + qpart[2*tid+1];
    if(r==0){
        float cs = ssm[0][c]+ssm[1][c]+ssm[2][c]+ssm[3][c];
        int b = grow >> 10;
        atomicAdd(&g_colsum[b*KC + c], cs);
    }
}

// ss = s^T s [B,64,64]
__global__ void ss1_kernel(){
    int b = blockIdx.x, tid = threadIdx.x;     // 1024 threads
    __shared__ float sc[32][KC+1];
    int l = tid & 63, kg = tid >> 6;
    float acc[4] = {0,0,0,0};
    const float* Sb = g_s + b*NN*KC;
    for(int ch=0;ch<NN/32;ch++){
        for(int i=tid;i<32*KC;i+=1024){ int r=i>>6,k=i&63; sc[r][k]=Sb[(ch*32+r)*KC+k]; }
        __syncthreads();
        for(int r=0;r<32;r++){
            float sl = sc[r][l];
            #pragma unroll
            for(int i=0;i<4;i++) acc[i] += sc[r][kg*4+i]*sl;
        }
        __syncthreads();
    }
    #pragma unroll
    for(int i=0;i<4;i++) g_ss[(b*KC + kg*4+i)*KC + l] = acc[i];
}

__global__ void tdd_kernel(){
    int b = blockIdx.x;
    float s = 0.f;
    for(int n=threadIdx.x;n<NN;n+=256) s += g_dflat[b*NN+n]*g_qn[b*NN+n];
    s = blockReduceSum(s);
    if(threadIdx.x==0) g_tdd[b] = s;
}

// Fused: Gram 128x128 tile (8x8/thread) -> cdist -> adj_new; accumulate sum(adj*G)
__global__ void ct_main_kernel(const float* __restrict__ adj){
    __shared__ float As[32][132];
    __shared__ float Bs[32][132];
    __shared__ float qa[128], qb[128];
    int b = blockIdx.z;
    int rowbase = blockIdx.y*128, colbase = blockIdx.x*128;
    int tid = threadIdx.x;                      // 256
    int tx = tid & 15, ty = tid >> 4;
    const float* Sp = g_s + b*NN*KC;
    if(tid<128) qa[tid] = g_qn[b*NN+rowbase+tid];
    else qb[tid-128] = g_qn[b*NN+colbase+(tid-128)];
    float acc[8][8] = {};
    #pragma unroll
    for(int kc=0;kc<2;kc++){
        __syncthreads();
        for(int i=tid;i<4096;i+=256){ int r=i>>5,k=i&31; As[k][r]=Sp[(rowbase+r)*KC + kc*32 + k]; }
        for(int i=tid;i<4096;i+=256){ int r=i>>5,k=i&31; Bs[k][r]=Sp[(colbase+r)*KC + kc*32 + k]; }
        __syncthreads();
        #pragma unroll 8
        for(int k=0;k<32;k++){
            float4 a0=*(const float4*)&As[k][ty*8];
            float4 a1=*(const float4*)&As[k][ty*8+4];
            float4 b0=*(const float4*)&Bs[k][tx*8];
            float4 b1=*(const float4*)&Bs[k][tx*8+4];
            float av[8]={a0.x,a0.y,a0.z,a0.w,a1.x,a1.y,a1.z,a1.w};
            float bv[8]={b0.x,b0.y,b0.z,b0.w,b1.x,b1.y,b1.z,b1.w};
            #pragma unroll
            for(int i=0;i<8;i++)
                #pragma unroll
                for(int j=0;j<8;j++) acc[i][j] += av[i]*bv[j];
        }
    }
    float invvol = 1.0f / g_vol[b];
    float tda = 0.f;
    const float* Ap = adj + (size_t)b*NN*NN;
    float* Onp = g_adjn + (size_t)b*NN*NN;
    #pragma unroll
    for(int i=0;i<8;i++){
        size_t rof = (size_t)(rowbase + ty*8 + i)*NN + colbase + tx*8;
        float4 j0 = *(const float4*)&Ap[rof];
        float4 j1 = *(const float4*)&Ap[rof+4];
        float aj[8]={j0.x,j0.y,j0.z,j0.w,j1.x,j1.y,j1.z,j1.w};
        float qai = qa[ty*8+i];
        float rr[8];
        #pragma unroll
        for(int j=0;j<8;j++){
            float g = acc[i][j];
            float d2 = qai + qb[tx*8+j] - 2.0f*g;
            rr[j] = sqrtf(fmaxf(d2, 0.f)) * invvol * aj[j];
            tda += aj[j]*g;
        }
        *(float4*)&Onp[rof]   = make_float4(rr[0],rr[1],rr[2],rr[3]);
        *(float4*)&Onp[rof+4] = make_float4(rr[4],rr[5],rr[6],rr[7]);
    }
    tda = blockReduceSum(tda);
    if(tid==0) atomicAdd(&g_tda[b], tda);
}

// O[b] = A[b] @ X[b],  A [N,N], X [N,32] — 128x32 tile, 4x4/thread
__device__ __forceinline__ void bmm_ax_body(const float* __restrict__ A,
                                            const float* __restrict__ X,
                                            float* __restrict__ O){
    __shared__ float At[32][132];
    __shared__ float Xs[32][36];
    int b = blockIdx.y, rowbase = blockIdx.x*128;
    int tid = threadIdx.x;                      // 256
    int colg = tid & 7, rowg = tid >> 3;
    const float* Ab = A + (size_t)b*NN*NN;
    const float* Xb = X + (size_t)b*NN*32;
    float acc[4][4] = {};
    for(int kt=0;kt<NN;kt+=32){
        __syncthreads();
        for(int i=tid;i<4096;i+=256){ int r=i>>5,k=i&31; At[k][r]=Ab[(size_t)(rowbase+r)*NN + kt + k]; }
        for(int i=tid;i<1024;i+=256){ int r=i>>5,c=i&31; Xs[r][c]=Xb[(kt+r)*32 + c]; }
        __syncthreads();
        #pragma unroll 8
        for(int k=0;k<32;k++){
            float4 a  = *(const float4*)&At[k][rowg*4];
            float4 xv = *(const float4*)&Xs[k][colg*4];
            float av[4]={a.x,a.y,a.z,a.w}, xr[4]={xv.x,xv.y,xv.z,xv.w};
            #pragma unroll
            for(int i=0;i<4;i++)
                #pragma unroll
                for(int j=0;j<4;j++) acc[i][j] += av[i]*xr[j];
        }
    }
    float* Ob = O + (size_t)b*NN*32;
    #pragma unroll
    for(int i=0;i<4;i++){
        float4 res = make_float4(acc[i][0],acc[i][1],acc[i][2],acc[i][3]);
        *(float4*)&Ob[(rowbase+rowg*4+i)*32 + colg*4] = res;
    }
}

__global__ void bmm_Y_kernel(){ bmm_ax_body(g_adjn, g_x1, g_Y); }
__global__ void bmm_P_kernel(){ bmm_ax_body(g_adjn, g_s2e, g_P); }

// x2 = (Y@Wrel + brel) + x1@Wroot ; s2 = softmax(x2@Wp2+bp2); qs2; s2e
__global__ void k4_kernel(const float* __restrict__ Wrel, const float* __restrict__ brel,
                          const float* __restrict__ Wroot, const float* __restrict__ Wp2,
                          const float* __restrict__ bp2){
    __shared__ float Wr[32*32], Wo[32*32], Wp[32*16];
    __shared__ float brs[32], bps[16];
    __shared__ float Ys[8][33], Xs[8][33], x2s[8][33];
    int tx = threadIdx.x, ty = threadIdx.y;
    int tid = tx + ty*32;
    for(int i=tid;i<1024;i+=256){ Wr[i]=Wrel[i]; Wo[i]=Wroot[i]; }
    for(int i=tid;i<512;i+=256) Wp[i]=Wp2[i];
    if(tid<32) brs[tid]=brel[tid];
    if(tid<16) bps[tid]=bp2[tid];
    int rowbase = blockIdx.x*8;
    for(int i=tid;i<8*32;i+=256){ int r=i>>5,c=i&31; Ys[r][c]=g_Y[(rowbase+r)*32+c]; Xs[r][c]=g_x1[(rowbase+r)*32+c]; }
    __syncthreads();
    float acc = brs[tx];
    #pragma unroll 8
    for(int k=0;k<32;k++) acc += Ys[ty][k]*Wr[k*32+tx] + Xs[ty][k]*Wo[k*32+tx];
    int grow = rowbase + ty;
    g_x2[grow*32+tx] = acc;
    x2s[ty][tx] = acc;
    __syncthreads();
    int cc = tx & 15;
    float lg = bps[cc];
    #pragma unroll 8
    for(int k=0;k<32;k++) lg += x2s[ty][k]*Wp[k*16+cc];
    float m = lg;
    #pragma unroll
    for(int o=8;o;o>>=1) m = fmaxf(m, __shfl_xor_sync(0xffffffffu, m, o));
    float e = expf(lg - m);
    float ssum = e;
    #pragma unroll
    for(int o=8;o;o>>=1) ssum += __shfl_xor_sync(0xffffffffu, ssum, o);
    float p = e/ssum;
    if(tx<16){ g_s2[grow*16+tx]=p; g_s2e[grow*32+tx]=p; }
    else g_s2e[grow*32+tx] = (tx==16) ? 1.0f : 0.0f;
    float q = p*p;
    #pragma unroll
    for(int o=8;o;o>>=1) q += __shfl_xor_sync(0xffffffffu, q, o);
    if(tx==0) g_qs2[grow] = q;
}

// per-batch reductions: oadj = s2^T P, ss2 = s2^T s2, outx = s2^T x2
__global__ void k6a_kernel(){
    int b = blockIdx.x, tid = threadIdx.x;      // 1024 threads
    __shared__ float s2c[32][17], x2c[32][33], Pc[32][17];
    float acc = 0.f;
    for(int ch=0;ch<32;ch++){
        int nb = ch*32;
        if(tid<512){ int r=tid>>4,c=tid&15; s2c[r][c]=g_s2[(b*NN+nb+r)*16+c]; }
        { int r=tid>>5,c=tid&31; x2c[r][c]=g_x2[(b*NN+nb+r)*32+c]; }
        if(tid<544){ int r=tid/17,c=tid%17; Pc[r][c]=g_P[(b*NN+nb+r)*32+c]; }
        __syncthreads();
        if(tid<256){
            int k=tid>>4, l=tid&15;
            for(int r=0;r<32;r++) acc += s2c[r][k]*Pc[r][l];
        } else if(tid<512){
            int t=tid-256; int k=t>>4, l=t&15;
            for(int r=0;r<32;r++) acc += s2c[r][k]*s2c[r][l];
        } else {
            int t=tid-512; int k=t>>5, f=t&31;
            for(int r=0;r<32;r++) acc += s2c[r][k]*x2c[r][f];
        }
        __syncthreads();
    }
    if(tid<256) g_oadj[b*256+tid] = acc;
    else if(tid<512) g_ss2[b*256+(tid-256)] = acc;
    else g_outx[b*512+(tid-512)] = acc;
}

__global__ void den2_kernel(){
    int b = blockIdx.x;
    float s = 0.f;
    for(int n=threadIdx.x;n<NN;n+=256)
        s += (g_P[(b*NN+n)*32+16] + EPSF)*g_qs2[b*NN+n];
    s = blockReduceSum(s);
    if(threadIdx.x==0) g_den2[b] = s;
}

// per-batch ortho1 partial
__global__ void ortho1_kernel(){
    int b = blockIdx.x, tid = threadIdx.x;      // 256
    const float* ssb = g_ss + b*KC*KC;
    float p = 0.f;
    for(int i=tid;i<KC*KC;i+=256){ float x=ssb[i]; p += x*x; }
    float ssn = sqrtf(blockReduceSum(p));
    float inv = 1.0f/ssn;
    p = 0.f;
    for(int i=tid;i<KC*KC;i+=256){
        float d = ssb[i]*inv - ((i%(KC+1))==0 ? 1.0f : 0.0f);
        p += d*d;
    }
    p = blockReduceSum(p);
    if(tid==0) g_o1b[b] = p;
}

// per-batch ortho2 frobenius
__global__ void ortho2_kernel(){
    int b = blockIdx.x, tid = threadIdx.x;      // 256
    float x = g_ss2[b*256 + tid];
    float ssn2 = sqrtf(blockReduceSum(x*x));
    float d = x/ssn2 - ((tid%17)==0 ? 0.25f : 0.0f);
    float fb = blockReduceSum(d*d);
    if(tid==0) g_o2b[b] = sqrtf(fb);
}

// per-batch head: mincut normalize, conv2, MLP, log_softmax
__global__ void head_kernel(const float* __restrict__ Wrel2, const float* __restrict__ brel2,
                            const float* __restrict__ Wroot2,
                            const float* __restrict__ W2, const float* __restrict__ b2,
                            const float* __restrict__ W3, const float* __restrict__ b3,
                            float* __restrict__ out){
    int tid = threadIdx.x;                       // 256
    int b = blockIdx.x;
    __shared__ float oa[16][17];
    __shared__ float dk[16], ca[16], mS[32], oS[32], xsum[32], hsh[32], lsh[16];
    { int k=tid>>4, l=tid&15; float x=g_oadj[b*256+tid]; if(k==l) x=0.f; oa[k][l]=x; }
    __syncthreads();
    if(tid<16){
        float rs=0.f; for(int l=0;l<16;l++) rs += oa[tid][l];
        dk[tid] = sqrtf(rs + EPSF) + EPSF;
    }
    __syncthreads();
    { int k=tid>>4, l=tid&15; oa[k][l] = oa[k][l]/(dk[k]*dk[l]); }
    __syncthreads();
    if(tid<16){ float c=0.f; for(int k=0;k<16;k++) c += oa[k][tid]; ca[tid]=c; }
    __syncthreads();
    if(tid<32){
        float m=0.f, o=0.f;
        for(int l=0;l<16;l++){ float ox=g_outx[(b*16+l)*32+tid]; m += ca[l]*ox; o += ox; }
        mS[tid]=m; oS[tid]=o;
    }
    __syncthreads();
    if(tid<32){
        float x = 16.0f*brel2[tid];
        for(int g=0;g<32;g++) x += mS[g]*Wrel2[g*32+tid] + oS[g]*Wroot2[g*32+tid];
        xsum[tid] = x;
    }
    __syncthreads();
    if(tid<32){
        float h = b2[tid];
        for(int g=0;g<32;g++) h += xsum[g]*W2[g*32+tid];
        hsh[tid] = fmaxf(h, 0.f);
    }
    __syncthreads();
    if(tid<10){
        float lg = b3[tid];
        for(int g=0;g<32;g++) lg += hsh[g]*W3[g*10+tid];
        lsh[tid] = lg;
    }
    __syncthreads();
    if(tid==0){
        float m = lsh[0];
        for(int o=1;o<10;o++) m = fmaxf(m, lsh[o]);
        float s = 0.f;
        for(int o=0;o<10;o++) s += expf(lsh[o]-m);
        float lse = m + logf(s);
        for(int o=0;o<10;o++) out[b*10+o] = lsh[o]-lse;
    }
}

// single small block: scalar losses
__global__ void loss_kernel(float* __restrict__ out){
    int tid = threadIdx.x;                       // 256
    float v = 0.f;
    if(tid<BB){
        float cs2 = 0.f;
        for(int k=0;k<KC;k++){ float c=g_colsum[tid*KC+k]; cs2 += c*c; }
        float tddf = g_tdd[tid] + EPSF*cs2;
        float num = tddf - g_tda[tid];
        float den = tddf + EPSF;
        v = num/den;
    }
    float ct_loss = blockReduceSum(v)*(1.0f/BB);
    v = (tid<BB) ? g_o1b[tid] : 0.f;
    float ortho1 = sqrtf(blockReduceSum(v));
    v = 0.f;
    if(tid<BB){
        float num = 0.f;
        for(int k=0;k<K2C;k++) num += g_oadj[tid*256 + k*17];
        v = -num/g_den2[tid];
    }
    float mc_loss = blockReduceSum(v)*(1.0f/BB);
    v = (tid<BB) ? g_o2b[tid] : 0.f;
    float ortho2 = blockReduceSum(v)*(1.0f/BB);
    if(tid==0){ out[160] = ct_loss + ortho1; out[161] = mc_loss + ortho2; }
}

// ---------------- launch ----------------
extern "C" void kernel_launch(void* const* d_in, const int* in_sizes, int n_in,
                              void* d_out, int out_size){
    const float* x       = (const float*)d_in[0];
    const float* adj     = (const float*)d_in[1];
    // d_in[2] = mask (all true; unused)
    const float* W_lin1  = (const float*)d_in[3];
    const float* b_lin1  = (const float*)d_in[4];
    const float* W_pool1 = (const float*)d_in[5];
    const float* b_pool1 = (const float*)d_in[6];
    const float* W_pool2 = (const float*)d_in[7];
    const float* b_pool2 = (const float*)d_in[8];
    const float* Wrel1   = (const float*)d_in[9];
    const float* brel1   = (const float*)d_in[10];
    const float* Wroot1  = (const float*)d_in[11];
    const float* Wrel2   = (const float*)d_in[12];
    const float* brel2   = (const float*)d_in[13];
    const float* Wroot2  = (const float*)d_in[14];
    const float* W_lin2  = (const float*)d_in[15];
    const float* b_lin2  = (const float*)d_in[16];
    const float* W_lin3  = (const float*)d_in[17];
    const float* b_lin3  = (const float*)d_in[18];
    float* out = (float*)d_out;

    zero_kernel<<<1,256>>>();
    rowsum_kernel<<<BB*NN/8, 256>>>(adj);
    vol_kernel<<<BB, 256>>>();
    lin1_kernel<<<BB*NN/128, 256>>>(x, W_lin1, b_lin1);
    pool1_kernel<<<BB*NN/4, dim3(64,4)>>>(W_pool1, b_pool1);
    ss1_kernel<<<BB, 1024>>>();
    tdd_kernel<<<BB, 256>>>();
    ct_main_kernel<<<dim3(8,8,BB), 256>>>(adj);
    bmm_Y_kernel<<<dim3(8,BB), 256>>>();
    k4_kernel<<<BB*NN/8, dim3(32,8)>>>(Wrel1, brel1, Wroot1, W_pool2, b_pool2);
    bmm_P_kernel<<<dim3(8,BB), 256>>>();
    k6a_kernel<<<BB, 1024>>>();
    den2_kernel<<<BB, 256>>>();
    ortho1_kernel<<<BB, 256>>>();
    ortho2_kernel<<<BB, 256>>>();
    head_kernel<<<BB, 256>>>(Wrel2, brel2, Wroot2, W_lin2, b_lin2, W_lin3, b_lin3, out);
    loss_kernel<<<1, 256>>>(out);
}

// round 3
// speedup vs baseline: 1.3731x; 1.3302x over previous
#include <cuda_runtime.h>
#include <math.h>

#define BB 16
#define NN 1024
#define FIN 128
#define HH 32
#define KC 64
#define K2C 16
#define EPSF 1e-15f

// ---------------- device scratch (static, no allocation) ----------------
__device__ float g_x1[BB*NN*HH];          // lin1 output
__device__ float g_s [BB*NN*KC];          // tanh(s1)
__device__ float g_qn[BB*NN];             // ||s_n||^2
__device__ float g_colsum[BB*KC];         // sum_n s[n,k]
__device__ float g_dflat[BB*NN];          // rowsum(adj)
__device__ float g_vol[BB];
__device__ float g_tda[BB];               // sum adj*G
__device__ float g_tdd[BB];               // sum dflat*qn
__device__ float g_adjn[(size_t)BB*NN*NN];// adj_new (64MB)
__device__ float g_Y[BB*NN*HH];           // adj_new @ x1
__device__ float g_x2[BB*NN*HH];          // conv1 output
__device__ float g_s2[BB*NN*K2C];         // softmax(s2)
__device__ float g_s2e[BB*NN*32];         // [s2 | 1 | 0...]
__device__ float g_qs2[BB*NN];            // ||s2_n||^2
__device__ float g_P[BB*NN*32];           // adj_new @ s2e
__device__ float g_ss[BB*KC*KC];          // s^T s (atomic-accumulated)
__device__ float g_red[BB*16*64];         // [b][k][c]: c<16 oadj, 16..31 ss2, 32..63 outx
__device__ float g_den2[BB];              // mincut denominator
__device__ float g_o1b[BB];               // per-batch ortho1 partial
__device__ float g_o2b[BB];               // per-batch ortho2 frobenius

// ---------------- helpers ----------------
__device__ __forceinline__ float blockReduceSum(float v){
    __shared__ float sh[32];
    int tid = threadIdx.x + threadIdx.y*blockDim.x;
    int nth = blockDim.x*blockDim.y;
    int lane = tid & 31, wid = tid >> 5;
    __syncthreads();
    #pragma unroll
    for(int o=16;o;o>>=1) v += __shfl_down_sync(0xffffffffu, v, o);
    if(lane==0) sh[wid] = v;
    __syncthreads();
    float r = (tid < (nth>>5)) ? sh[tid] : 0.f;
    if(wid==0){
        #pragma unroll
        for(int o=16;o;o>>=1) r += __shfl_down_sync(0xffffffffu, r, o);
        if(lane==0) sh[0] = r;
    }
    __syncthreads();
    return sh[0];
}

// ---------------- kernels ----------------
// grid-strided zero of all atomic accumulators
__global__ void zero_kernel(){
    int t = blockIdx.x*256 + threadIdx.x;
    int stride = gridDim.x*256;
    for(int i=t;i<BB*KC;i+=stride) g_colsum[i]=0.f;
    for(int i=t;i<BB;i+=stride) g_tda[i]=0.f;
    for(int i=t;i<BB*KC*KC;i+=stride) g_ss[i]=0.f;
    for(int i=t;i<BB*16*64;i+=stride) g_red[i]=0.f;
}

// warp per row: d_flat = rowsum(adj), vectorized
__global__ void rowsum_kernel(const float* __restrict__ adj){
    int warp = threadIdx.x>>5, lane = threadIdx.x&31;
    int row = blockIdx.x*8 + warp;
    const float4* p = (const float4*)(adj + (size_t)row*NN);
    float s = 0.f;
    #pragma unroll
    for(int m=lane;m<NN/4;m+=32){ float4 v=p[m]; s += v.x+v.y+v.z+v.w; }
    #pragma unroll
    for(int o=16;o;o>>=1) s += __shfl_down_sync(0xffffffffu, s, o);
    if(lane==0) g_dflat[row] = s;
}

__global__ void vol_kernel(){
    int b = blockIdx.x;
    float s = 0.f;
    for(int n=threadIdx.x;n<NN;n+=256) s += g_dflat[b*NN+n];
    s = blockReduceSum(s);
    if(threadIdx.x==0) g_vol[b] = s + (float)NN*EPSF;
}

// x1 = x @ W_lin1 + b : 64-row tile, 128 threads, 4x4/thread
__global__ void lin1_kernel(const float* __restrict__ x, const float* __restrict__ W,
                            const float* __restrict__ bias){
    __shared__ float Ws[FIN][36];
    __shared__ float xt[32][68];
    int tid = threadIdx.x;                 // 128
    int colg = tid & 7, rowg = tid >> 3;   // 8 col groups x4, 16 row groups x4
    for(int i=tid;i<FIN*32;i+=128){ int k=i>>5,c=i&31; Ws[k][c]=W[k*HH+c]; }
    int rowbase = blockIdx.x*64;
    float acc[4][4] = {};
    #pragma unroll
    for(int kc=0;kc<4;kc++){
        __syncthreads();
        for(int i=tid;i<2048;i+=128){ int r=i>>5,k=i&31; xt[k][r]=x[(size_t)(rowbase+r)*FIN + kc*32 + k]; }
        __syncthreads();
        #pragma unroll 8
        for(int k=0;k<32;k++){
            float4 a = *(const float4*)&xt[k][rowg*4];
            float4 w = *(const float4*)&Ws[kc*32+k][colg*4];
            float av[4]={a.x,a.y,a.z,a.w}, wv[4]={w.x,w.y,w.z,w.w};
            #pragma unroll
            for(int i=0;i<4;i++)
                #pragma unroll
                for(int j=0;j<4;j++) acc[i][j] += av[i]*wv[j];
        }
    }
    float4 bb = *(const float4*)&bias[colg*4];
    float bv[4]={bb.x,bb.y,bb.z,bb.w};
    #pragma unroll
    for(int i=0;i<4;i++){
        float4 res = make_float4(acc[i][0]+bv[0],acc[i][1]+bv[1],acc[i][2]+bv[2],acc[i][3]+bv[3]);
        *(float4*)&g_x1[(rowbase+rowg*4+i)*HH + colg*4] = res;
    }
}

// s = tanh(x1@W_pool1+b); qn; colsum (atomic)
__global__ void pool1_kernel(const float* __restrict__ W, const float* __restrict__ bias){
    __shared__ float Ws[HH*KC];
    __shared__ float xs[4][HH];
    __shared__ float ssm[4][KC];
    __shared__ float qpart[8];
    int tid = threadIdx.x + threadIdx.y*64;
    for(int i=tid;i<HH*KC;i+=256) Ws[i]=W[i];
    int rowbase = blockIdx.x*4;
    for(int i=tid;i<4*HH;i+=256){ int r=i>>5,k=i&31; xs[r][k]=g_x1[(rowbase+r)*HH+k]; }
    __syncthreads();
    int c = threadIdx.x, r = threadIdx.y;
    float acc = bias[c];
    #pragma unroll 8
    for(int k=0;k<HH;k++) acc += xs[r][k]*Ws[k*KC+c];
    float s = tanhf(acc);
    int grow = rowbase + r;
    g_s[grow*KC + c] = s;
    ssm[r][c] = s;
    float q = s*s;
    #pragma unroll
    for(int o=16;o;o>>=1) q += __shfl_down_sync(0xffffffffu, q, o);
    int lane = tid & 31;
    if(lane==0) qpart[tid>>5] = q;
    __syncthreads();
    if(tid<4) g_qn[rowbase+tid] = qpart[2*tid] + qpart[2*tid+1];
    if(r==0){
        float cs = ssm[0][c]+ssm[1][c]+ssm[2][c]+ssm[3][c];
        int b = grow >> 10;
        atomicAdd(&g_colsum[b*KC + c], cs);
    }
}

// ss += s^T s over 128-row slices : grid (8, BB), 256 thr, 4x4 tile, atomics
__global__ void ss1_kernel(){
    int b = blockIdx.y, tid = threadIdx.x;      // 256
    int rb = blockIdx.x*128;
    int kg = tid >> 4, lg = tid & 15;           // 16x16 groups of 4
    __shared__ float sc[32][68];
    const float* Sb = g_s + (b*NN + rb)*KC;
    float acc[4][4] = {};
    for(int ch=0;ch<4;ch++){
        __syncthreads();
        for(int i=tid;i<32*KC;i+=256){ int r=i>>6,k=i&63; sc[r][k]=Sb[(ch*32+r)*KC+k]; }
        __syncthreads();
        #pragma unroll 4
        for(int r=0;r<32;r++){
            float4 a = *(const float4*)&sc[r][kg*4];
            float4 c = *(const float4*)&sc[r][lg*4];
            float av[4]={a.x,a.y,a.z,a.w}, cv[4]={c.x,c.y,c.z,c.w};
            #pragma unroll
            for(int i=0;i<4;i++)
                #pragma unroll
                for(int j=0;j<4;j++) acc[i][j] += av[i]*cv[j];
        }
    }
    #pragma unroll
    for(int i=0;i<4;i++)
        #pragma unroll
        for(int j=0;j<4;j++)
            atomicAdd(&g_ss[(b*KC + kg*4+i)*KC + lg*4+j], acc[i][j]);
}

__global__ void tdd_kernel(){
    int b = blockIdx.x;
    float s = 0.f;
    for(int n=threadIdx.x;n<NN;n+=256) s += g_dflat[b*NN+n]*g_qn[b*NN+n];
    s = blockReduceSum(s);
    if(threadIdx.x==0) g_tdd[b] = s;
}

// Fused: Gram 128x128 tile (8x8/thread) -> cdist -> adj_new; accumulate sum(adj*G)
__global__ void ct_main_kernel(const float* __restrict__ adj){
    __shared__ float As[32][132];
    __shared__ float Bs[32][132];
    __shared__ float qa[128], qb[128];
    int b = blockIdx.z;
    int rowbase = blockIdx.y*128, colbase = blockIdx.x*128;
    int tid = threadIdx.x;                      // 256
    int tx = tid & 15, ty = tid >> 4;
    const float* Sp = g_s + b*NN*KC;
    if(tid<128) qa[tid] = g_qn[b*NN+rowbase+tid];
    else qb[tid-128] = g_qn[b*NN+colbase+(tid-128)];
    float acc[8][8] = {};
    #pragma unroll
    for(int kc=0;kc<2;kc++){
        __syncthreads();
        for(int i=tid;i<4096;i+=256){ int r=i>>5,k=i&31; As[k][r]=Sp[(rowbase+r)*KC + kc*32 + k]; }
        for(int i=tid;i<4096;i+=256){ int r=i>>5,k=i&31; Bs[k][r]=Sp[(colbase+r)*KC + kc*32 + k]; }
        __syncthreads();
        #pragma unroll 8
        for(int k=0;k<32;k++){
            float4 a0=*(const float4*)&As[k][ty*8];
            float4 a1=*(const float4*)&As[k][ty*8+4];
            float4 b0=*(const float4*)&Bs[k][tx*8];
            float4 b1=*(const float4*)&Bs[k][tx*8+4];
            float av[8]={a0.x,a0.y,a0.z,a0.w,a1.x,a1.y,a1.z,a1.w};
            float bv[8]={b0.x,b0.y,b0.z,b0.w,b1.x,b1.y,b1.z,b1.w};
            #pragma unroll
            for(int i=0;i<8;i++)
                #pragma unroll
                for(int j=0;j<8;j++) acc[i][j] += av[i]*bv[j];
        }
    }
    float invvol = 1.0f / g_vol[b];
    float tda = 0.f;
    const float* Ap = adj + (size_t)b*NN*NN;
    float* Onp = g_adjn + (size_t)b*NN*NN;
    #pragma unroll
    for(int i=0;i<8;i++){
        size_t rof = (size_t)(rowbase + ty*8 + i)*NN + colbase + tx*8;
        float4 j0 = *(const float4*)&Ap[rof];
        float4 j1 = *(const float4*)&Ap[rof+4];
        float aj[8]={j0.x,j0.y,j0.z,j0.w,j1.x,j1.y,j1.z,j1.w};
        float qai = qa[ty*8+i];
        float rr[8];
        #pragma unroll
        for(int j=0;j<8;j++){
            float g = acc[i][j];
            float d2 = qai + qb[tx*8+j] - 2.0f*g;
            rr[j] = sqrtf(fmaxf(d2, 0.f)) * invvol * aj[j];
            tda += aj[j]*g;
        }
        *(float4*)&Onp[rof]   = make_float4(rr[0],rr[1],rr[2],rr[3]);
        *(float4*)&Onp[rof+4] = make_float4(rr[4],rr[5],rr[6],rr[7]);
    }
    tda = blockReduceSum(tda);
    if(tid==0) atomicAdd(&g_tda[b], tda);
}

// O[b] = A[b] @ X[b],  A [N,N], X [N,32] — 128x32 tile, 4x4/thread, 64-k chunks
__device__ __forceinline__ void bmm_ax_body(const float* __restrict__ A,
                                            const float* __restrict__ X,
                                            float* __restrict__ O){
    __shared__ float At[64][132];
    __shared__ float Xs[64][36];
    int b = blockIdx.y, rowbase = blockIdx.x*128;
    int tid = threadIdx.x;                      // 256
    int colg = tid & 7, rowg = tid >> 3;
    const float* Ab = A + (size_t)b*NN*NN;
    const float* Xb = X + (size_t)b*NN*32;
    float acc[4][4] = {};
    for(int kt=0;kt<NN;kt+=64){
        __syncthreads();
        for(int i=tid;i<8192;i+=256){ int r=i>>6,k=i&63; At[k][r]=Ab[(size_t)(rowbase+r)*NN + kt + k]; }
        for(int i=tid;i<2048;i+=256){ int r=i>>5,c=i&31; Xs[r][c]=Xb[(kt+r)*32 + c]; }
        __syncthreads();
        #pragma unroll 8
        for(int k=0;k<64;k++){
            float4 a  = *(const float4*)&At[k][rowg*4];
            float4 xv = *(const float4*)&Xs[k][colg*4];
            float av[4]={a.x,a.y,a.z,a.w}, xr[4]={xv.x,xv.y,xv.z,xv.w};
            #pragma unroll
            for(int i=0;i<4;i++)
                #pragma unroll
                for(int j=0;j<4;j++) acc[i][j] += av[i]*xr[j];
        }
    }
    float* Ob = O + (size_t)b*NN*32;
    #pragma unroll
    for(int i=0;i<4;i++){
        float4 res = make_float4(acc[i][0],acc[i][1],acc[i][2],acc[i][3]);
        *(float4*)&Ob[(rowbase+rowg*4+i)*32 + colg*4] = res;
    }
}

__global__ void bmm_Y_kernel(){ bmm_ax_body(g_adjn, g_x1, g_Y); }
__global__ void bmm_P_kernel(){ bmm_ax_body(g_adjn, g_s2e, g_P); }

// x2 = (Y@Wrel + brel) + x1@Wroot ; s2 = softmax(x2@Wp2+bp2); qs2; s2e
// 64 rows per block in 8 chunks; weights staged once
__global__ void k4_kernel(const float* __restrict__ Wrel, const float* __restrict__ brel,
                          const float* __restrict__ Wroot, const float* __restrict__ Wp2,
                          const float* __restrict__ bp2){
    __shared__ float Wr[32*32], Wo[32*32], Wp[32*16];
    __shared__ float brs[32], bps[16];
    __shared__ float Ys[8][33], Xs[8][33], x2s[8][33];
    int tx = threadIdx.x, ty = threadIdx.y;
    int tid = tx + ty*32;
    for(int i=tid;i<1024;i+=256){ Wr[i]=Wrel[i]; Wo[i]=Wroot[i]; }
    for(int i=tid;i<512;i+=256) Wp[i]=Wp2[i];
    if(tid<32) brs[tid]=brel[tid];
    if(tid<16) bps[tid]=bp2[tid];
    int rowbase = blockIdx.x*64;
    for(int rc=0;rc<8;rc++){
        int rb = rowbase + rc*8;
        __syncthreads();
        for(int i=tid;i<256;i+=256){ int r=i>>5,c=i&31; Ys[r][c]=g_Y[(rb+r)*32+c]; Xs[r][c]=g_x1[(rb+r)*32+c]; }
        __syncthreads();
        float acc = brs[tx];
        #pragma unroll 8
        for(int k=0;k<32;k++) acc += Ys[ty][k]*Wr[k*32+tx] + Xs[ty][k]*Wo[k*32+tx];
        int grow = rb + ty;
        g_x2[grow*32+tx] = acc;
        x2s[ty][tx] = acc;
        __syncthreads();
        int cc = tx & 15;
        float lg = bps[cc];
        #pragma unroll 8
        for(int k=0;k<32;k++) lg += x2s[ty][k]*Wp[k*16+cc];
        float m = lg;
        #pragma unroll
        for(int o=8;o;o>>=1) m = fmaxf(m, __shfl_xor_sync(0xffffffffu, m, o));
        float e = expf(lg - m);
        float ssum = e;
        #pragma unroll
        for(int o=8;o;o>>=1) ssum += __shfl_xor_sync(0xffffffffu, ssum, o);
        float p = e/ssum;
        if(tx<16){ g_s2[grow*16+tx]=p; g_s2e[grow*32+tx]=p; }
        else g_s2e[grow*32+tx] = (tx==16) ? 1.0f : 0.0f;
        float q = p*p;
        #pragma unroll
        for(int o=8;o;o>>=1) q += __shfl_xor_sync(0xffffffffu, q, o);
        if(tx==0) g_qs2[grow] = q;
    }
}

// red[b][k][c] += s2^T [P(0:16) | s2(16) | x2(32)] over 128-row slices
// grid (8, BB), 256 thr: k=tid>>4 (16), cg=tid&15 (16 groups of 4 cols)
__global__ void k6a_kernel(){
    int b = blockIdx.y, tid = threadIdx.x;      // 256
    int rb = blockIdx.x*128;
    int k = tid >> 4, cg = tid & 15;
    __shared__ float Mc[32][68];
    float acc[4] = {0,0,0,0};
    for(int ch=0;ch<4;ch++){
        int base = b*NN + rb + ch*32;
        __syncthreads();
        for(int i=tid;i<32*64;i+=256){
            int r=i>>6, c=i&63;
            int row = base + r;
            float v;
            if(c<16) v = g_P[row*32 + c];
            else if(c<32) v = g_s2[row*16 + (c-16)];
            else v = g_x2[row*32 + (c-32)];
            Mc[r][c] = v;
        }
        __syncthreads();
        #pragma unroll 4
        for(int r=0;r<32;r++){
            float s2v = Mc[r][16+k];
            float4 m = *(const float4*)&Mc[r][cg*4];
            acc[0] += s2v*m.x; acc[1] += s2v*m.y; acc[2] += s2v*m.z; acc[3] += s2v*m.w;
        }
    }
    #pragma unroll
    for(int j=0;j<4;j++)
        atomicAdd(&g_red[b*1024 + k*64 + cg*4 + j], acc[j]);
}

__global__ void den2_kernel(){
    int b = blockIdx.x;
    float s = 0.f;
    for(int n=threadIdx.x;n<NN;n+=256)
        s += (g_P[(b*NN+n)*32+16] + EPSF)*g_qs2[b*NN+n];
    s = blockReduceSum(s);
    if(threadIdx.x==0) g_den2[b] = s;
}

// per-batch ortho1 partial
__global__ void ortho1_kernel(){
    int b = blockIdx.x, tid = threadIdx.x;      // 256
    const float* ssb = g_ss + b*KC*KC;
    float p = 0.f;
    for(int i=tid;i<KC*KC;i+=256){ float x=ssb[i]; p += x*x; }
    float ssn = sqrtf(blockReduceSum(p));
    float inv = 1.0f/ssn;
    p = 0.f;
    for(int i=tid;i<KC*KC;i+=256){
        float d = ssb[i]*inv - ((i%(KC+1))==0 ? 1.0f : 0.0f);
        p += d*d;
    }
    p = blockReduceSum(p);
    if(tid==0) g_o1b[b] = p;
}

// per-batch ortho2 frobenius (ss2 = red[:, 16:32])
__global__ void ortho2_kernel(){
    int b = blockIdx.x, tid = threadIdx.x;      // 256
    float x = g_red[b*1024 + (tid>>4)*64 + 16 + (tid&15)];
    float ssn2 = sqrtf(blockReduceSum(x*x));
    float d = x/ssn2 - ((tid%17)==0 ? 0.25f : 0.0f);
    float fb = blockReduceSum(d*d);
    if(tid==0) g_o2b[b] = sqrtf(fb);
}

// per-batch head: mincut normalize, conv2, MLP, log_softmax
__global__ void head_kernel(const float* __restrict__ Wrel2, const float* __restrict__ brel2,
                            const float* __restrict__ Wroot2,
                            const float* __restrict__ W2, const float* __restrict__ b2,
                            const float* __restrict__ W3, const float* __restrict__ b3,
                            float* __restrict__ out){
    int tid = threadIdx.x;                       // 256
    int b = blockIdx.x;
    __shared__ float oa[16][17];
    __shared__ float dk[16], ca[16], mS[32], oS[32], xsum[32], hsh[32], lsh[16];
    { int k=tid>>4, l=tid&15; float x=g_red[b*1024 + k*64 + l]; if(k==l) x=0.f; oa[k][l]=x; }
    __syncthreads();
    if(tid<16){
        float rs=0.f; for(int l=0;l<16;l++) rs += oa[tid][l];
        dk[tid] = sqrtf(rs + EPSF) + EPSF;
    }
    __syncthreads();
    { int k=tid>>4, l=tid&15; oa[k][l] = oa[k][l]/(dk[k]*dk[l]); }
    __syncthreads();
    if(tid<16){ float c=0.f; for(int k=0;k<16;k++) c += oa[k][tid]; ca[tid]=c; }
    __syncthreads();
    if(tid<32){
        float m=0.f, o=0.f;
        for(int l=0;l<16;l++){ float ox=g_red[b*1024 + l*64 + 32 + tid]; m += ca[l]*ox; o += ox; }
        mS[tid]=m; oS[tid]=o;
    }
    __syncthreads();
    if(tid<32){
        float x = 16.0f*brel2[tid];
        for(int g=0;g<32;g++) x += mS[g]*Wrel2[g*32+tid] + oS[g]*Wroot2[g*32+tid];
        xsum[tid] = x;
    }
    __syncthreads();
    if(tid<32){
        float h = b2[tid];
        for(int g=0;g<32;g++) h += xsum[g]*W2[g*32+tid];
        hsh[tid] = fmaxf(h, 0.f);
    }
    __syncthreads();
    if(tid<10){
        float lg = b3[tid];
        for(int g=0;g<32;g++) lg += hsh[g]*W3[g*10+tid];
        lsh[tid] = lg;
    }
    __syncthreads();
    if(tid==0){
        float m = lsh[0];
        for(int o=1;o<10;o++) m = fmaxf(m, lsh[o]);
        float s = 0.f;
        for(int o=0;o<10;o++) s += expf(lsh[o]-m);
        float lse = m + logf(s);
        for(int o=0;o<10;o++) out[b*10+o] = lsh[o]-lse;
    }
}

// single small block: scalar losses
__global__ void loss_kernel(float* __restrict__ out){
    int tid = threadIdx.x;                       // 256
    float v = 0.f;
    if(tid<BB){
        float cs2 = 0.f;
        for(int k=0;k<KC;k++){ float c=g_colsum[tid*KC+k]; cs2 += c*c; }
        float tddf = g_tdd[tid] + EPSF*cs2;
        float num = tddf - g_tda[tid];
        float den = tddf + EPSF;
        v = num/den;
    }
    float ct_loss = blockReduceSum(v)*(1.0f/BB);
    v = (tid<BB) ? g_o1b[tid] : 0.f;
    float ortho1 = sqrtf(blockReduceSum(v));
    v = 0.f;
    if(tid<BB){
        float num = 0.f;
        for(int k=0;k<K2C;k++) num += g_red[tid*1024 + k*64 + k];
        v = -num/g_den2[tid];
    }
    float mc_loss = blockReduceSum(v)*(1.0f/BB);
    v = (tid<BB) ? g_o2b[tid] : 0.f;
    float ortho2 = blockReduceSum(v)*(1.0f/BB);
    if(tid==0){ out[160] = ct_loss + ortho1; out[161] = mc_loss + ortho2; }
}

// ---------------- launch ----------------
extern "C" void kernel_launch(void* const* d_in, const int* in_sizes, int n_in,
                              void* d_out, int out_size){
    const float* x       = (const float*)d_in[0];
    const float* adj     = (const float*)d_in[1];
    // d_in[2] = mask (all true; unused)
    const float* W_lin1  = (const float*)d_in[3];
    const float* b_lin1  = (const float*)d_in[4];
    const float* W_pool1 = (const float*)d_in[5];
    const float* b_pool1 = (const float*)d_in[6];
    const float* W_pool2 = (const float*)d_in[7];
    const float* b_pool2 = (const float*)d_in[8];
    const float* Wrel1   = (const float*)d_in[9];
    const float* brel1   = (const float*)d_in[10];
    const float* Wroot1  = (const float*)d_in[11];
    const float* Wrel2   = (const float*)d_in[12];
    const float* brel2   = (const float*)d_in[13];
    const float* Wroot2  = (const float*)d_in[14];
    const float* W_lin2  = (const float*)d_in[15];
    const float* b_lin2  = (const float*)d_in[16];
    const float* W_lin3  = (const float*)d_in[17];
    const float* b_lin3  = (const float*)d_in[18];
    float* out = (float*)d_out;

    zero_kernel<<<32,256>>>();
    rowsum_kernel<<<BB*NN/8, 256>>>(adj);
    vol_kernel<<<BB, 256>>>();
    lin1_kernel<<<BB*NN/64, 128>>>(x, W_lin1, b_lin1);
    pool1_kernel<<<BB*NN/4, dim3(64,4)>>>(W_pool1, b_pool1);
    ss1_kernel<<<dim3(8,BB), 256>>>();
    tdd_kernel<<<BB, 256>>>();
    ct_main_kernel<<<dim3(8,8,BB), 256>>>(adj);
    bmm_Y_kernel<<<dim3(8,BB), 256>>>();
    k4_kernel<<<BB*NN/64, dim3(32,8)>>>(Wrel1, brel1, Wroot1, W_pool2, b_pool2);
    bmm_P_kernel<<<dim3(8,BB), 256>>>();
    k6a_kernel<<<dim3(8,BB), 256>>>();
    den2_kernel<<<BB, 256>>>();
    ortho1_kernel<<<BB, 256>>>();
    ortho2_kernel<<<BB, 256>>>();
    head_kernel<<<BB, 256>>>(Wrel2, brel2, Wroot2, W_lin2, b_lin2, W_lin3, b_lin3, out);
    loss_kernel<<<1, 256>>>(out);
}

// round 4
// speedup vs baseline: 1.7121x; 1.2469x over previous
#include <cuda_runtime.h>
#include <math.h>

#define BB 16
#define NN 1024
#define FIN 128
#define HH 32
#define KC 64
#define K2C 16
#define EPSF 1e-15f

// ---------------- device scratch (static, no allocation) ----------------
__device__ float g_x1[BB*NN*HH];          // lin1 output
__device__ float g_s [BB*NN*KC];          // tanh(s1)
__device__ float g_qn[BB*NN];             // ||s_n||^2
__device__ float g_dflat[BB*NN];          // rowsum(adj)
__device__ float g_vol[BB];
__device__ float g_tda[BB];               // sum adj*G
__device__ float g_tdd[BB];               // sum dflat*qn
__device__ float g_adjn[(size_t)BB*NN*NN];// adj_new (64MB)
__device__ float g_Y[BB*NN*HH];           // adj_new @ x1
__device__ float g_x2[BB*NN*HH];          // conv1 output
__device__ float g_s2[BB*NN*K2C];         // softmax(s2)
__device__ float g_s2e[BB*NN*32];         // [s2 | 1 | 0...]
__device__ float g_qs2[BB*NN];            // ||s2_n||^2
__device__ float g_P[BB*NN*32];           // adj_new @ s2e
__device__ float g_ss[BB*KC*KC];          // s^T s (atomic-accumulated)
__device__ float g_red[BB*16*64];         // [b][k][c]: c<16 oadj, 16..31 ss2, 32..63 outx
__device__ float g_den2[BB];              // mincut denominator
__device__ float g_o1b[BB];               // per-batch ortho1 partial
__device__ float g_o2b[BB];               // per-batch ortho2 frobenius

// ---------------- helpers ----------------
__device__ __forceinline__ float blockReduceSum(float v){
    __shared__ float sh[32];
    int tid = threadIdx.x + threadIdx.y*blockDim.x;
    int nth = blockDim.x*blockDim.y;
    int lane = tid & 31, wid = tid >> 5;
    __syncthreads();
    #pragma unroll
    for(int o=16;o;o>>=1) v += __shfl_down_sync(0xffffffffu, v, o);
    if(lane==0) sh[wid] = v;
    __syncthreads();
    float r = (tid < (nth>>5)) ? sh[tid] : 0.f;
    if(wid==0){
        #pragma unroll
        for(int o=16;o;o>>=1) r += __shfl_down_sync(0xffffffffu, r, o);
        if(lane==0) sh[0] = r;
    }
    __syncthreads();
    return sh[0];
}

// ---------------- kernels ----------------
__global__ void zero_kernel(){
    int t = blockIdx.x*256 + threadIdx.x;
    int stride = gridDim.x*256;
    for(int i=t;i<BB;i+=stride){ g_tda[i]=0.f; g_vol[i]=0.f; g_tdd[i]=0.f; }
    for(int i=t;i<BB*KC*KC;i+=stride) g_ss[i]=0.f;
    for(int i=t;i<BB*16*64;i+=stride) g_red[i]=0.f;
}

// warp per row: d_flat = rowsum(adj); per-block vol partial
__global__ void rowsum_kernel(const float* __restrict__ adj){
    __shared__ float part[8];
    int warp = threadIdx.x>>5, lane = threadIdx.x&31;
    int row = blockIdx.x*8 + warp;
    const float4* p = (const float4*)(adj + (size_t)row*NN);
    float s = 0.f;
    #pragma unroll
    for(int m=lane;m<NN/4;m+=32){ float4 v=p[m]; s += v.x+v.y+v.z+v.w; }
    #pragma unroll
    for(int o=16;o;o>>=1) s += __shfl_down_sync(0xffffffffu, s, o);
    if(lane==0){ g_dflat[row] = s; part[warp] = s; }
    __syncthreads();
    if(threadIdx.x==0){
        float t = 0.f;
        #pragma unroll
        for(int w=0;w<8;w++) t += part[w];
        atomicAdd(&g_vol[(blockIdx.x*8)>>10], t);
    }
}

// Fused: x1 = x@W1+b1 (double-buffered) ; s = tanh(x1@Wp+bp); qn; tdd
// 64 rows/block, 128 threads
__global__ __launch_bounds__(128) void lin1pool_kernel(
        const float* __restrict__ x, const float* __restrict__ W1, const float* __restrict__ b1,
        const float* __restrict__ Wp, const float* __restrict__ bp){
    __shared__ float Ws[FIN][36];
    __shared__ float xt[2][32][68];
    __shared__ float Wps[HH][68];
    __shared__ float bps[KC];
    __shared__ float x1s[64][33];
    int tid = threadIdx.x;                 // 128
    int colg = tid & 7, rowg = tid >> 3;   // 4 cols, 4 rows each
    int rowbase = blockIdx.x*64;
    int b = rowbase >> 10;
    for(int i=tid;i<FIN*32;i+=128){ int k=i>>5,c=i&31; Ws[k][c]=W1[i]; }
    for(int i=tid;i<HH*KC;i+=128){ int k=i>>6,c=i&63; Wps[k][c]=Wp[i]; }
    if(tid<KC) bps[tid]=bp[tid];
    // prefetch kc=0
    for(int i=tid;i<2048;i+=128){ int r=i>>5,k=i&31; xt[0][k][r]=x[(size_t)(rowbase+r)*FIN + k]; }
    float acc[4][4] = {};
    #pragma unroll
    for(int kc=0;kc<4;kc++){
        __syncthreads();
        if(kc<3){
            int nb=(kc+1)&1;
            for(int i=tid;i<2048;i+=128){ int r=i>>5,k=i&31; xt[nb][k][r]=x[(size_t)(rowbase+r)*FIN + (kc+1)*32 + k]; }
        }
        int cb=kc&1;
        #pragma unroll
        for(int k=0;k<32;k++){
            float4 a = *(const float4*)&xt[cb][k][rowg*4];
            float4 w = *(const float4*)&Ws[kc*32+k][colg*4];
            float av[4]={a.x,a.y,a.z,a.w}, wv[4]={w.x,w.y,w.z,w.w};
            #pragma unroll
            for(int i=0;i<4;i++)
                #pragma unroll
                for(int j=0;j<4;j++) acc[i][j] += av[i]*wv[j];
        }
    }
    float4 bb = *(const float4*)&b1[colg*4];
    float bv[4]={bb.x,bb.y,bb.z,bb.w};
    #pragma unroll
    for(int i=0;i<4;i++){
        int lr = rowg*4+i;
        float4 res = make_float4(acc[i][0]+bv[0],acc[i][1]+bv[1],acc[i][2]+bv[2],acc[i][3]+bv[3]);
        *(float4*)&g_x1[(rowbase+lr)*HH + colg*4] = res;
        x1s[lr][colg*4+0]=res.x; x1s[lr][colg*4+1]=res.y;
        x1s[lr][colg*4+2]=res.z; x1s[lr][colg*4+3]=res.w;
    }
    __syncthreads();
    // pool phase: thread -> row r = tid>>1, half = tid&1 (32 cols)
    int r = tid>>1, half = tid&1;
    int cb2 = half*32;
    float sv[32];
    #pragma unroll
    for(int c=0;c<32;c++) sv[c]=bps[cb2+c];
    #pragma unroll
    for(int k=0;k<32;k++){
        float xk = x1s[r][k];
        #pragma unroll
        for(int c4=0;c4<8;c4++){
            float4 w = *(const float4*)&Wps[k][cb2+c4*4];
            sv[c4*4+0] += xk*w.x; sv[c4*4+1] += xk*w.y;
            sv[c4*4+2] += xk*w.z; sv[c4*4+3] += xk*w.w;
        }
    }
    float q = 0.f;
    int grow = rowbase + r;
    #pragma unroll
    for(int c=0;c<32;c++){ float s=tanhf(sv[c]); sv[c]=s; q += s*s; }
    #pragma unroll
    for(int c4=0;c4<8;c4++){
        float4 res = make_float4(sv[c4*4],sv[c4*4+1],sv[c4*4+2],sv[c4*4+3]);
        *(float4*)&g_s[grow*KC + cb2 + c4*4] = res;
    }
    q += __shfl_xor_sync(0xffffffffu, q, 1);
    float v = 0.f;
    if(half==0){ g_qn[grow] = q; v = g_dflat[grow]*q; }
    v = blockReduceSum(v);
    if(tid==0) atomicAdd(&g_tdd[b], v);
}

// ss += s^T s over 128-row slices : grid (8, BB), 256 thr, 4x4 tile, atomics
__global__ void ss1_kernel(){
    int b = blockIdx.y, tid = threadIdx.x;      // 256
    int rb = blockIdx.x*128;
    int kg = tid >> 4, lg = tid & 15;
    __shared__ float sc[32][68];
    const float* Sb = g_s + (b*NN + rb)*KC;
    float acc[4][4] = {};
    for(int ch=0;ch<4;ch++){
        __syncthreads();
        for(int i=tid;i<32*KC;i+=256){ int r=i>>6,k=i&63; sc[r][k]=Sb[(ch*32+r)*KC+k]; }
        __syncthreads();
        #pragma unroll 4
        for(int r=0;r<32;r++){
            float4 a = *(const float4*)&sc[r][kg*4];
            float4 c = *(const float4*)&sc[r][lg*4];
            float av[4]={a.x,a.y,a.z,a.w}, cv[4]={c.x,c.y,c.z,c.w};
            #pragma unroll
            for(int i=0;i<4;i++)
                #pragma unroll
                for(int j=0;j<4;j++) acc[i][j] += av[i]*cv[j];
        }
    }
    #pragma unroll
    for(int i=0;i<4;i++)
        #pragma unroll
        for(int j=0;j<4;j++)
            atomicAdd(&g_ss[(b*KC + kg*4+i)*KC + lg*4+j], acc[i][j]);
}

// Symmetric fused Gram -> cdist -> adj_new for tile pair (ti,tj), ti<=tj.
// grid (36, BB), 256 thr, 8x8 micro-tile.
__global__ __launch_bounds__(256,2) void ct_main_kernel(const float* __restrict__ adj){
    __shared__ float As[32][132];
    __shared__ float Bs[32][132];
    __shared__ float qa[128], qb[128];
    int b = blockIdx.y;
    int p = blockIdx.x, ti = 0;
    while(p >= 8-ti){ p -= 8-ti; ti++; }
    int tj = ti + p;
    int rowbase = ti*128, colbase = tj*128;
    int tid = threadIdx.x;
    int tx = tid & 15, ty = tid >> 4;
    const float* Sp = g_s + b*NN*KC;
    if(tid<128) qa[tid] = g_qn[b*NN+rowbase+tid];
    else qb[tid-128] = g_qn[b*NN+colbase+(tid-128)];
    float acc[8][8] = {};
    #pragma unroll
    for(int kc=0;kc<2;kc++){
        __syncthreads();
        for(int i=tid;i<4096;i+=256){ int r=i>>5,k=i&31; As[k][r]=Sp[(rowbase+r)*KC + kc*32 + k]; }
        for(int i=tid;i<4096;i+=256){ int r=i>>5,k=i&31; Bs[k][r]=Sp[(colbase+r)*KC + kc*32 + k]; }
        __syncthreads();
        #pragma unroll 8
        for(int k=0;k<32;k++){
            float4 a0=*(const float4*)&As[k][ty*8];
            float4 a1=*(const float4*)&As[k][ty*8+4];
            float4 b0=*(const float4*)&Bs[k][tx*8];
            float4 b1=*(const float4*)&Bs[k][tx*8+4];
            float av[8]={a0.x,a0.y,a0.z,a0.w,a1.x,a1.y,a1.z,a1.w};
            float bv[8]={b0.x,b0.y,b0.z,b0.w,b1.x,b1.y,b1.z,b1.w};
            #pragma unroll
            for(int i=0;i<8;i++)
                #pragma unroll
                for(int j=0;j<8;j++) acc[i][j] += av[i]*bv[j];
        }
    }
    float invvol = 1.0f / g_vol[b];
    float tda = 0.f;
    const float* Ap = adj + (size_t)b*NN*NN;
    float* Onp = g_adjn + (size_t)b*NN*NN;
    // direct tile (rows rowbase.., cols colbase..)
    #pragma unroll
    for(int i=0;i<8;i++){
        size_t rof = (size_t)(rowbase + ty*8 + i)*NN + colbase + tx*8;
        float4 j0 = *(const float4*)&Ap[rof];
        float4 j1 = *(const float4*)&Ap[rof+4];
        float aj[8]={j0.x,j0.y,j0.z,j0.w,j1.x,j1.y,j1.z,j1.w};
        float qai = qa[ty*8+i];
        float rr[8];
        #pragma unroll
        for(int j=0;j<8;j++){
            float g = acc[i][j];
            float d2 = qai + qb[tx*8+j] - 2.0f*g;
            rr[j] = sqrtf(fmaxf(d2, 0.f)) * invvol * aj[j];
            tda += aj[j]*g;
        }
        *(float4*)&Onp[rof]   = make_float4(rr[0],rr[1],rr[2],rr[3]);
        *(float4*)&Onp[rof+4] = make_float4(rr[4],rr[5],rr[6],rr[7]);
    }
    if(ti != tj){
        // mirror tile (rows colbase.., cols rowbase..): cdist^T * adj(c,r)
        #pragma unroll
        for(int jj=0;jj<8;jj++){
            size_t rof = (size_t)(colbase + tx*8 + jj)*NN + rowbase + ty*8;
            float4 t0 = *(const float4*)&Ap[rof];
            float4 t1 = *(const float4*)&Ap[rof+4];
            float aj[8]={t0.x,t0.y,t0.z,t0.w,t1.x,t1.y,t1.z,t1.w};
            float qbj = qb[tx*8+jj];
            float rr[8];
            #pragma unroll
            for(int ii=0;ii<8;ii++){
                float g = acc[ii][jj];
                float d2 = qa[ty*8+ii] + qbj - 2.0f*g;
                rr[ii] = sqrtf(fmaxf(d2, 0.f)) * invvol * aj[ii];
                tda += aj[ii]*g;
            }
            *(float4*)&Onp[rof]   = make_float4(rr[0],rr[1],rr[2],rr[3]);
            *(float4*)&Onp[rof+4] = make_float4(rr[4],rr[5],rr[6],rr[7]);
        }
    }
    tda = blockReduceSum(tda);
    if(tid==0) atomicAdd(&g_tda[b], tda);
}

// O[b] = A[b] @ X[b], A [N,N], X [N,32] — 64x32 tile, grid (16,BB), 256 thr,
// 2x4 micro-tile, double-buffered 64-k chunks
__device__ __forceinline__ void bmm_ax_body(const float* __restrict__ A,
                                            const float* __restrict__ X,
                                            float* __restrict__ O){
    __shared__ float At[2][64][68];
    __shared__ float Xs[2][64][36];
    int b = blockIdx.y, rowbase = blockIdx.x*64;
    int tid = threadIdx.x;                      // 256
    int colg = tid & 7, rowg = tid >> 3;        // 4 cols, 2 rows
    const float* Ab = A + (size_t)b*NN*NN;
    const float* Xb = X + (size_t)b*NN*32;
    float acc[2][4] = {};
    for(int i=tid;i<4096;i+=256){ int r=i>>6,k=i&63; At[0][k][r]=Ab[(size_t)(rowbase+r)*NN + k]; }
    for(int i=tid;i<2048;i+=256){ int r=i>>5,c=i&31; Xs[0][r][c]=Xb[r*32+c]; }
    for(int kt=0;kt<16;kt++){
        __syncthreads();
        if(kt<15){
            int nb=(kt+1)&1, ko=(kt+1)*64;
            for(int i=tid;i<4096;i+=256){ int r=i>>6,k=i&63; At[nb][k][r]=Ab[(size_t)(rowbase+r)*NN + ko + k]; }
            for(int i=tid;i<2048;i+=256){ int r=i>>5,c=i&31; Xs[nb][r][c]=Xb[(ko+r)*32+c]; }
        }
        int cb=kt&1;
        #pragma unroll 8
        for(int k=0;k<64;k++){
            float2 a  = *(const float2*)&At[cb][k][rowg*2];
            float4 xv = *(const float4*)&Xs[cb][k][colg*4];
            acc[0][0] += a.x*xv.x; acc[0][1] += a.x*xv.y; acc[0][2] += a.x*xv.z; acc[0][3] += a.x*xv.w;
            acc[1][0] += a.y*xv.x; acc[1][1] += a.y*xv.y; acc[1][2] += a.y*xv.z; acc[1][3] += a.y*xv.w;
        }
    }
    float* Ob = O + (size_t)b*NN*32;
    #pragma unroll
    for(int i=0;i<2;i++){
        float4 res = make_float4(acc[i][0],acc[i][1],acc[i][2],acc[i][3]);
        *(float4*)&Ob[(rowbase+rowg*2+i)*32 + colg*4] = res;
    }
}

__global__ __launch_bounds__(256) void bmm_Y_kernel(){ bmm_ax_body(g_adjn, g_x1, g_Y); }
__global__ __launch_bounds__(256) void bmm_P_kernel(){ bmm_ax_body(g_adjn, g_s2e, g_P); }

// x2 = (Y@Wrel + brel) + x1@Wroot ; s2 = softmax(x2@Wp2+bp2); qs2; s2e
// 64 rows per block, single chunk, grid 256 x 256thr
__global__ __launch_bounds__(256) void k4_kernel(
        const float* __restrict__ Wrel, const float* __restrict__ brel,
        const float* __restrict__ Wroot, const float* __restrict__ Wp2,
        const float* __restrict__ bp2){
    __shared__ float Wr[32][33], Wo[32][33], Wp[32][17];
    __shared__ float brs[32], bps[16];
    __shared__ float Ys[64][33], Xs[64][33], x2s[64][33], lgS[64][17];
    int tid = threadIdx.x;
    for(int i=tid;i<1024;i+=256){ int k=i>>5,c=i&31; Wr[k][c]=Wrel[i]; Wo[k][c]=Wroot[i]; }
    for(int i=tid;i<512;i+=256){ int k=i>>4,c=i&15; Wp[k][c]=Wp2[i]; }
    if(tid<32) brs[tid]=brel[tid];
    if(tid<16) bps[tid]=bp2[tid];
    int rowbase = blockIdx.x*64;
    for(int i=tid;i<2048;i+=256){ int r=i>>5,c=i&31;
        Ys[r][c]=g_Y[(rowbase+r)*32+c]; Xs[r][c]=g_x1[(rowbase+r)*32+c]; }
    __syncthreads();
    // x2: thread = (col = tid&31, rg = tid>>5), 8 rows each
    {
        int col = tid & 31, rg = tid >> 5;
        float a8[8];
        #pragma unroll
        for(int rr=0;rr<8;rr++) a8[rr] = brs[col];
        #pragma unroll
        for(int k=0;k<32;k++){
            float wr = Wr[k][col], wo = Wo[k][col];
            #pragma unroll
            for(int rr=0;rr<8;rr++){
                int row = rg*8+rr;
                a8[rr] += Ys[row][k]*wr + Xs[row][k]*wo;
            }
        }
        #pragma unroll
        for(int rr=0;rr<8;rr++){
            int row = rg*8+rr;
            x2s[row][col] = a8[rr];
            g_x2[(rowbase+row)*32+col] = a8[rr];
        }
    }
    __syncthreads();
    // logits: thread = (row = tid>>2, 4 cols)
    {
        int row = tid>>2, cq = tid&3;
        float lg[4];
        #pragma unroll
        for(int c=0;c<4;c++) lg[c]=bps[cq*4+c];
        #pragma unroll
        for(int k=0;k<32;k++){
            float xv = x2s[row][k];
            #pragma unroll
            for(int c=0;c<4;c++) lg[c] += xv*Wp[k][cq*4+c];
        }
        #pragma unroll
        for(int c=0;c<4;c++) lgS[row][cq*4+c]=lg[c];
    }
    __syncthreads();
    if(tid<64){
        int row = tid, grow = rowbase + row;
        float m = lgS[row][0];
        #pragma unroll
        for(int j=1;j<16;j++) m = fmaxf(m, lgS[row][j]);
        float e[16], sum=0.f;
        #pragma unroll
        for(int j=0;j<16;j++){ e[j]=expf(lgS[row][j]-m); sum+=e[j]; }
        float inv = 1.0f/sum, q=0.f;
        #pragma unroll
        for(int j=0;j<16;j++){
            float pv = e[j]*inv;
            g_s2[grow*16+j]=pv; g_s2e[grow*32+j]=pv; q += pv*pv;
        }
        g_s2e[grow*32+16]=1.0f;
        #pragma unroll
        for(int j=17;j<32;j++) g_s2e[grow*32+j]=0.0f;
        g_qs2[grow]=q;
    }
}

// red[b][k][c] += s2^T [P(0:16) | s2(16) | x2(32)] over 128-row slices
__global__ void k6a_kernel(){
    int b = blockIdx.y, tid = threadIdx.x;      // 256
    int rb = blockIdx.x*128;
    int k = tid >> 4, cg = tid & 15;
    __shared__ float Mc[32][68];
    float acc[4] = {0,0,0,0};
    for(int ch=0;ch<4;ch++){
        int base = b*NN + rb + ch*32;
        __syncthreads();
        for(int i=tid;i<32*64;i+=256){
            int r=i>>6, c=i&63;
            int row = base + r;
            float v;
            if(c<16) v = g_P[row*32 + c];
            else if(c<32) v = g_s2[row*16 + (c-16)];
            else v = g_x2[row*32 + (c-32)];
            Mc[r][c] = v;
        }
        __syncthreads();
        #pragma unroll 4
        for(int r=0;r<32;r++){
            float s2v = Mc[r][16+k];
            float4 m = *(const float4*)&Mc[r][cg*4];
            acc[0] += s2v*m.x; acc[1] += s2v*m.y; acc[2] += s2v*m.z; acc[3] += s2v*m.w;
        }
    }
    #pragma unroll
    for(int j=0;j<4;j++)
        atomicAdd(&g_red[b*1024 + k*64 + cg*4 + j], acc[j]);
}

__global__ void den2_kernel(){
    int b = blockIdx.x;
    float s = 0.f;
    for(int n=threadIdx.x;n<NN;n+=256)
        s += (g_P[(b*NN+n)*32+16] + EPSF)*g_qs2[b*NN+n];
    s = blockReduceSum(s);
    if(threadIdx.x==0) g_den2[b] = s;
}

__global__ void ortho1_kernel(){
    int b = blockIdx.x, tid = threadIdx.x;      // 256
    const float* ssb = g_ss + b*KC*KC;
    float p = 0.f;
    for(int i=tid;i<KC*KC;i+=256){ float x=ssb[i]; p += x*x; }
    float ssn = sqrtf(blockReduceSum(p));
    float inv = 1.0f/ssn;
    p = 0.f;
    for(int i=tid;i<KC*KC;i+=256){
        float d = ssb[i]*inv - ((i%(KC+1))==0 ? 1.0f : 0.0f);
        p += d*d;
    }
    p = blockReduceSum(p);
    if(tid==0) g_o1b[b] = p;
}

__global__ void ortho2_kernel(){
    int b = blockIdx.x, tid = threadIdx.x;      // 256
    float x = g_red[b*1024 + (tid>>4)*64 + 16 + (tid&15)];
    float ssn2 = sqrtf(blockReduceSum(x*x));
    float d = x/ssn2 - ((tid%17)==0 ? 0.25f : 0.0f);
    float fb = blockReduceSum(d*d);
    if(tid==0) g_o2b[b] = sqrtf(fb);
}

// per-batch head: mincut normalize, conv2, MLP, log_softmax
__global__ void head_kernel(const float* __restrict__ Wrel2, const float* __restrict__ brel2,
                            const float* __restrict__ Wroot2,
                            const float* __restrict__ W2, const float* __restrict__ b2,
                            const float* __restrict__ W3, const float* __restrict__ b3,
                            float* __restrict__ out){
    int tid = threadIdx.x;                       // 256
    int b = blockIdx.x;
    __shared__ float oa[16][17];
    __shared__ float dk[16], ca[16], mS[32], oS[32], xsum[32], hsh[32], lsh[16];
    { int k=tid>>4, l=tid&15; float x=g_red[b*1024 + k*64 + l]; if(k==l) x=0.f; oa[k][l]=x; }
    __syncthreads();
    if(tid<16){
        float rs=0.f; for(int l=0;l<16;l++) rs += oa[tid][l];
        dk[tid] = sqrtf(rs + EPSF) + EPSF;
    }
    __syncthreads();
    { int k=tid>>4, l=tid&15; oa[k][l] = oa[k][l]/(dk[k]*dk[l]); }
    __syncthreads();
    if(tid<16){ float c=0.f; for(int k=0;k<16;k++) c += oa[k][tid]; ca[tid]=c; }
    __syncthreads();
    if(tid<32){
        float m=0.f, o=0.f;
        for(int l=0;l<16;l++){ float ox=g_red[b*1024 + l*64 + 32 + tid]; m += ca[l]*ox; o += ox; }
        mS[tid]=m; oS[tid]=o;
    }
    __syncthreads();
    if(tid<32){
        float x = 16.0f*brel2[tid];
        for(int g=0;g<32;g++) x += mS[g]*Wrel2[g*32+tid] + oS[g]*Wroot2[g*32+tid];
        xsum[tid] = x;
    }
    __syncthreads();
    if(tid<32){
        float h = b2[tid];
        for(int g=0;g<32;g++) h += xsum[g]*W2[g*32+tid];
        hsh[tid] = fmaxf(h, 0.f);
    }
    __syncthreads();
    if(tid<10){
        float lg = b3[tid];
        for(int g=0;g<32;g++) lg += hsh[g]*W3[g*10+tid];
        lsh[tid] = lg;
    }
    __syncthreads();
    if(tid==0){
        float m = lsh[0];
        for(int o=1;o<10;o++) m = fmaxf(m, lsh[o]);
        float s = 0.f;
        for(int o=0;o<10;o++) s += expf(lsh[o]-m);
        float lse = m + logf(s);
        for(int o=0;o<10;o++) out[b*10+o] = lsh[o]-lse;
    }
}

__global__ void loss_kernel(float* __restrict__ out){
    int tid = threadIdx.x;                       // 256
    float v = 0.f;
    if(tid<BB){
        float tddf = g_tdd[tid];
        v = (tddf - g_tda[tid])/(tddf + EPSF);
    }
    float ct_loss = blockReduceSum(v)*(1.0f/BB);
    v = (tid<BB) ? g_o1b[tid] : 0.f;
    float ortho1 = sqrtf(blockReduceSum(v));
    v = 0.f;
    if(tid<BB){
        float num = 0.f;
        for(int k=0;k<K2C;k++) num += g_red[tid*1024 + k*64 + k];
        v = -num/g_den2[tid];
    }
    float mc_loss = blockReduceSum(v)*(1.0f/BB);
    v = (tid<BB) ? g_o2b[tid] : 0.f;
    float ortho2 = blockReduceSum(v)*(1.0f/BB);
    if(tid==0){ out[160] = ct_loss + ortho1; out[161] = mc_loss + ortho2; }
}

// ---------------- launch ----------------
extern "C" void kernel_launch(void* const* d_in, const int* in_sizes, int n_in,
                              void* d_out, int out_size){
    const float* x       = (const float*)d_in[0];
    const float* adj     = (const float*)d_in[1];
    const float* W_lin1  = (const float*)d_in[3];
    const float* b_lin1  = (const float*)d_in[4];
    const float* W_pool1 = (const float*)d_in[5];
    const float* b_pool1 = (const float*)d_in[6];
    const float* W_pool2 = (const float*)d_in[7];
    const float* b_pool2 = (const float*)d_in[8];
    const float* Wrel1   = (const float*)d_in[9];
    const float* brel1   = (const float*)d_in[10];
    const float* Wroot1  = (const float*)d_in[11];
    const float* Wrel2   = (const float*)d_in[12];
    const float* brel2   = (const float*)d_in[13];
    const float* Wroot2  = (const float*)d_in[14];
    const float* W_lin2  = (const float*)d_in[15];
    const float* b_lin2  = (const float*)d_in[16];
    const float* W_lin3  = (const float*)d_in[17];
    const float* b_lin3  = (const float*)d_in[18];
    float* out = (float*)d_out;

    zero_kernel<<<32,256>>>();
    rowsum_kernel<<<BB*NN/8, 256>>>(adj);
    lin1pool_kernel<<<BB*NN/64, 128>>>(x, W_lin1, b_lin1, W_pool1, b_pool1);
    ss1_kernel<<<dim3(8,BB), 256>>>();
    ct_main_kernel<<<dim3(36,BB), 256>>>(adj);
    bmm_Y_kernel<<<dim3(16,BB), 256>>>();
    k4_kernel<<<BB*NN/64, 256>>>(Wrel1, brel1, Wroot1, W_pool2, b_pool2);
    bmm_P_kernel<<<dim3(16,BB), 256>>>();
    k6a_kernel<<<dim3(8,BB), 256>>>();
    den2_kernel<<<BB, 256>>>();
    ortho1_kernel<<<BB, 256>>>();
    ortho2_kernel<<<BB, 256>>>();
    head_kernel<<<BB, 256>>>(Wrel2, brel2, Wroot2, W_lin2, b_lin2, W_lin3, b_lin3, out);
    loss_kernel<<<1, 256>>>(out);
}

// round 6
// speedup vs baseline: 1.7497x; 1.0219x over previous
#include <cuda_runtime.h>
#include <cuda_fp16.h>
#include <math.h>

#define BB 16
#define NN 1024
#define FIN 128
#define HH 32
#define KC 64
#define K2C 16
#define EPSF 1e-15f

// ---------------- device scratch ----------------
__device__ float g_x1[BB*NN*HH];
__device__ float g_s [BB*NN*KC];
__device__ float g_qn[BB*NN];
__device__ float g_dflat[BB*NN];          // rowsum(adj), atomic
__device__ float g_vol[BB];               // atomic
__device__ float g_tda[BB];               // atomic
__device__ float g_tdd[BB];
__device__ __half g_T[(size_t)BB*NN*NN];  // cdist*adj (fp16, no /vol)
__device__ float g_Y[BB*NN*HH];
__device__ float g_x2[BB*NN*HH];
__device__ float g_s2[BB*NN*K2C];
__device__ float g_s2e[BB*NN*32];
__device__ float g_qs2[BB*NN];
__device__ float g_P[BB*NN*32];
__device__ float g_ss[BB*KC*KC];          // atomic
__device__ float g_red[BB*16*64];         // atomic: c<16 oadj | 16..31 ss2 | 32..63 outx
__device__ float g_den2[BB];              // atomic
__device__ float g_o1b[BB];
__device__ float g_o2b[BB];

// ---------------- helpers ----------------
__device__ __forceinline__ float blockReduceSum(float v){
    __shared__ float sh[32];
    int tid = threadIdx.x;
    int nth = blockDim.x;
    int lane = tid & 31, wid = tid >> 5;
    __syncthreads();
    #pragma unroll
    for(int o=16;o;o>>=1) v += __shfl_down_sync(0xffffffffu, v, o);
    if(lane==0) sh[wid] = v;
    __syncthreads();
    float r = (tid < (nth>>5)) ? sh[tid] : 0.f;
    if(wid==0){
        #pragma unroll
        for(int o=16;o;o>>=1) r += __shfl_down_sync(0xffffffffu, r, o);
        if(lane==0) sh[0] = r;
    }
    __syncthreads();
    return sh[0];
}

// ---------------- kernels ----------------
__global__ void zero_kernel(){
    int t = blockIdx.x*256 + threadIdx.x;
    int stride = gridDim.x*256;
    for(int i=t;i<BB;i+=stride){ g_tda[i]=0.f; g_vol[i]=0.f; g_den2[i]=0.f; }
    for(int i=t;i<BB*NN;i+=stride) g_dflat[i]=0.f;
    for(int i=t;i<BB*KC*KC;i+=stride) g_ss[i]=0.f;
    for(int i=t;i<BB*16*64;i+=stride) g_red[i]=0.f;
}

// Fused: x1 = x@W1+b1 ; s = tanh(x1@Wp+bp); qn; ss += s^T s (atomics)
// 64 rows/block, 128 threads
__global__ __launch_bounds__(128) void lin1pool_kernel(
        const float* __restrict__ x, const float* __restrict__ W1, const float* __restrict__ b1,
        const float* __restrict__ Wp, const float* __restrict__ bp){
    __shared__ float Ws[FIN][36];
    __shared__ float xt[2][32][68];
    __shared__ float Wps[HH][68];
    __shared__ float bps[KC];
    __shared__ float x1s[64][33];
    __shared__ float sS[64][68];
    int tid = threadIdx.x;                 // 128
    int colg = tid & 7, rowg = tid >> 3;
    int rowbase = blockIdx.x*64;
    int b = rowbase >> 10;
    for(int i=tid;i<FIN*32;i+=128){ int k=i>>5,c=i&31; Ws[k][c]=W1[i]; }
    for(int i=tid;i<HH*KC;i+=128){ int k=i>>6,c=i&63; Wps[k][c]=Wp[i]; }
    if(tid<KC) bps[tid]=bp[tid];
    for(int i=tid;i<2048;i+=128){ int r=i>>5,k=i&31; xt[0][k][r]=x[(size_t)(rowbase+r)*FIN + k]; }
    float acc[4][4] = {};
    #pragma unroll
    for(int kc=0;kc<4;kc++){
        __syncthreads();
        if(kc<3){
            int nb=(kc+1)&1;
            for(int i=tid;i<2048;i+=128){ int r=i>>5,k=i&31; xt[nb][k][r]=x[(size_t)(rowbase+r)*FIN + (kc+1)*32 + k]; }
        }
        int cb=kc&1;
        #pragma unroll
        for(int k=0;k<32;k++){
            float4 a = *(const float4*)&xt[cb][k][rowg*4];
            float4 w = *(const float4*)&Ws[kc*32+k][colg*4];
            float av[4]={a.x,a.y,a.z,a.w}, wv[4]={w.x,w.y,w.z,w.w};
            #pragma unroll
            for(int i=0;i<4;i++)
                #pragma unroll
                for(int j=0;j<4;j++) acc[i][j] += av[i]*wv[j];
        }
    }
    float4 bb = *(const float4*)&b1[colg*4];
    float bv[4]={bb.x,bb.y,bb.z,bb.w};
    #pragma unroll
    for(int i=0;i<4;i++){
        int lr = rowg*4+i;
        float4 res = make_float4(acc[i][0]+bv[0],acc[i][1]+bv[1],acc[i][2]+bv[2],acc[i][3]+bv[3]);
        *(float4*)&g_x1[(rowbase+lr)*HH + colg*4] = res;
        x1s[lr][colg*4+0]=res.x; x1s[lr][colg*4+1]=res.y;
        x1s[lr][colg*4+2]=res.z; x1s[lr][colg*4+3]=res.w;
    }
    __syncthreads();
    // pool phase: r = tid>>1, half = tid&1 (32 cols each)
    {
        int r = tid>>1, half = tid&1;
        int cb2 = half*32;
        float sv[32];
        #pragma unroll
        for(int c=0;c<32;c++) sv[c]=bps[cb2+c];
        #pragma unroll
        for(int k=0;k<32;k++){
            float xk = x1s[r][k];
            #pragma unroll
            for(int c4=0;c4<8;c4++){
                float4 w = *(const float4*)&Wps[k][cb2+c4*4];
                sv[c4*4+0] += xk*w.x; sv[c4*4+1] += xk*w.y;
                sv[c4*4+2] += xk*w.z; sv[c4*4+3] += xk*w.w;
            }
        }
        float q = 0.f;
        int grow = rowbase + r;
        #pragma unroll
        for(int c=0;c<32;c++){ float s=tanhf(sv[c]); sv[c]=s; q += s*s; }
        #pragma unroll
        for(int c4=0;c4<8;c4++){
            float4 res = make_float4(sv[c4*4],sv[c4*4+1],sv[c4*4+2],sv[c4*4+3]);
            *(float4*)&g_s[grow*KC + cb2 + c4*4] = res;
            *(float4*)&sS[r][cb2 + c4*4] = res;
        }
        q += __shfl_xor_sync(0xffffffffu, q, 1);
        if(half==0) g_qn[grow] = q;
    }
    __syncthreads();
    // ss phase: kg = tid>>3 (4 k-rows), lg = tid&7 (cols lg*4 and lg*4+32)
    {
        int kg = tid>>3, lg = tid&7;
        float accs[4][8] = {};
        #pragma unroll 4
        for(int r=0;r<64;r++){
            float4 a  = *(const float4*)&sS[r][kg*4];
            float4 c0 = *(const float4*)&sS[r][lg*4];
            float4 c1 = *(const float4*)&sS[r][lg*4+32];
            float av[4]={a.x,a.y,a.z,a.w};
            float cv[8]={c0.x,c0.y,c0.z,c0.w,c1.x,c1.y,c1.z,c1.w};
            #pragma unroll
            for(int i=0;i<4;i++)
                #pragma unroll
                for(int j=0;j<8;j++) accs[i][j] += av[i]*cv[j];
        }
        #pragma unroll
        for(int i=0;i<4;i++)
            #pragma unroll
            for(int j=0;j<8;j++){
                int col = (j<4) ? lg*4+j : lg*4+32+(j-4);
                atomicAdd(&g_ss[(b*KC + kg*4+i)*KC + col], accs[i][j]);
            }
    }
}

// Symmetric fused: Gram -> cdist -> T(fp16) ; accumulates tda, dflat, vol
// grid (36, BB), 256 thr, 8x8 micro-tile (j split into tx*4 / tx*4+64)
__global__ __launch_bounds__(256) void ct_main_kernel(const float* __restrict__ adj){
    __shared__ float As[32][132];
    __shared__ float Bs[32][132];
    __shared__ float qa[128], qb[128];
    int b = blockIdx.y;
    int p = blockIdx.x, ti = 0;
    while(p >= 8-ti){ p -= 8-ti; ti++; }
    int tj = ti + p;
    int rowbase = ti*128, colbase = tj*128;
    int tid = threadIdx.x;
    int tx = tid & 15, ty = tid >> 4;
    const float* Sp = g_s + b*NN*KC;
    if(tid<128) qa[tid] = g_qn[b*NN+rowbase+tid];
    else qb[tid-128] = g_qn[b*NN+colbase+(tid-128)];
    float acc[8][8] = {};
    #pragma unroll
    for(int kc=0;kc<2;kc++){
        __syncthreads();
        for(int i=tid;i<4096;i+=256){ int r=i>>5,k=i&31; As[k][r]=Sp[(rowbase+r)*KC + kc*32 + k]; }
        for(int i=tid;i<4096;i+=256){ int r=i>>5,k=i&31; Bs[k][r]=Sp[(colbase+r)*KC + kc*32 + k]; }
        __syncthreads();
        #pragma unroll 8
        for(int k=0;k<32;k++){
            float4 a0=*(const float4*)&As[k][ty*8];
            float4 a1=*(const float4*)&As[k][ty*8+4];
            float4 b0=*(const float4*)&Bs[k][tx*4];
            float4 b1=*(const float4*)&Bs[k][tx*4+64];
            float av[8]={a0.x,a0.y,a0.z,a0.w,a1.x,a1.y,a1.z,a1.w};
            float bv[8]={b0.x,b0.y,b0.z,b0.w,b1.x,b1.y,b1.z,b1.w};
            #pragma unroll
            for(int i=0;i<8;i++)
                #pragma unroll
                for(int j=0;j<8;j++) acc[i][j] += av[i]*bv[j];
        }
    }
    float tda = 0.f, volp = 0.f;
    const float* Ap = adj + (size_t)b*NN*NN;
    __half* Tp = g_T + (size_t)b*NN*NN;
    // direct tile
    #pragma unroll
    for(int i=0;i<8;i++){
        int row = rowbase + ty*8 + i;
        size_t ro = (size_t)row*NN;
        float4 j0 = *(const float4*)&Ap[ro + colbase + tx*4];
        float4 j1 = *(const float4*)&Ap[ro + colbase + tx*4 + 64];
        float aj[8]={j0.x,j0.y,j0.z,j0.w,j1.x,j1.y,j1.z,j1.w};
        float qai = qa[ty*8+i];
        float rr[8]; float rp = 0.f;
        #pragma unroll
        for(int j=0;j<8;j++){
            int cj = tx*4 + ((j<4)? j : 60+j);
            float g = acc[i][j];
            float d2 = qai + qb[cj] - 2.0f*g;
            rr[j] = sqrtf(fmaxf(d2, 0.f)) * aj[j];
            tda += aj[j]*g; rp += aj[j];
        }
        __align__(8) __half2 p0[2], p1[2];
        p0[0]=__floats2half2_rn(rr[0],rr[1]); p0[1]=__floats2half2_rn(rr[2],rr[3]);
        p1[0]=__floats2half2_rn(rr[4],rr[5]); p1[1]=__floats2half2_rn(rr[6],rr[7]);
        *(uint2*)&Tp[ro + colbase + tx*4]      = *(uint2*)p0;
        *(uint2*)&Tp[ro + colbase + tx*4 + 64] = *(uint2*)p1;
        volp += rp;
        #pragma unroll
        for(int o=8;o;o>>=1) rp += __shfl_down_sync(0xffffffffu, rp, o, 16);
        if(tx==0) atomicAdd(&g_dflat[b*NN+row], rp);
    }
    if(ti != tj){
        // mirror tile
        #pragma unroll
        for(int jj=0;jj<8;jj++){
            int cj = tx*4 + ((jj<4)? jj : 60+jj);
            int row = colbase + cj;
            size_t ro = (size_t)row*NN;
            float4 t0 = *(const float4*)&Ap[ro + rowbase + ty*8];
            float4 t1 = *(const float4*)&Ap[ro + rowbase + ty*8 + 4];
            float aj[8]={t0.x,t0.y,t0.z,t0.w,t1.x,t1.y,t1.z,t1.w};
            float qbj = qb[cj];
            float rr[8]; float rp = 0.f;
            #pragma unroll
            for(int ii=0;ii<8;ii++){
                float g = acc[ii][jj];
                float d2 = qa[ty*8+ii] + qbj - 2.0f*g;
                rr[ii] = sqrtf(fmaxf(d2, 0.f)) * aj[ii];
                tda += aj[ii]*g; rp += aj[ii];
            }
            __align__(16) __half2 pm[4];
            pm[0]=__floats2half2_rn(rr[0],rr[1]); pm[1]=__floats2half2_rn(rr[2],rr[3]);
            pm[2]=__floats2half2_rn(rr[4],rr[5]); pm[3]=__floats2half2_rn(rr[6],rr[7]);
            *(uint4*)&Tp[ro + rowbase + ty*8] = *(uint4*)pm;
            volp += rp;
            atomicAdd(&g_dflat[b*NN+row], rp);
        }
    }
    volp = blockReduceSum(volp);
    if(tid==0) atomicAdd(&g_vol[b], volp);
    tda = blockReduceSum(tda);
    if(tid==0) atomicAdd(&g_tda[b], tda);
}

// O[b] = invvol * (T[b] @ X[b]), T fp16 [N,N], X [N,32]
// 64x32 tile, grid (16,BB), 256 thr, 2x4 micro-tile, double-buffered
__device__ __forceinline__ void bmm_ax_body(const float* __restrict__ X, float* __restrict__ O){
    __shared__ __align__(16) __half At[2][64][72];
    __shared__ float Xs[2][64][36];
    int b = blockIdx.y, rowbase = blockIdx.x*64;
    int tid = threadIdx.x;                      // 256
    int colg = tid & 7, rowg = tid >> 3;        // 4 cols, 2 rows
    const __half* Ab = g_T + (size_t)b*NN*NN;
    const float* Xb = X + (size_t)b*NN*32;
    float acc[2][4] = {};
    for(int i=tid;i<512;i+=256){ int r=i>>3,q=i&7; *(uint4*)&At[0][r][q*8] = *(const uint4*)&Ab[(size_t)(rowbase+r)*NN + q*8]; }
    for(int i=tid;i<2048;i+=256){ Xs[0][i>>5][i&31]=Xb[i]; }
    for(int kt=0;kt<16;kt++){
        __syncthreads();
        if(kt<15){
            int nb=(kt+1)&1, ko=(kt+1)*64;
            for(int i=tid;i<512;i+=256){ int r=i>>3,q=i&7; *(uint4*)&At[nb][r][q*8] = *(const uint4*)&Ab[(size_t)(rowbase+r)*NN + ko + q*8]; }
            for(int i=tid;i<2048;i+=256){ Xs[nb][i>>5][i&31]=Xb[(size_t)ko*32 + i]; }
        }
        int cb=kt&1;
        #pragma unroll 8
        for(int k2=0;k2<32;k2++){
            float2 a0 = __half22float2(*(const __half2*)&At[cb][rowg*2  ][k2*2]);
            float2 a1 = __half22float2(*(const __half2*)&At[cb][rowg*2+1][k2*2]);
            float4 x0 = *(const float4*)&Xs[cb][2*k2  ][colg*4];
            float4 x1 = *(const float4*)&Xs[cb][2*k2+1][colg*4];
            acc[0][0] += a0.x*x0.x + a0.y*x1.x;
            acc[0][1] += a0.x*x0.y + a0.y*x1.y;
            acc[0][2] += a0.x*x0.z + a0.y*x1.z;
            acc[0][3] += a0.x*x0.w + a0.y*x1.w;
            acc[1][0] += a1.x*x0.x + a1.y*x1.x;
            acc[1][1] += a1.x*x0.y + a1.y*x1.y;
            acc[1][2] += a1.x*x0.z + a1.y*x1.z;
            acc[1][3] += a1.x*x0.w + a1.y*x1.w;
        }
    }
    float iv = 1.0f/(g_vol[b] + (float)NN*EPSF);
    float* Ob = O + (size_t)b*NN*32;
    #pragma unroll
    for(int i=0;i<2;i++){
        float4 res = make_float4(acc[i][0]*iv,acc[i][1]*iv,acc[i][2]*iv,acc[i][3]*iv);
        *(float4*)&Ob[(rowbase+rowg*2+i)*32 + colg*4] = res;
    }
}

__global__ __launch_bounds__(256) void bmm_Y_kernel(){ bmm_ax_body(g_x1, g_Y); }
__global__ __launch_bounds__(256) void bmm_P_kernel(){ bmm_ax_body(g_s2e, g_P); }

// x2 = (Y@Wrel + brel) + x1@Wroot ; s2 = softmax(x2@Wp2+bp2); qs2; s2e
__global__ __launch_bounds__(256) void k4_kernel(
        const float* __restrict__ Wrel, const float* __restrict__ brel,
        const float* __restrict__ Wroot, const float* __restrict__ Wp2,
        const float* __restrict__ bp2){
    __shared__ float Wr[32][33], Wo[32][33], Wp[32][17];
    __shared__ float brs[32], bps[16];
    __shared__ float Ys[64][33], Xs[64][33], x2s[64][33], lgS[64][17];
    int tid = threadIdx.x;
    for(int i=tid;i<1024;i+=256){ int k=i>>5,c=i&31; Wr[k][c]=Wrel[i]; Wo[k][c]=Wroot[i]; }
    for(int i=tid;i<512;i+=256){ int k=i>>4,c=i&15; Wp[k][c]=Wp2[i]; }
    if(tid<32) brs[tid]=brel[tid];
    if(tid<16) bps[tid]=bp2[tid];
    int rowbase = blockIdx.x*64;
    for(int i=tid;i<2048;i+=256){ int r=i>>5,c=i&31;
        Ys[r][c]=g_Y[(rowbase+r)*32+c]; Xs[r][c]=g_x1[(rowbase+r)*32+c]; }
    __syncthreads();
    {
        int col = tid & 31, rg = tid >> 5;
        float a8[8];
        #pragma unroll
        for(int rr=0;rr<8;rr++) a8[rr] = brs[col];
        #pragma unroll
        for(int k=0;k<32;k++){
            float wr = Wr[k][col], wo = Wo[k][col];
            #pragma unroll
            for(int rr=0;rr<8;rr++){
                int row = rg*8+rr;
                a8[rr] += Ys[row][k]*wr + Xs[row][k]*wo;
            }
        }
        #pragma unroll
        for(int rr=0;rr<8;rr++){
            int row = rg*8+rr;
            x2s[row][col] = a8[rr];
            g_x2[(rowbase+row)*32+col] = a8[rr];
        }
    }
    __syncthreads();
    {
        int row = tid>>2, cq = tid&3;
        float lg[4];
        #pragma unroll
        for(int c=0;c<4;c++) lg[c]=bps[cq*4+c];
        #pragma unroll
        for(int k=0;k<32;k++){
            float xv = x2s[row][k];
            #pragma unroll
            for(int c=0;c<4;c++) lg[c] += xv*Wp[k][cq*4+c];
        }
        #pragma unroll
        for(int c=0;c<4;c++) lgS[row][cq*4+c]=lg[c];
    }
    __syncthreads();
    if(tid<64){
        int row = tid, grow = rowbase + row;
        float m = lgS[row][0];
        #pragma unroll
        for(int j=1;j<16;j++) m = fmaxf(m, lgS[row][j]);
        float e[16], sum=0.f;
        #pragma unroll
        for(int j=0;j<16;j++){ e[j]=expf(lgS[row][j]-m); sum+=e[j]; }
        float inv = 1.0f/sum, q=0.f;
        #pragma unroll
        for(int j=0;j<16;j++){
            float pv = e[j]*inv;
            g_s2[grow*16+j]=pv; g_s2e[grow*32+j]=pv; q += pv*pv;
        }
        g_s2e[grow*32+16]=1.0f;
        #pragma unroll
        for(int j=17;j<32;j++) g_s2e[grow*32+j]=0.0f;
        g_qs2[grow]=q;
    }
}

// red += s2^T [P(0:16)|s2|x2] over 128-row slices ; den2 partial folded in
__global__ void k6a_kernel(){
    int b = blockIdx.y, tid = threadIdx.x;      // 256
    int rb = blockIdx.x*128;
    int k = tid >> 4, cg = tid & 15;
    __shared__ float Mc[32][68];
    float acc[4] = {0,0,0,0};
    float dp = 0.f;
    for(int ch=0;ch<4;ch++){
        int base = b*NN + rb + ch*32;
        __syncthreads();
        for(int i=tid;i<32*64;i+=256){
            int r=i>>6, c=i&63;
            int row = base + r;
            float v;
            if(c<16) v = g_P[row*32 + c];
            else if(c<32) v = g_s2[row*16 + (c-16)];
            else v = g_x2[row*32 + (c-32)];
            Mc[r][c] = v;
        }
        __syncthreads();
        if(tid<32) dp += (g_P[(base+tid)*32+16] + EPSF)*g_qs2[base+tid];
        #pragma unroll 4
        for(int r=0;r<32;r++){
            float s2v = Mc[r][16+k];
            float4 m = *(const float4*)&Mc[r][cg*4];
            acc[0] += s2v*m.x; acc[1] += s2v*m.y; acc[2] += s2v*m.z; acc[3] += s2v*m.w;
        }
    }
    #pragma unroll
    for(int j=0;j<4;j++)
        atomicAdd(&g_red[b*1024 + k*64 + cg*4 + j], acc[j]);
    dp = blockReduceSum(dp);
    if(tid==0) atomicAdd(&g_den2[b], dp);
}

// per-batch tail: tdd, ortho1, ortho2, mincut-normalize + conv2 + MLP + log_softmax
__global__ void tail_kernel(const float* __restrict__ Wrel2, const float* __restrict__ brel2,
                            const float* __restrict__ Wroot2,
                            const float* __restrict__ W2, const float* __restrict__ b2,
                            const float* __restrict__ W3, const float* __restrict__ b3,
                            float* __restrict__ out){
    int tid = threadIdx.x;                       // 256
    int b = blockIdx.x;
    // tdd
    float td = 0.f;
    for(int n=tid;n<NN;n+=256) td += g_dflat[b*NN+n]*g_qn[b*NN+n];
    td = blockReduceSum(td);
    if(tid==0) g_tdd[b] = td;
    // ortho1
    {
        const float* ssb = g_ss + b*KC*KC;
        float p = 0.f;
        for(int i=tid;i<KC*KC;i+=256){ float x=ssb[i]; p += x*x; }
        float ssn = sqrtf(blockReduceSum(p));
        float inv = 1.0f/ssn;
        p = 0.f;
        for(int i=tid;i<KC*KC;i+=256){
            float d = ssb[i]*inv - ((i%(KC+1))==0 ? 1.0f : 0.0f);
            p += d*d;
        }
        p = blockReduceSum(p);
        if(tid==0) g_o1b[b] = p;
    }
    // ortho2
    {
        float x = g_red[b*1024 + (tid>>4)*64 + 16 + (tid&15)];
        float ssn2 = sqrtf(blockReduceSum(x*x));
        float d = x/ssn2 - ((tid%17)==0 ? 0.25f : 0.0f);
        float fb = blockReduceSum(d*d);
        if(tid==0) g_o2b[b] = sqrtf(fb);
    }
    // head
    __shared__ float oa[16][17];
    __shared__ float dk[16], ca[16], mS[32], oS[32], xsum[32], hsh[32], lsh[16];
    { int k=tid>>4, l=tid&15; float x=g_red[b*1024 + k*64 + l]; if(k==l) x=0.f; oa[k][l]=x; }
    __syncthreads();
    if(tid<16){
        float rs=0.f; for(int l=0;l<16;l++) rs += oa[tid][l];
        dk[tid] = sqrtf(rs + EPSF) + EPSF;
    }
    __syncthreads();
    { int k=tid>>4, l=tid&15; oa[k][l] = oa[k][l]/(dk[k]*dk[l]); }
    __syncthreads();
    if(tid<16){ float c=0.f; for(int k=0;k<16;k++) c += oa[k][tid]; ca[tid]=c; }
    __syncthreads();
    if(tid<32){
        float m=0.f, o=0.f;
        for(int l=0;l<16;l++){ float ox=g_red[b*1024 + l*64 + 32 + tid]; m += ca[l]*ox; o += ox; }
        mS[tid]=m; oS[tid]=o;
    }
    __syncthreads();
    if(tid<32){
        float x = 16.0f*brel2[tid];
        for(int g=0;g<32;g++) x += mS[g]*Wrel2[g*32+tid] + oS[g]*Wroot2[g*32+tid];
        xsum[tid] = x;
    }
    __syncthreads();
    if(tid<32){
        float h = b2[tid];
        for(int g=0;g<32;g++) h += xsum[g]*W2[g*32+tid];
        hsh[tid] = fmaxf(h, 0.f);
    }
    __syncthreads();
    if(tid<10){
        float lg = b3[tid];
        for(int g=0;g<32;g++) lg += hsh[g]*W3[g*10+tid];
        lsh[tid] = lg;
    }
    __syncthreads();
    if(tid==0){
        float m = lsh[0];
        for(int o=1;o<10;o++) m = fmaxf(m, lsh[o]);
        float s = 0.f;
        for(int o=0;o<10;o++) s += expf(lsh[o]-m);
        float lse = m + logf(s);
        for(int o=0;o<10;o++) out[b*10+o] = lsh[o]-lse;
    }
}

__global__ void loss_kernel(float* __restrict__ out){
    int tid = threadIdx.x;                       // 256
    float v = 0.f;
    if(tid<BB){
        float tddf = g_tdd[tid];
        v = (tddf - g_tda[tid])/(tddf + EPSF);
    }
    float ct_loss = blockReduceSum(v)*(1.0f/BB);
    v = (tid<BB) ? g_o1b[tid] : 0.f;
    float ortho1 = sqrtf(blockReduceSum(v));
    v = 0.f;
    if(tid<BB){
        float num = 0.f;
        for(int k=0;k<K2C;k++) num += g_red[tid*1024 + k*64 + k];
        v = -num/g_den2[tid];
    }
    float mc_loss = blockReduceSum(v)*(1.0f/BB);
    v = (tid<BB) ? g_o2b[tid] : 0.f;
    float ortho2 = blockReduceSum(v)*(1.0f/BB);
    if(tid==0){ out[160] = ct_loss + ortho1; out[161] = mc_loss + ortho2; }
}

// ---------------- launch ----------------
extern "C" void kernel_launch(void* const* d_in, const int* in_sizes, int n_in,
                              void* d_out, int out_size){
    const float* x       = (const float*)d_in[0];
    const float* adj     = (const float*)d_in[1];
    const float* W_lin1  = (const float*)d_in[3];
    const float* b_lin1  = (const float*)d_in[4];
    const float* W_pool1 = (const float*)d_in[5];
    const float* b_pool1 = (const float*)d_in[6];
    const float* W_pool2 = (const float*)d_in[7];
    const float* b_pool2 = (const float*)d_in[8];
    const float* Wrel1   = (const float*)d_in[9];
    const float* brel1   = (const float*)d_in[10];
    const float* Wroot1  = (const float*)d_in[11];
    const float* Wrel2   = (const float*)d_in[12];
    const float* brel2   = (const float*)d_in[13];
    const float* Wroot2  = (const float*)d_in[14];
    const float* W_lin2  = (const float*)d_in[15];
    const float* b_lin2  = (const float*)d_in[16];
    const float* W_lin3  = (const float*)d_in[17];
    const float* b_lin3  = (const float*)d_in[18];
    float* out = (float*)d_out;

    zero_kernel<<<64,256>>>();
    lin1pool_kernel<<<BB*NN/64, 128>>>(x, W_lin1, b_lin1, W_pool1, b_pool1);
    ct_main_kernel<<<dim3(36,BB), 256>>>(adj);
    bmm_Y_kernel<<<dim3(16,BB), 256>>>();
    k4_kernel<<<BB*NN/64, 256>>>(Wrel1, brel1, Wroot1, W_pool2, b_pool2);
    bmm_P_kernel<<<dim3(16,BB), 256>>>();
    k6a_kernel<<<dim3(8,BB), 256>>>();
    tail_kernel<<<BB, 256>>>(Wrel2, brel2, Wroot2, W_lin2, b_lin2, W_lin3, b_lin3, out);
    loss_kernel<<<1, 256>>>(out);
}

// round 9
// speedup vs baseline: 1.9986x; 1.1423x over previous
#include <cuda_runtime.h>
#include <cuda_fp16.h>
#include <math.h>
#include <stdint.h>

#define BB 16
#define NN 1024
#define FIN 128
#define HH 32
#define KC 64
#define K2C 16
#define EPSF 1e-15f

// ---------------- device scratch ----------------
__device__ float g_x1[BB*NN*HH];
__device__ __half g_x1h[BB*NN*HH];
__device__ float g_s [BB*NN*KC];
__device__ float g_qn[BB*NN];
__device__ float g_dflat[BB*NN];          // rowsum(adj), atomic
__device__ float g_vol[BB];               // atomic
__device__ float g_tda[BB];               // atomic
__device__ float g_tdd[BB];
__device__ __half g_T[(size_t)BB*NN*NN];  // cdist*adj (fp16, no /vol)
__device__ float g_Y[BB*NN*HH];
__device__ float g_x2[BB*NN*HH];
__device__ float g_s2[BB*NN*K2C];
__device__ __half g_s2eh[BB*NN*32];       // [s2 | 1 | 0...] fp16
__device__ float g_qs2[BB*NN];
__device__ float g_P[BB*NN*32];
__device__ float g_ss[BB*KC*KC];          // atomic
__device__ float g_red[BB*16*64];         // atomic: c<16 oadj | 16..31 ss2 | 32..63 outx
__device__ float g_den2[BB];              // atomic
__device__ float g_o1b[BB];
__device__ float g_o2b[BB];

// ---------------- helpers ----------------
__device__ __forceinline__ float blockReduceSum(float v){
    __shared__ float sh[32];
    int tid = threadIdx.x;
    int nth = blockDim.x;
    int lane = tid & 31, wid = tid >> 5;
    __syncthreads();
    #pragma unroll
    for(int o=16;o;o>>=1) v += __shfl_down_sync(0xffffffffu, v, o);
    if(lane==0) sh[wid] = v;
    __syncthreads();
    float r = (tid < (nth>>5)) ? sh[tid] : 0.f;
    if(wid==0){
        #pragma unroll
        for(int o=16;o;o>>=1) r += __shfl_down_sync(0xffffffffu, r, o);
        if(lane==0) sh[0] = r;
    }
    __syncthreads();
    return sh[0];
}

__device__ __forceinline__ uint32_t smem_u32(const void* p){
    uint32_t a;
    asm("{ .reg .u64 t; cvta.to.shared.u64 t, %1; cvt.u32.u64 %0, t; }" : "=r"(a) : "l"(p));
    return a;
}
__device__ __forceinline__ void ldsm_x4(uint32_t&r0,uint32_t&r1,uint32_t&r2,uint32_t&r3,uint32_t a){
    asm volatile("ldmatrix.sync.aligned.m8n8.x4.shared.b16 {%0,%1,%2,%3}, [%4];"
        :"=r"(r0),"=r"(r1),"=r"(r2),"=r"(r3):"r"(a));
}
__device__ __forceinline__ void ldsm_x4_t(uint32_t&r0,uint32_t&r1,uint32_t&r2,uint32_t&r3,uint32_t a){
    asm volatile("ldmatrix.sync.aligned.m8n8.x4.trans.shared.b16 {%0,%1,%2,%3}, [%4];"
        :"=r"(r0),"=r"(r1),"=r"(r2),"=r"(r3):"r"(a));
}
__device__ __forceinline__ void mma16816(float* c, uint32_t a0,uint32_t a1,uint32_t a2,uint32_t a3,
                                         uint32_t b0,uint32_t b1){
    asm volatile("mma.sync.aligned.m16n8k16.row.col.f32.f16.f16.f32 "
        "{%0,%1,%2,%3}, {%4,%5,%6,%7}, {%8,%9}, {%0,%1,%2,%3};"
        : "+f"(c[0]),"+f"(c[1]),"+f"(c[2]),"+f"(c[3])
        : "r"(a0),"r"(a1),"r"(a2),"r"(a3),"r"(b0),"r"(b1));
}

// ---------------- kernels ----------------
__global__ void zero_kernel(){
    int t = blockIdx.x*256 + threadIdx.x;
    int stride = gridDim.x*256;
    for(int i=t;i<BB;i+=stride){ g_tda[i]=0.f; g_vol[i]=0.f; g_den2[i]=0.f; }
    for(int i=t;i<BB*NN;i+=stride) g_dflat[i]=0.f;
    for(int i=t;i<BB*KC*KC;i+=stride) g_ss[i]=0.f;
    for(int i=t;i<BB*16*64;i+=stride) g_red[i]=0.f;
}

// Fused: x1 = x@W1+b1 ; s = tanh(x1@Wp+bp); qn; ss += s^T s (atomics)
__global__ __launch_bounds__(128) void lin1pool_kernel(
        const float* __restrict__ x, const float* __restrict__ W1, const float* __restrict__ b1,
        const float* __restrict__ Wp, const float* __restrict__ bp){
    __shared__ float Ws[FIN][36];
    __shared__ float xt[2][32][68];
    __shared__ float Wps[HH][68];
    __shared__ float bps[KC];
    __shared__ float x1s[64][33];
    __shared__ float sS[64][68];
    int tid = threadIdx.x;                 // 128
    int colg = tid & 7, rowg = tid >> 3;
    int rowbase = blockIdx.x*64;
    int b = rowbase >> 10;
    for(int i=tid;i<FIN*32;i+=128){ int k=i>>5,c=i&31; Ws[k][c]=W1[i]; }
    for(int i=tid;i<HH*KC;i+=128){ int k=i>>6,c=i&63; Wps[k][c]=Wp[i]; }
    if(tid<KC) bps[tid]=bp[tid];
    for(int i=tid;i<2048;i+=128){ int r=i>>5,k=i&31; xt[0][k][r]=x[(size_t)(rowbase+r)*FIN + k]; }
    float acc[4][4] = {};
    #pragma unroll
    for(int kc=0;kc<4;kc++){
        __syncthreads();
        if(kc<3){
            int nb=(kc+1)&1;
            for(int i=tid;i<2048;i+=128){ int r=i>>5,k=i&31; xt[nb][k][r]=x[(size_t)(rowbase+r)*FIN + (kc+1)*32 + k]; }
        }
        int cb=kc&1;
        #pragma unroll
        for(int k=0;k<32;k++){
            float4 a = *(const float4*)&xt[cb][k][rowg*4];
            float4 w = *(const float4*)&Ws[kc*32+k][colg*4];
            float av[4]={a.x,a.y,a.z,a.w}, wv[4]={w.x,w.y,w.z,w.w};
            #pragma unroll
            for(int i=0;i<4;i++)
                #pragma unroll
                for(int j=0;j<4;j++) acc[i][j] += av[i]*wv[j];
        }
    }
    float4 bb = *(const float4*)&b1[colg*4];
    float bv[4]={bb.x,bb.y,bb.z,bb.w};
    #pragma unroll
    for(int i=0;i<4;i++){
        int lr = rowg*4+i;
        float4 res = make_float4(acc[i][0]+bv[0],acc[i][1]+bv[1],acc[i][2]+bv[2],acc[i][3]+bv[3]);
        *(float4*)&g_x1[(rowbase+lr)*HH + colg*4] = res;
        __align__(8) __half2 hh[2];
        hh[0]=__floats2half2_rn(res.x,res.y); hh[1]=__floats2half2_rn(res.z,res.w);
        *(uint2*)&g_x1h[(rowbase+lr)*HH + colg*4] = *(uint2*)hh;
        x1s[lr][colg*4+0]=res.x; x1s[lr][colg*4+1]=res.y;
        x1s[lr][colg*4+2]=res.z; x1s[lr][colg*4+3]=res.w;
    }
    __syncthreads();
    // pool phase
    {
        int r = tid>>1, half = tid&1;
        int cb2 = half*32;
        float sv[32];
        #pragma unroll
        for(int c=0;c<32;c++) sv[c]=bps[cb2+c];
        #pragma unroll
        for(int k=0;k<32;k++){
            float xk = x1s[r][k];
            #pragma unroll
            for(int c4=0;c4<8;c4++){
                float4 w = *(const float4*)&Wps[k][cb2+c4*4];
                sv[c4*4+0] += xk*w.x; sv[c4*4+1] += xk*w.y;
                sv[c4*4+2] += xk*w.z; sv[c4*4+3] += xk*w.w;
            }
        }
        float q = 0.f;
        int grow = rowbase + r;
        #pragma unroll
        for(int c=0;c<32;c++){ float s=tanhf(sv[c]); sv[c]=s; q += s*s; }
        #pragma unroll
        for(int c4=0;c4<8;c4++){
            float4 res = make_float4(sv[c4*4],sv[c4*4+1],sv[c4*4+2],sv[c4*4+3]);
            *(float4*)&g_s[grow*KC + cb2 + c4*4] = res;
            *(float4*)&sS[r][cb2 + c4*4] = res;
        }
        q += __shfl_xor_sync(0xffffffffu, q, 1);
        if(half==0) g_qn[grow] = q;
    }
    __syncthreads();
    // ss phase
    {
        int kg = tid>>3, lg = tid&7;
        float accs[4][8] = {};
        #pragma unroll 4
        for(int r=0;r<64;r++){
            float4 a  = *(const float4*)&sS[r][kg*4];
            float4 c0 = *(const float4*)&sS[r][lg*4];
            float4 c1 = *(const float4*)&sS[r][lg*4+32];
            float av[4]={a.x,a.y,a.z,a.w};
            float cv[8]={c0.x,c0.y,c0.z,c0.w,c1.x,c1.y,c1.z,c1.w};
            #pragma unroll
            for(int i=0;i<4;i++)
                #pragma unroll
                for(int j=0;j<8;j++) accs[i][j] += av[i]*cv[j];
        }
        #pragma unroll
        for(int i=0;i<4;i++)
            #pragma unroll
            for(int j=0;j<8;j++){
                int col = (j<4) ? lg*4+j : lg*4+32+(j-4);
                atomicAdd(&g_ss[(b*KC + kg*4+i)*KC + col], accs[i][j]);
            }
    }
}

// Symmetric fused: Gram -> cdist -> T(fp16) ; accumulates tda, dflat, vol
__global__ __launch_bounds__(256) void ct_main_kernel(const float* __restrict__ adj){
    __shared__ float As[32][132];
    __shared__ float Bs[32][132];
    __shared__ float qa[128], qb[128];
    int b = blockIdx.y;
    int p = blockIdx.x, ti = 0;
    while(p >= 8-ti){ p -= 8-ti; ti++; }
    int tj = ti + p;
    int rowbase = ti*128, colbase = tj*128;
    int tid = threadIdx.x;
    int tx = tid & 15, ty = tid >> 4;
    const float* Sp = g_s + b*NN*KC;
    if(tid<128) qa[tid] = g_qn[b*NN+rowbase+tid];
    else qb[tid-128] = g_qn[b*NN+colbase+(tid-128)];
    float acc[8][8] = {};
    #pragma unroll
    for(int kc=0;kc<2;kc++){
        __syncthreads();
        for(int i=tid;i<4096;i+=256){ int r=i>>5,k=i&31; As[k][r]=Sp[(rowbase+r)*KC + kc*32 + k]; }
        for(int i=tid;i<4096;i+=256){ int r=i>>5,k=i&31; Bs[k][r]=Sp[(colbase+r)*KC + kc*32 + k]; }
        __syncthreads();
        #pragma unroll 8
        for(int k=0;k<32;k++){
            float4 a0=*(const float4*)&As[k][ty*8];
            float4 a1=*(const float4*)&As[k][ty*8+4];
            float4 b0=*(const float4*)&Bs[k][tx*4];
            float4 b1=*(const float4*)&Bs[k][tx*4+64];
            float av[8]={a0.x,a0.y,a0.z,a0.w,a1.x,a1.y,a1.z,a1.w};
            float bv[8]={b0.x,b0.y,b0.z,b0.w,b1.x,b1.y,b1.z,b1.w};
            #pragma unroll
            for(int i=0;i<8;i++)
                #pragma unroll
                for(int j=0;j<8;j++) acc[i][j] += av[i]*bv[j];
        }
    }
    float tda = 0.f, volp = 0.f;
    const float* Ap = adj + (size_t)b*NN*NN;
    __half* Tp = g_T + (size_t)b*NN*NN;
    #pragma unroll
    for(int i=0;i<8;i++){
        int row = rowbase + ty*8 + i;
        size_t ro = (size_t)row*NN;
        float4 j0 = *(const float4*)&Ap[ro + colbase + tx*4];
        float4 j1 = *(const float4*)&Ap[ro + colbase + tx*4 + 64];
        float aj[8]={j0.x,j0.y,j0.z,j0.w,j1.x,j1.y,j1.z,j1.w};
        float qai = qa[ty*8+i];
        float rr[8]; float rp = 0.f;
        #pragma unroll
        for(int j=0;j<8;j++){
            int cj = tx*4 + ((j<4)? j : 60+j);
            float g = acc[i][j];
            float d2 = qai + qb[cj] - 2.0f*g;
            rr[j] = sqrtf(fmaxf(d2, 0.f)) * aj[j];
            tda += aj[j]*g; rp += aj[j];
        }
        __align__(8) __half2 p0[2], p1[2];
        p0[0]=__floats2half2_rn(rr[0],rr[1]); p0[1]=__floats2half2_rn(rr[2],rr[3]);
        p1[0]=__floats2half2_rn(rr[4],rr[5]); p1[1]=__floats2half2_rn(rr[6],rr[7]);
        *(uint2*)&Tp[ro + colbase + tx*4]      = *(uint2*)p0;
        *(uint2*)&Tp[ro + colbase + tx*4 + 64] = *(uint2*)p1;
        volp += rp;
        #pragma unroll
        for(int o=8;o;o>>=1) rp += __shfl_down_sync(0xffffffffu, rp, o, 16);
        if(tx==0) atomicAdd(&g_dflat[b*NN+row], rp);
    }
    if(ti != tj){
        #pragma unroll
        for(int jj=0;jj<8;jj++){
            int cj = tx*4 + ((jj<4)? jj : 60+jj);
            int row = colbase + cj;
            size_t ro = (size_t)row*NN;
            float4 t0 = *(const float4*)&Ap[ro + rowbase + ty*8];
            float4 t1 = *(const float4*)&Ap[ro + rowbase + ty*8 + 4];
            float aj[8]={t0.x,t0.y,t0.z,t0.w,t1.x,t1.y,t1.z,t1.w};
            float qbj = qb[cj];
            float rr[8]; float rp = 0.f;
            #pragma unroll
            for(int ii=0;ii<8;ii++){
                float g = acc[ii][jj];
                float d2 = qa[ty*8+ii] + qbj - 2.0f*g;
                rr[ii] = sqrtf(fmaxf(d2, 0.f)) * aj[ii];
                tda += aj[ii]*g; rp += aj[ii];
            }
            __align__(16) __half2 pm[4];
            pm[0]=__floats2half2_rn(rr[0],rr[1]); pm[1]=__floats2half2_rn(rr[2],rr[3]);
            pm[2]=__floats2half2_rn(rr[4],rr[5]); pm[3]=__floats2half2_rn(rr[6],rr[7]);
            *(uint4*)&Tp[ro + rowbase + ty*8] = *(uint4*)pm;
            volp += rp;
            atomicAdd(&g_dflat[b*NN+row], rp);
        }
    }
    volp = blockReduceSum(volp);
    if(tid==0) atomicAdd(&g_vol[b], volp);
    tda = blockReduceSum(tda);
    if(tid==0) atomicAdd(&g_tda[b], tda);
}

// O[b] = invvol * (T[b] @ Xh[b]) via mma.m16n8k16
// 64-row tile, 128 thr (4 warps x 16 rows), grid (16,BB), double-buffered 64-k
__device__ __forceinline__ void bmm_mma(const __half* __restrict__ Xh, float* __restrict__ O){
    __shared__ __align__(16) __half At[2][64][72];
    __shared__ __align__(16) __half Xs[2][64][40];
    int b = blockIdx.y, rowbase = blockIdx.x*64;
    int tid = threadIdx.x;
    int w = tid>>5, lane = tid&31;
    const __half* Ab = g_T + (size_t)b*NN*NN;
    const __half* Xb = Xh + (size_t)b*NN*32;
    float c[4][4] = {};
    for(int i=tid;i<512;i+=128){ int r=i>>3,q=i&7; *(uint4*)&At[0][r][q*8] = *(const uint4*)&Ab[(size_t)(rowbase+r)*NN + q*8]; }
    for(int i=tid;i<256;i+=128){ int r=i>>2,q=i&3; *(uint4*)&Xs[0][r][q*8] = *(const uint4*)&Xb[r*32 + q*8]; }
    uint32_t at_base = smem_u32(&At[0][0][0]);
    uint32_t xs_base = smem_u32(&Xs[0][0][0]);
    int a_row = lane & 15, a_half = lane >> 4;
    int b_t = lane >> 3, b_row = lane & 7;
    for(int kt=0;kt<16;kt++){
        __syncthreads();
        if(kt<15){
            int nb=(kt+1)&1; size_t ko=(size_t)(kt+1)*64;
            for(int i=tid;i<512;i+=128){ int r=i>>3,q=i&7; *(uint4*)&At[nb][r][q*8] = *(const uint4*)&Ab[(size_t)(rowbase+r)*NN + ko + q*8]; }
            for(int i=tid;i<256;i+=128){ int r=i>>2,q=i&3; *(uint4*)&Xs[nb][r][q*8] = *(const uint4*)&Xb[(ko+r)*32 + q*8]; }
        }
        int cb=kt&1;
        uint32_t atb = at_base + cb*(64*72*2);
        uint32_t xsb = xs_base + cb*(64*40*2);
        #pragma unroll
        for(int kk=0;kk<4;kk++){
            uint32_t a0,a1,a2,a3;
            uint32_t aaddr = atb + ((16*w + a_row)*72 + kk*16 + a_half*8)*2;
            ldsm_x4(a0,a1,a2,a3,aaddr);
            #pragma unroll
            for(int g=0;g<2;g++){
                uint32_t b0,b1,b2,b3;
                uint32_t baddr = xsb + ((kk*16 + b_row + (b_t&1)*8)*40 + g*16 + (b_t>>1)*8)*2;
                ldsm_x4_t(b0,b1,b2,b3,baddr);
                mma16816(c[2*g],   a0,a1,a2,a3, b0,b1);
                mma16816(c[2*g+1], a0,a1,a2,a3, b2,b3);
            }
        }
    }
    float iv = 1.0f/(g_vol[b] + (float)NN*EPSF);
    float* Ob = O + (size_t)b*NN*32;
    int row0 = rowbase + 16*w + (lane>>2);
    int col0 = (lane&3)*2;
    #pragma unroll
    for(int t=0;t<4;t++){
        *(float2*)&Ob[(size_t)row0*32 + t*8 + col0]     = make_float2(c[t][0]*iv, c[t][1]*iv);
        *(float2*)&Ob[(size_t)(row0+8)*32 + t*8 + col0] = make_float2(c[t][2]*iv, c[t][3]*iv);
    }
}

__global__ __launch_bounds__(128) void bmm_Y_kernel(){ bmm_mma(g_x1h, g_Y); }
__global__ __launch_bounds__(128) void bmm_P_kernel(){ bmm_mma(g_s2eh, g_P); }

// x2 = (Y@Wrel + brel) + x1@Wroot ; s2 = softmax(x2@Wp2+bp2); qs2; s2eh
__global__ __launch_bounds__(256) void k4_kernel(
        const float* __restrict__ Wrel, const float* __restrict__ brel,
        const float* __restrict__ Wroot, const float* __restrict__ Wp2,
        const float* __restrict__ bp2){
    __shared__ float Wr[32][33], Wo[32][33], Wp[32][17];
    __shared__ float brs[32], bps[16];
    __shared__ float Ys[64][33], Xs[64][33], x2s[64][33], lgS[64][17];
    int tid = threadIdx.x;
    for(int i=tid;i<1024;i+=256){ int k=i>>5,c=i&31; Wr[k][c]=Wrel[i]; Wo[k][c]=Wroot[i]; }
    for(int i=tid;i<512;i+=256){ int k=i>>4,c=i&15; Wp[k][c]=Wp2[i]; }
    if(tid<32) brs[tid]=brel[tid];
    if(tid<16) bps[tid]=bp2[tid];
    int rowbase = blockIdx.x*64;
    for(int i=tid;i<2048;i+=256){ int r=i>>5,c=i&31;
        Ys[r][c]=g_Y[(rowbase+r)*32+c]; Xs[r][c]=g_x1[(rowbase+r)*32+c]; }
    __syncthreads();
    {
        int col = tid & 31, rg = tid >> 5;
        float a8[8];
        #pragma unroll
        for(int rr=0;rr<8;rr++) a8[rr] = brs[col];
        #pragma unroll
        for(int k=0;k<32;k++){
            float wr = Wr[k][col], wo = Wo[k][col];
            #pragma unroll
            for(int rr=0;rr<8;rr++){
                int row = rg*8+rr;
                a8[rr] += Ys[row][k]*wr + Xs[row][k]*wo;
            }
        }
        #pragma unroll
        for(int rr=0;rr<8;rr++){
            int row = rg*8+rr;
            x2s[row][col] = a8[rr];
            g_x2[(rowbase+row)*32+col] = a8[rr];
        }
    }
    __syncthreads();
    {
        int row = tid>>2, cq = tid&3;
        float lg[4];
        #pragma unroll
        for(int c=0;c<4;c++) lg[c]=bps[cq*4+c];
        #pragma unroll
        for(int k=0;k<32;k++){
            float xv = x2s[row][k];
            #pragma unroll
            for(int c=0;c<4;c++) lg[c] += xv*Wp[k][cq*4+c];
        }
        #pragma unroll
        for(int c=0;c<4;c++) lgS[row][cq*4+c]=lg[c];
    }
    __syncthreads();
    if(tid<64){
        int row = tid, grow = rowbase + row;
        float m = lgS[row][0];
        #pragma unroll
        for(int j=1;j<16;j++) m = fmaxf(m, lgS[row][j]);
        float e[16], sum=0.f;
        #pragma unroll
        for(int j=0;j<16;j++){ e[j]=expf(lgS[row][j]-m); sum+=e[j]; }
        float inv = 1.0f/sum, q=0.f;
        #pragma unroll
        for(int j=0;j<16;j++){
            float pv = e[j]*inv;
            g_s2[grow*16+j]=pv;
            g_s2eh[grow*32+j]=__float2half(pv);
            q += pv*pv;
        }
        g_s2eh[grow*32+16]=__float2half(1.0f);
        #pragma unroll
        for(int j=17;j<32;j++) g_s2eh[grow*32+j]=__float2half(0.0f);
        g_qs2[grow]=q;
    }
}

// red += s2^T [P(0:16)|s2|x2] over 128-row slices ; den2 partial folded in
__global__ void k6a_kernel(){
    int b = blockIdx.y, tid = threadIdx.x;      // 256
    int rb = blockIdx.x*128;
    int k = tid >> 4, cg = tid & 15;
    __shared__ float Mc[32][68];
    float acc[4] = {0,0,0,0};
    float dp = 0.f;
    for(int ch=0;ch<4;ch++){
        int base = b*NN + rb + ch*32;
        __syncthreads();
        for(int i=tid;i<32*64;i+=256){
            int r=i>>6, c=i&63;
            int row = base + r;
            float v;
            if(c<16) v = g_P[row*32 + c];
            else if(c<32) v = g_s2[row*16 + (c-16)];
            else v = g_x2[row*32 + (c-32)];
            Mc[r][c] = v;
        }
        __syncthreads();
        if(tid<32) dp += (g_P[(base+tid)*32+16] + EPSF)*g_qs2[base+tid];
        #pragma unroll 4
        for(int r=0;r<32;r++){
            float s2v = Mc[r][16+k];
            float4 m = *(const float4*)&Mc[r][cg*4];
            acc[0] += s2v*m.x; acc[1] += s2v*m.y; acc[2] += s2v*m.z; acc[3] += s2v*m.w;
        }
    }
    #pragma unroll
    for(int j=0;j<4;j++)
        atomicAdd(&g_red[b*1024 + k*64 + cg*4 + j], acc[j]);
    dp = blockReduceSum(dp);
    if(tid==0) atomicAdd(&g_den2[b], dp);
}

// per-batch tail: tdd, ortho1, ortho2, mincut-normalize + conv2 + MLP + log_softmax
__global__ void tail_kernel(const float* __restrict__ Wrel2, const float* __restrict__ brel2,
                            const float* __restrict__ Wroot2,
                            const float* __restrict__ W2, const float* __restrict__ b2,
                            const float* __restrict__ W3, const float* __restrict__ b3,
                            float* __restrict__ out){
    int tid = threadIdx.x;                       // 256
    int b = blockIdx.x;
    float td = 0.f;
    for(int n=tid;n<NN;n+=256) td += g_dflat[b*NN+n]*g_qn[b*NN+n];
    td = blockReduceSum(td);
    if(tid==0) g_tdd[b] = td;
    {
        const float* ssb = g_ss + b*KC*KC;
        float p = 0.f;
        for(int i=tid;i<KC*KC;i+=256){ float x=ssb[i]; p += x*x; }
        float ssn = sqrtf(blockReduceSum(p));
        float inv = 1.0f/ssn;
        p = 0.f;
        for(int i=tid;i<KC*KC;i+=256){
            float d = ssb[i]*inv - ((i%(KC+1))==0 ? 1.0f : 0.0f);
            p += d*d;
        }
        p = blockReduceSum(p);
        if(tid==0) g_o1b[b] = p;
    }
    {
        float x = g_red[b*1024 + (tid>>4)*64 + 16 + (tid&15)];
        float ssn2 = sqrtf(blockReduceSum(x*x));
        float d = x/ssn2 - ((tid%17)==0 ? 0.25f : 0.0f);
        float fb = blockReduceSum(d*d);
        if(tid==0) g_o2b[b] = sqrtf(fb);
    }
    __shared__ float oa[16][17];
    __shared__ float dk[16], ca[16], mS[32], oS[32], xsum[32], hsh[32], lsh[16];
    { int k=tid>>4, l=tid&15; float x=g_red[b*1024 + k*64 + l]; if(k==l) x=0.f; oa[k][l]=x; }
    __syncthreads();
    if(tid<16){
        float rs=0.f; for(int l=0;l<16;l++) rs += oa[tid][l];
        dk[tid] = sqrtf(rs + EPSF) + EPSF;
    }
    __syncthreads();
    { int k=tid>>4, l=tid&15; oa[k][l] = oa[k][l]/(dk[k]*dk[l]); }
    __syncthreads();
    if(tid<16){ float c=0.f; for(int k=0;k<16;k++) c += oa[k][tid]; ca[tid]=c; }
    __syncthreads();
    if(tid<32){
        float m=0.f, o=0.f;
        for(int l=0;l<16;l++){ float ox=g_red[b*1024 + l*64 + 32 + tid]; m += ca[l]*ox; o += ox; }
        mS[tid]=m; oS[tid]=o;
    }
    __syncthreads();
    if(tid<32){
        float x = 16.0f*brel2[tid];
        for(int g=0;g<32;g++) x += mS[g]*Wrel2[g*32+tid] + oS[g]*Wroot2[g*32+tid];
        xsum[tid] = x;
    }
    __syncthreads();
    if(tid<32){
        float h = b2[tid];
        for(int g=0;g<32;g++) h += xsum[g]*W2[g*32+tid];
        hsh[tid] = fmaxf(h, 0.f);
    }
    __syncthreads();
    if(tid<10){
        float lg = b3[tid];
        for(int g=0;g<32;g++) lg += hsh[g]*W3[g*10+tid];
        lsh[tid] = lg;
    }
    __syncthreads();
    if(tid==0){
        float m = lsh[0];
        for(int o=1;o<10;o++) m = fmaxf(m, lsh[o]);
        float s = 0.f;
        for(int o=0;o<10;o++) s += expf(lsh[o]-m);
        float lse = m + logf(s);
        for(int o=0;o<10;o++) out[b*10+o] = lsh[o]-lse;
    }
}

__global__ void loss_kernel(float* __restrict__ out){
    int tid = threadIdx.x;                       // 256
    float v = 0.f;
    if(tid<BB){
        float tddf = g_tdd[tid];
        v = (tddf - g_tda[tid])/(tddf + EPSF);
    }
    float ct_loss = blockReduceSum(v)*(1.0f/BB);
    v = (tid<BB) ? g_o1b[tid] : 0.f;
    float ortho1 = sqrtf(blockReduceSum(v));
    v = 0.f;
    if(tid<BB){
        float num = 0.f;
        for(int k=0;k<K2C;k++) num += g_red[tid*1024 + k*64 + k];
        v = -num/g_den2[tid];
    }
    float mc_loss = blockReduceSum(v)*(1.0f/BB);
    v = (tid<BB) ? g_o2b[tid] : 0.f;
    float ortho2 = blockReduceSum(v)*(1.0f/BB);
    if(tid==0){ out[160] = ct_loss + ortho1; out[161] = mc_loss + ortho2; }
}

// ---------------- launch ----------------
extern "C" void kernel_launch(void* const* d_in, const int* in_sizes, int n_in,
                              void* d_out, int out_size){
    const float* x       = (const float*)d_in[0];
    const float* adj     = (const float*)d_in[1];
    const float* W_lin1  = (const float*)d_in[3];
    const float* b_lin1  = (const float*)d_in[4];
    const float* W_pool1 = (const float*)d_in[5];
    const float* b_pool1 = (const float*)d_in[6];
    const float* W_pool2 = (const float*)d_in[7];
    const float* b_pool2 = (const float*)d_in[8];
    const float* Wrel1   = (const float*)d_in[9];
    const float* brel1   = (const float*)d_in[10];
    const float* Wroot1  = (const float*)d_in[11];
    const float* Wrel2   = (const float*)d_in[12];
    const float* brel2   = (const float*)d_in[13];
    const float* Wroot2  = (const float*)d_in[14];
    const float* W_lin2  = (const float*)d_in[15];
    const float* b_lin2  = (const float*)d_in[16];
    const float* W_lin3  = (const float*)d_in[17];
    const float* b_lin3  = (const float*)d_in[18];
    float* out = (float*)d_out;

    zero_kernel<<<64,256>>>();
    lin1pool_kernel<<<BB*NN/64, 128>>>(x, W_lin1, b_lin1, W_pool1, b_pool1);
    ct_main_kernel<<<dim3(36,BB), 256>>>(adj);
    bmm_Y_kernel<<<dim3(16,BB), 128>>>();
    k4_kernel<<<BB*NN/64, 256>>>(Wrel1, brel1, Wroot1, W_pool2, b_pool2);
    bmm_P_kernel<<<dim3(16,BB), 128>>>();
    k6a_kernel<<<dim3(8,BB), 256>>>();
    tail_kernel<<<BB, 256>>>(Wrel2, brel2, Wroot2, W_lin2, b_lin2, W_lin3, b_lin3, out);
    loss_kernel<<<1, 256>>>(out);
}

// round 11
// speedup vs baseline: 2.5115x; 1.2566x over previous
#include <cuda_runtime.h>
#include <cuda_fp16.h>
#include <math.h>
#include <stdint.h>

#define BB 16
#define NN 1024
#define FIN 128
#define HH 32
#define KC 64
#define K2C 16
#define EPSF 1e-15f

// ---------------- device scratch ----------------
__device__ float g_x1[BB*NN*HH];
__device__ __half g_x1h[BB*NN*HH];
__device__ float g_s [BB*NN*KC];
__device__ float g_qn[BB*NN];
__device__ float g_dflat[BB*NN];          // rowsum(adj), atomic
__device__ float g_vol[BB];               // atomic
__device__ float g_tda[BB];               // atomic
__device__ float g_tdd[BB];
__device__ __half g_T[(size_t)BB*NN*NN];  // cdist*adj (fp16, no /vol)
__device__ float g_Y[BB*NN*HH];
__device__ float g_x2[BB*NN*HH];
__device__ float g_s2[BB*NN*K2C];
__device__ __half g_s2eh[BB*NN*32];       // [s2 | 1 | 0...] fp16
__device__ float g_qs2[BB*NN];
__device__ float g_P[BB*NN*32];
__device__ float g_ss[BB*KC*KC];          // atomic
__device__ float g_red[BB*16*64];         // atomic: c<16 oadj | 16..31 ss2 | 32..63 outx
__device__ float g_den2[BB];              // atomic
__device__ float g_o1b[BB];
__device__ float g_o2b[BB];

// ---------------- helpers ----------------
__device__ __forceinline__ float blockReduceSum(float v){
    __shared__ float sh[32];
    int tid = threadIdx.x;
    int nth = blockDim.x;
    int lane = tid & 31, wid = tid >> 5;
    __syncthreads();
    #pragma unroll
    for(int o=16;o;o>>=1) v += __shfl_down_sync(0xffffffffu, v, o);
    if(lane==0) sh[wid] = v;
    __syncthreads();
    float r = (tid < (nth>>5)) ? sh[tid] : 0.f;
    if(wid==0){
        #pragma unroll
        for(int o=16;o;o>>=1) r += __shfl_down_sync(0xffffffffu, r, o);
        if(lane==0) sh[0] = r;
    }
    __syncthreads();
    return sh[0];
}

__device__ __forceinline__ uint32_t smem_u32(const void* p){
    uint32_t a;
    asm("{ .reg .u64 t; cvta.to.shared.u64 t, %1; cvt.u32.u64 %0, t; }" : "=r"(a) : "l"(p));
    return a;
}
__device__ __forceinline__ void ldsm_x4(uint32_t&r0,uint32_t&r1,uint32_t&r2,uint32_t&r3,uint32_t a){
    asm volatile("ldmatrix.sync.aligned.m8n8.x4.shared.b16 {%0,%1,%2,%3}, [%4];"
        :"=r"(r0),"=r"(r1),"=r"(r2),"=r"(r3):"r"(a));
}
__device__ __forceinline__ void ldsm_x4_t(uint32_t&r0,uint32_t&r1,uint32_t&r2,uint32_t&r3,uint32_t a){
    asm volatile("ldmatrix.sync.aligned.m8n8.x4.trans.shared.b16 {%0,%1,%2,%3}, [%4];"
        :"=r"(r0),"=r"(r1),"=r"(r2),"=r"(r3):"r"(a));
}
__device__ __forceinline__ void mma16816(float* c, uint32_t a0,uint32_t a1,uint32_t a2,uint32_t a3,
                                         uint32_t b0,uint32_t b1){
    asm volatile("mma.sync.aligned.m16n8k16.row.col.f32.f16.f16.f32 "
        "{%0,%1,%2,%3}, {%4,%5,%6,%7}, {%8,%9}, {%0,%1,%2,%3};"
        : "+f"(c[0]),"+f"(c[1]),"+f"(c[2]),"+f"(c[3])
        : "r"(a0),"r"(a1),"r"(a2),"r"(a3),"r"(b0),"r"(b1));
}
__device__ __forceinline__ void cp_async16(uint32_t smem_addr, const void* gptr){
    asm volatile("cp.async.ca.shared.global [%0], [%1], 16;" :: "r"(smem_addr), "l"(gptr));
}
__device__ __forceinline__ void cp_commit(){ asm volatile("cp.async.commit_group;" ::: "memory"); }
template<int N> __device__ __forceinline__ void cp_wait(){ asm volatile("cp.async.wait_group %0;" :: "n"(N) : "memory"); }

// ---------------- kernels ----------------
__global__ void zero_kernel(){
    int t = blockIdx.x*256 + threadIdx.x;
    int stride = gridDim.x*256;
    for(int i=t;i<BB;i+=stride){ g_tda[i]=0.f; g_vol[i]=0.f; g_den2[i]=0.f; }
    for(int i=t;i<BB*NN;i+=stride) g_dflat[i]=0.f;
    for(int i=t;i<BB*KC*KC;i+=stride) g_ss[i]=0.f;
    for(int i=t;i<BB*16*64;i+=stride) g_red[i]=0.f;
}

// Fused: x1 = x@W1+b1 ; s = tanh(x1@Wp+bp); qn; ss += s^T s (atomics)
__global__ __launch_bounds__(128) void lin1pool_kernel(
        const float* __restrict__ x, const float* __restrict__ W1, const float* __restrict__ b1,
        const float* __restrict__ Wp, const float* __restrict__ bp){
    __shared__ float Ws[FIN][36];
    __shared__ float xt[2][32][68];
    __shared__ float Wps[HH][68];
    __shared__ float bps[KC];
    __shared__ float x1s[64][33];
    __shared__ float sS[64][68];
    int tid = threadIdx.x;                 // 128
    int colg = tid & 7, rowg = tid >> 3;
    int rowbase = blockIdx.x*64;
    int b = rowbase >> 10;
    for(int i=tid;i<FIN*32;i+=128){ int k=i>>5,c=i&31; Ws[k][c]=W1[i]; }
    for(int i=tid;i<HH*KC;i+=128){ int k=i>>6,c=i&63; Wps[k][c]=Wp[i]; }
    if(tid<KC) bps[tid]=bp[tid];
    for(int i=tid;i<2048;i+=128){ int r=i>>5,k=i&31; xt[0][k][r]=x[(size_t)(rowbase+r)*FIN + k]; }
    float acc[4][4] = {};
    #pragma unroll
    for(int kc=0;kc<4;kc++){
        __syncthreads();
        if(kc<3){
            int nb=(kc+1)&1;
            for(int i=tid;i<2048;i+=128){ int r=i>>5,k=i&31; xt[nb][k][r]=x[(size_t)(rowbase+r)*FIN + (kc+1)*32 + k]; }
        }
        int cb=kc&1;
        #pragma unroll
        for(int k=0;k<32;k++){
            float4 a = *(const float4*)&xt[cb][k][rowg*4];
            float4 w = *(const float4*)&Ws[kc*32+k][colg*4];
            float av[4]={a.x,a.y,a.z,a.w}, wv[4]={w.x,w.y,w.z,w.w};
            #pragma unroll
            for(int i=0;i<4;i++)
                #pragma unroll
                for(int j=0;j<4;j++) acc[i][j] += av[i]*wv[j];
        }
    }
    float4 bb = *(const float4*)&b1[colg*4];
    float bv[4]={bb.x,bb.y,bb.z,bb.w};
    #pragma unroll
    for(int i=0;i<4;i++){
        int lr = rowg*4+i;
        float4 res = make_float4(acc[i][0]+bv[0],acc[i][1]+bv[1],acc[i][2]+bv[2],acc[i][3]+bv[3]);
        *(float4*)&g_x1[(rowbase+lr)*HH + colg*4] = res;
        __align__(8) __half2 hh[2];
        hh[0]=__floats2half2_rn(res.x,res.y); hh[1]=__floats2half2_rn(res.z,res.w);
        *(uint2*)&g_x1h[(rowbase+lr)*HH + colg*4] = *(uint2*)hh;
        x1s[lr][colg*4+0]=res.x; x1s[lr][colg*4+1]=res.y;
        x1s[lr][colg*4+2]=res.z; x1s[lr][colg*4+3]=res.w;
    }
    __syncthreads();
    // pool phase
    {
        int r = tid>>1, half = tid&1;
        int cb2 = half*32;
        float sv[32];
        #pragma unroll
        for(int c=0;c<32;c++) sv[c]=bps[cb2+c];
        #pragma unroll
        for(int k=0;k<32;k++){
            float xk = x1s[r][k];
            #pragma unroll
            for(int c4=0;c4<8;c4++){
                float4 w = *(const float4*)&Wps[k][cb2+c4*4];
                sv[c4*4+0] += xk*w.x; sv[c4*4+1] += xk*w.y;
                sv[c4*4+2] += xk*w.z; sv[c4*4+3] += xk*w.w;
            }
        }
        float q = 0.f;
        int grow = rowbase + r;
        #pragma unroll
        for(int c=0;c<32;c++){ float s=tanhf(sv[c]); sv[c]=s; q += s*s; }
        #pragma unroll
        for(int c4=0;c4<8;c4++){
            float4 res = make_float4(sv[c4*4],sv[c4*4+1],sv[c4*4+2],sv[c4*4+3]);
            *(float4*)&g_s[grow*KC + cb2 + c4*4] = res;
            *(float4*)&sS[r][cb2 + c4*4] = res;
        }
        q += __shfl_xor_sync(0xffffffffu, q, 1);
        if(half==0) g_qn[grow] = q;
    }
    __syncthreads();
    // ss phase
    {
        int kg = tid>>3, lg = tid&7;
        float accs[4][8] = {};
        #pragma unroll 4
        for(int r=0;r<64;r++){
            float4 a  = *(const float4*)&sS[r][kg*4];
            float4 c0 = *(const float4*)&sS[r][lg*4];
            float4 c1 = *(const float4*)&sS[r][lg*4+32];
            float av[4]={a.x,a.y,a.z,a.w};
            float cv[8]={c0.x,c0.y,c0.z,c0.w,c1.x,c1.y,c1.z,c1.w};
            #pragma unroll
            for(int i=0;i<4;i++)
                #pragma unroll
                for(int j=0;j<8;j++) accs[i][j] += av[i]*cv[j];
        }
        #pragma unroll
        for(int i=0;i<4;i++)
            #pragma unroll
            for(int j=0;j<8;j++){
                int col = (j<4) ? lg*4+j : lg*4+32+(j-4);
                atomicAdd(&g_ss[(b*KC + kg*4+i)*KC + col], accs[i][j]);
            }
    }
}

// Symmetric fused: Gram -> cdist -> T(fp16) ; accumulates tda, dflat, vol
__global__ __launch_bounds__(256) void ct_main_kernel(const float* __restrict__ adj){
    __shared__ float As[32][132];
    __shared__ float Bs[32][132];
    __shared__ float qa[128], qb[128];
    int b = blockIdx.y;
    int p = blockIdx.x, ti = 0;
    while(p >= 8-ti){ p -= 8-ti; ti++; }
    int tj = ti + p;
    int rowbase = ti*128, colbase = tj*128;
    int tid = threadIdx.x;
    int tx = tid & 15, ty = tid >> 4;
    const float* Sp = g_s + b*NN*KC;
    if(tid<128) qa[tid] = g_qn[b*NN+rowbase+tid];
    else qb[tid-128] = g_qn[b*NN+colbase+(tid-128)];
    float acc[8][8] = {};
    #pragma unroll
    for(int kc=0;kc<2;kc++){
        __syncthreads();
        for(int i=tid;i<4096;i+=256){ int r=i>>5,k=i&31; As[k][r]=Sp[(rowbase+r)*KC + kc*32 + k]; }
        for(int i=tid;i<4096;i+=256){ int r=i>>5,k=i&31; Bs[k][r]=Sp[(colbase+r)*KC + kc*32 + k]; }
        __syncthreads();
        #pragma unroll 8
        for(int k=0;k<32;k++){
            float4 a0=*(const float4*)&As[k][ty*8];
            float4 a1=*(const float4*)&As[k][ty*8+4];
            float4 b0=*(const float4*)&Bs[k][tx*4];
            float4 b1=*(const float4*)&Bs[k][tx*4+64];
            float av[8]={a0.x,a0.y,a0.z,a0.w,a1.x,a1.y,a1.z,a1.w};
            float bv[8]={b0.x,b0.y,b0.z,b0.w,b1.x,b1.y,b1.z,b1.w};
            #pragma unroll
            for(int i=0;i<8;i++)
                #pragma unroll
                for(int j=0;j<8;j++) acc[i][j] += av[i]*bv[j];
        }
    }
    float tda = 0.f, volp = 0.f;
    const float* Ap = adj + (size_t)b*NN*NN;
    __half* Tp = g_T + (size_t)b*NN*NN;
    #pragma unroll
    for(int i=0;i<8;i++){
        int row = rowbase + ty*8 + i;
        size_t ro = (size_t)row*NN;
        float4 j0 = *(const float4*)&Ap[ro + colbase + tx*4];
        float4 j1 = *(const float4*)&Ap[ro + colbase + tx*4 + 64];
        float aj[8]={j0.x,j0.y,j0.z,j0.w,j1.x,j1.y,j1.z,j1.w};
        float qai = qa[ty*8+i];
        float rr[8]; float rp = 0.f;
        #pragma unroll
        for(int j=0;j<8;j++){
            int cj = tx*4 + ((j<4)? j : 60+j);
            float g = acc[i][j];
            float d2 = qai + qb[cj] - 2.0f*g;
            rr[j] = sqrtf(fmaxf(d2, 0.f)) * aj[j];
            tda += aj[j]*g; rp += aj[j];
        }
        __align__(8) __half2 p0[2], p1[2];
        p0[0]=__floats2half2_rn(rr[0],rr[1]); p0[1]=__floats2half2_rn(rr[2],rr[3]);
        p1[0]=__floats2half2_rn(rr[4],rr[5]); p1[1]=__floats2half2_rn(rr[6],rr[7]);
        *(uint2*)&Tp[ro + colbase + tx*4]      = *(uint2*)p0;
        *(uint2*)&Tp[ro + colbase + tx*4 + 64] = *(uint2*)p1;
        volp += rp;
        #pragma unroll
        for(int o=8;o;o>>=1) rp += __shfl_down_sync(0xffffffffu, rp, o, 16);
        if(tx==0) atomicAdd(&g_dflat[b*NN+row], rp);
    }
    if(ti != tj){
        #pragma unroll
        for(int jj=0;jj<8;jj++){
            int cj = tx*4 + ((jj<4)? jj : 60+jj);
            int row = colbase + cj;
            size_t ro = (size_t)row*NN;
            float4 t0 = *(const float4*)&Ap[ro + rowbase + ty*8];
            float4 t1 = *(const float4*)&Ap[ro + rowbase + ty*8 + 4];
            float aj[8]={t0.x,t0.y,t0.z,t0.w,t1.x,t1.y,t1.z,t1.w};
            float qbj = qb[cj];
            float rr[8]; float rp = 0.f;
            #pragma unroll
            for(int ii=0;ii<8;ii++){
                float g = acc[ii][jj];
                float d2 = qa[ty*8+ii] + qbj - 2.0f*g;
                rr[ii] = sqrtf(fmaxf(d2, 0.f)) * aj[ii];
                tda += aj[ii]*g; rp += aj[ii];
            }
            __align__(16) __half2 pm[4];
            pm[0]=__floats2half2_rn(rr[0],rr[1]); pm[1]=__floats2half2_rn(rr[2],rr[3]);
            pm[2]=__floats2half2_rn(rr[4],rr[5]); pm[3]=__floats2half2_rn(rr[6],rr[7]);
            *(uint4*)&Tp[ro + rowbase + ty*8] = *(uint4*)pm;
            volp += rp;
            atomicAdd(&g_dflat[b*NN+row], rp);
        }
    }
    volp = blockReduceSum(volp);
    if(tid==0) atomicAdd(&g_vol[b], volp);
    tda = blockReduceSum(tda);
    if(tid==0) atomicAdd(&g_tda[b], tda);
}

// O[b] = invvol * (T[b] @ Xh[b]) via mma.m16n8k16 + cp.async 3-stage pipeline
// 64-row tile, 256 thr (8 warps: 4 row-groups x 2 col-groups), grid (16,BB)
#define BST 3
__device__ __forceinline__ void bmm_mma(const __half* __restrict__ Xh, float* __restrict__ O){
    __shared__ __align__(16) __half At[BST][64][72];
    __shared__ __align__(16) __half Xs[BST][64][40];
    int b = blockIdx.y, rowbase = blockIdx.x*64;
    int tid = threadIdx.x;
    int w = tid>>5, lane = tid&31;
    int wr = (w&3)*16, wc = (w>>2)*16;          // warp row/col base
    const __half* Ab = g_T + (size_t)b*NN*NN;
    const __half* Xb = Xh + (size_t)b*NN*32;
    float c[2][4] = {};
    uint32_t at_base = smem_u32(&At[0][0][0]);
    uint32_t xs_base = smem_u32(&Xs[0][0][0]);
    // per-thread load slots: T: i=tid, tid+256 (512 xfers); X: tid<256 -> 256 xfers
    int tr0 = tid>>3,        tq0 = tid&7;
    int tr1 = (tid+256)>>3,  tq1 = (tid+256)&7;
    int xr  = tid>>2,        xq  = tid&2 ? (tid&3) : (tid&3); // = tid&3
    xq = tid&3;
    // prologue: stages 0..BST-1
    #pragma unroll
    for(int s=0;s<BST;s++){
        size_t ko = (size_t)s*64;
        cp_async16(at_base + (s*64*72 + tr0*72 + tq0*8)*2, &Ab[(size_t)(rowbase+tr0)*NN + ko + tq0*8]);
        cp_async16(at_base + (s*64*72 + tr1*72 + tq1*8)*2, &Ab[(size_t)(rowbase+tr1)*NN + ko + tq1*8]);
        cp_async16(xs_base + (s*64*40 + xr*40 + xq*8)*2,   &Xb[(ko+xr)*32 + xq*8]);
        cp_commit();
    }
    int a_row = lane & 15, a_half = lane >> 4;
    int b_t = lane >> 3, b_row = lane & 7;
    for(int kt=0;kt<16;kt++){
        cp_wait<BST-1>();
        __syncthreads();
        int cs = kt%BST;
        uint32_t atb = at_base + cs*(64*72*2);
        uint32_t xsb = xs_base + cs*(64*40*2);
        #pragma unroll
        for(int kk=0;kk<4;kk++){
            uint32_t a0,a1,a2,a3;
            ldsm_x4(a0,a1,a2,a3, atb + ((wr + a_row)*72 + kk*16 + a_half*8)*2);
            uint32_t b0,b1,b2,b3;
            ldsm_x4_t(b0,b1,b2,b3, xsb + ((kk*16 + b_row + (b_t&1)*8)*40 + wc + (b_t>>1)*8)*2);
            mma16816(c[0], a0,a1,a2,a3, b0,b1);
            mma16816(c[1], a0,a1,a2,a3, b2,b3);
        }
        __syncthreads();
        if(kt+BST<16){
            int s = (kt+BST)%BST;
            size_t ko = (size_t)(kt+BST)*64;
            cp_async16(at_base + (s*64*72 + tr0*72 + tq0*8)*2, &Ab[(size_t)(rowbase+tr0)*NN + ko + tq0*8]);
            cp_async16(at_base + (s*64*72 + tr1*72 + tq1*8)*2, &Ab[(size_t)(rowbase+tr1)*NN + ko + tq1*8]);
            cp_async16(xs_base + (s*64*40 + xr*40 + xq*8)*2,   &Xb[(ko+xr)*32 + xq*8]);
            cp_commit();
        }
    }
    float iv = 1.0f/(g_vol[b] + (float)NN*EPSF);
    float* Ob = O + (size_t)b*NN*32;
    int row0 = rowbase + wr + (lane>>2);
    int col0 = wc + (lane&3)*2;
    #pragma unroll
    for(int t=0;t<2;t++){
        *(float2*)&Ob[(size_t)row0*32 + t*8 + col0]     = make_float2(c[t][0]*iv, c[t][1]*iv);
        *(float2*)&Ob[(size_t)(row0+8)*32 + t*8 + col0] = make_float2(c[t][2]*iv, c[t][3]*iv);
    }
}

__global__ __launch_bounds__(256) void bmm_Y_kernel(){ bmm_mma(g_x1h, g_Y); }
__global__ __launch_bounds__(256) void bmm_P_kernel(){ bmm_mma(g_s2eh, g_P); }

// x2 = (Y@Wrel + brel) + x1@Wroot ; s2 = softmax(x2@Wp2+bp2); qs2; s2eh
__global__ __launch_bounds__(256) void k4_kernel(
        const float* __restrict__ Wrel, const float* __restrict__ brel,
        const float* __restrict__ Wroot, const float* __restrict__ Wp2,
        const float* __restrict__ bp2){
    __shared__ float Wr[32][33], Wo[32][33], Wp[32][17];
    __shared__ float brs[32], bps[16];
    __shared__ float Ys[64][33], Xs[64][33], x2s[64][33], lgS[64][17];
    int tid = threadIdx.x;
    for(int i=tid;i<1024;i+=256){ int k=i>>5,c=i&31; Wr[k][c]=Wrel[i]; Wo[k][c]=Wroot[i]; }
    for(int i=tid;i<512;i+=256){ int k=i>>4,c=i&15; Wp[k][c]=Wp2[i]; }
    if(tid<32) brs[tid]=brel[tid];
    if(tid<16) bps[tid]=bp2[tid];
    int rowbase = blockIdx.x*64;
    for(int i=tid;i<2048;i+=256){ int r=i>>5,c=i&31;
        Ys[r][c]=g_Y[(rowbase+r)*32+c]; Xs[r][c]=g_x1[(rowbase+r)*32+c]; }
    __syncthreads();
    {
        int col = tid & 31, rg = tid >> 5;
        float a8[8];
        #pragma unroll
        for(int rr=0;rr<8;rr++) a8[rr] = brs[col];
        #pragma unroll
        for(int k=0;k<32;k++){
            float wrv = Wr[k][col], wo = Wo[k][col];
            #pragma unroll
            for(int rr=0;rr<8;rr++){
                int row = rg*8+rr;
                a8[rr] += Ys[row][k]*wrv + Xs[row][k]*wo;
            }
        }
        #pragma unroll
        for(int rr=0;rr<8;rr++){
            int row = rg*8+rr;
            x2s[row][col] = a8[rr];
            g_x2[(rowbase+row)*32+col] = a8[rr];
        }
    }
    __syncthreads();
    {
        int row = tid>>2, cq = tid&3;
        float lg[4];
        #pragma unroll
        for(int c=0;c<4;c++) lg[c]=bps[cq*4+c];
        #pragma unroll
        for(int k=0;k<32;k++){
            float xv = x2s[row][k];
            #pragma unroll
            for(int c=0;c<4;c++) lg[c] += xv*Wp[k][cq*4+c];
        }
        #pragma unroll
        for(int c=0;c<4;c++) lgS[row][cq*4+c]=lg[c];
    }
    __syncthreads();
    if(tid<64){
        int row = tid, grow = rowbase + row;
        float m = lgS[row][0];
        #pragma unroll
        for(int j=1;j<16;j++) m = fmaxf(m, lgS[row][j]);
        float e[16], sum=0.f;
        #pragma unroll
        for(int j=0;j<16;j++){ e[j]=expf(lgS[row][j]-m); sum+=e[j]; }
        float inv = 1.0f/sum, q=0.f;
        #pragma unroll
        for(int j=0;j<16;j++){
            float pv = e[j]*inv;
            g_s2[grow*16+j]=pv;
            g_s2eh[grow*32+j]=__float2half(pv);
            q += pv*pv;
        }
        g_s2eh[grow*32+16]=__float2half(1.0f);
        #pragma unroll
        for(int j=17;j<32;j++) g_s2eh[grow*32+j]=__float2half(0.0f);
        g_qs2[grow]=q;
    }
}

// red += s2^T [P(0:16)|s2|x2] over 128-row slices ; den2 partial folded in
__global__ void k6a_kernel(){
    int b = blockIdx.y, tid = threadIdx.x;      // 256
    int rb = blockIdx.x*128;
    int k = tid >> 4, cg = tid & 15;
    __shared__ float Mc[32][68];
    float acc[4] = {0,0,0,0};
    float dp = 0.f;
    for(int ch=0;ch<4;ch++){
        int base = b*NN + rb + ch*32;
        __syncthreads();
        for(int i=tid;i<32*64;i+=256){
            int r=i>>6, c=i&63;
            int row = base + r;
            float v;
            if(c<16) v = g_P[row*32 + c];
            else if(c<32) v = g_s2[row*16 + (c-16)];
            else v = g_x2[row*32 + (c-32)];
            Mc[r][c] = v;
        }
        __syncthreads();
        if(tid<32) dp += (g_P[(base+tid)*32+16] + EPSF)*g_qs2[base+tid];
        #pragma unroll 4
        for(int r=0;r<32;r++){
            float s2v = Mc[r][16+k];
            float4 m = *(const float4*)&Mc[r][cg*4];
            acc[0] += s2v*m.x; acc[1] += s2v*m.y; acc[2] += s2v*m.z; acc[3] += s2v*m.w;
        }
    }
    #pragma unroll
    for(int j=0;j<4;j++)
        atomicAdd(&g_red[b*1024 + k*64 + cg*4 + j], acc[j]);
    dp = blockReduceSum(dp);
    if(tid==0) atomicAdd(&g_den2[b], dp);
}

// per-batch tail: tdd, ortho1, ortho2, mincut-normalize + conv2 + MLP + log_softmax
__global__ void tail_kernel(const float* __restrict__ Wrel2, const float* __restrict__ brel2,
                            const float* __restrict__ Wroot2,
                            const float* __restrict__ W2, const float* __restrict__ b2,
                            const float* __restrict__ W3, const float* __restrict__ b3,
                            float* __restrict__ out){
    int tid = threadIdx.x;                       // 256
    int b = blockIdx.x;
    float td = 0.f;
    for(int n=tid;n<NN;n+=256) td += g_dflat[b*NN+n]*g_qn[b*NN+n];
    td = blockReduceSum(td);
    if(tid==0) g_tdd[b] = td;
    {
        const float* ssb = g_ss + b*KC*KC;
        float p = 0.f;
        for(int i=tid;i<KC*KC;i+=256){ float x=ssb[i]; p += x*x; }
        float ssn = sqrtf(blockReduceSum(p));
        float inv = 1.0f/ssn;
        p = 0.f;
        for(int i=tid;i<KC*KC;i+=256){
            float d = ssb[i]*inv - ((i%(KC+1))==0 ? 1.0f : 0.0f);
            p += d*d;
        }
        p = blockReduceSum(p);
        if(tid==0) g_o1b[b] = p;
    }
    {
        float x = g_red[b*1024 + (tid>>4)*64 + 16 + (tid&15)];
        float ssn2 = sqrtf(blockReduceSum(x*x));
        float d = x/ssn2 - ((tid%17)==0 ? 0.25f : 0.0f);
        float fb = blockReduceSum(d*d);
        if(tid==0) g_o2b[b] = sqrtf(fb);
    }
    __shared__ float oa[16][17];
    __shared__ float dk[16], ca[16], mS[32], oS[32], xsum[32], hsh[32], lsh[16];
    { int k=tid>>4, l=tid&15; float x=g_red[b*1024 + k*64 + l]; if(k==l) x=0.f; oa[k][l]=x; }
    __syncthreads();
    if(tid<16){
        float rs=0.f; for(int l=0;l<16;l++) rs += oa[tid][l];
        dk[tid] = sqrtf(rs + EPSF) + EPSF;
    }
    __syncthreads();
    { int k=tid>>4, l=tid&15; oa[k][l] = oa[k][l]/(dk[k]*dk[l]); }
    __syncthreads();
    if(tid<16){ float c=0.f; for(int k=0;k<16;k++) c += oa[k][tid]; ca[tid]=c; }
    __syncthreads();
    if(tid<32){
        float m=0.f, o=0.f;
        for(int l=0;l<16;l++){ float ox=g_red[b*1024 + l*64 + 32 + tid]; m += ca[l]*ox; o += ox; }
        mS[tid]=m; oS[tid]=o;
    }
    __syncthreads();
    if(tid<32){
        float x = 16.0f*brel2[tid];
        for(int g=0;g<32;g++) x += mS[g]*Wrel2[g*32+tid] + oS[g]*Wroot2[g*32+tid];
        xsum[tid] = x;
    }
    __syncthreads();
    if(tid<32){
        float h = b2[tid];
        for(int g=0;g<32;g++) h += xsum[g]*W2[g*32+tid];
        hsh[tid] = fmaxf(h, 0.f);
    }
    __syncthreads();
    if(tid<10){
        float lg = b3[tid];
        for(int g=0;g<32;g++) lg += hsh[g]*W3[g*10+tid];
        lsh[tid] = lg;
    }
    __syncthreads();
    if(tid==0){
        float m = lsh[0];
        for(int o=1;o<10;o++) m = fmaxf(m, lsh[o]);
        float s = 0.f;
        for(int o=0;o<10;o++) s += expf(lsh[o]-m);
        float lse = m + logf(s);
        for(int o=0;o<10;o++) out[b*10+o] = lsh[o]-lse;
    }
}

__global__ void loss_kernel(float* __restrict__ out){
    int tid = threadIdx.x;                       // 256
    float v = 0.f;
    if(tid<BB){
        float tddf = g_tdd[tid];
        v = (tddf - g_tda[tid])/(tddf + EPSF);
    }
    float ct_loss = blockReduceSum(v)*(1.0f/BB);
    v = (tid<BB) ? g_o1b[tid] : 0.f;
    float ortho1 = sqrtf(blockReduceSum(v));
    v = 0.f;
    if(tid<BB){
        float num = 0.f;
        for(int k=0;k<K2C;k++) num += g_red[tid*1024 + k*64 + k];
        v = -num/g_den2[tid];
    }
    float mc_loss = blockReduceSum(v)*(1.0f/BB);
    v = (tid<BB) ? g_o2b[tid] : 0.f;
    float ortho2 = blockReduceSum(v)*(1.0f/BB);
    if(tid==0){ out[160] = ct_loss + ortho1; out[161] = mc_loss + ortho2; }
}

// ---------------- launch ----------------
extern "C" void kernel_launch(void* const* d_in, const int* in_sizes, int n_in,
                              void* d_out, int out_size){
    const float* x       = (const float*)d_in[0];
    const float* adj     = (const float*)d_in[1];
    const float* W_lin1  = (const float*)d_in[3];
    const float* b_lin1  = (const float*)d_in[4];
    const float* W_pool1 = (const float*)d_in[5];
    const float* b_pool1 = (const float*)d_in[6];
    const float* W_pool2 = (const float*)d_in[7];
    const float* b_pool2 = (const float*)d_in[8];
    const float* Wrel1   = (const float*)d_in[9];
    const float* brel1   = (const float*)d_in[10];
    const float* Wroot1  = (const float*)d_in[11];
    const float* Wrel2   = (const float*)d_in[12];
    const float* brel2   = (const float*)d_in[13];
    const float* Wroot2  = (const float*)d_in[14];
    const float* W_lin2  = (const float*)d_in[15];
    const float* b_lin2  = (const float*)d_in[16];
    const float* W_lin3  = (const float*)d_in[17];
    const float* b_lin3  = (const float*)d_in[18];
    float* out = (float*)d_out;

    zero_kernel<<<64,256>>>();
    lin1pool_kernel<<<BB*NN/64, 128>>>(x, W_lin1, b_lin1, W_pool1, b_pool1);
    ct_main_kernel<<<dim3(36,BB), 256>>>(adj);
    bmm_Y_kernel<<<dim3(16,BB), 256>>>();
    k4_kernel<<<BB*NN/64, 256>>>(Wrel1, brel1, Wroot1, W_pool2, b_pool2);
    bmm_P_kernel<<<dim3(16,BB), 256>>>();
    k6a_kernel<<<dim3(8,BB), 256>>>();
    tail_kernel<<<BB, 256>>>(Wrel2, brel2, Wroot2, W_lin2, b_lin2, W_lin3, b_lin3, out);
    loss_kernel<<<1, 256>>>(out);
}

// round 12
// speedup vs baseline: 3.2668x; 1.3008x over previous
#include <cuda_runtime.h>
#include <cuda_fp16.h>
#include <math.h>
#include <stdint.h>

#define BB 16
#define NN 1024
#define FIN 128
#define HH 32
#define KC 64
#define K2C 16
#define EPSF 1e-15f

// ---------------- device scratch ----------------
__device__ float g_x1[BB*NN*HH];
__device__ __half g_x1h[BB*NN*HH];
__device__ __half g_sh[BB*NN*KC];         // tanh(s1) fp16 (MMA operand)
__device__ float g_qn[BB*NN];
__device__ float g_dflat[BB*NN];          // rowsum(adj), atomic
__device__ float g_vol[BB];               // atomic
__device__ float g_tda[BB];               // atomic
__device__ float g_tdd[BB];
__device__ __half g_T[(size_t)BB*NN*NN];  // cdist*adj (fp16, no /vol)
__device__ float g_Y[BB*NN*HH];
__device__ float g_x2[BB*NN*HH];
__device__ float g_s2[BB*NN*K2C];
__device__ __half g_s2eh[BB*NN*32];       // [s2 | 1 | 0...] fp16
__device__ float g_qs2[BB*NN];
__device__ float g_P[BB*NN*32];
__device__ float g_ss[BB*KC*KC];          // atomic
__device__ float g_red[BB*16*64];         // atomic: c<16 oadj | 16..31 ss2 | 32..63 outx
__device__ float g_den2[BB];              // atomic
__device__ float g_o1b[BB];
__device__ float g_o2b[BB];

// ---------------- helpers ----------------
__device__ __forceinline__ float blockReduceSum(float v){
    __shared__ float sh[32];
    int tid = threadIdx.x;
    int nth = blockDim.x;
    int lane = tid & 31, wid = tid >> 5;
    __syncthreads();
    #pragma unroll
    for(int o=16;o;o>>=1) v += __shfl_down_sync(0xffffffffu, v, o);
    if(lane==0) sh[wid] = v;
    __syncthreads();
    float r = (tid < (nth>>5)) ? sh[tid] : 0.f;
    if(wid==0){
        #pragma unroll
        for(int o=16;o;o>>=1) r += __shfl_down_sync(0xffffffffu, r, o);
        if(lane==0) sh[0] = r;
    }
    __syncthreads();
    return sh[0];
}

__device__ __forceinline__ uint32_t smem_u32(const void* p){
    uint32_t a;
    asm("{ .reg .u64 t; cvta.to.shared.u64 t, %1; cvt.u32.u64 %0, t; }" : "=r"(a) : "l"(p));
    return a;
}
__device__ __forceinline__ void ldsm_x4(uint32_t&r0,uint32_t&r1,uint32_t&r2,uint32_t&r3,uint32_t a){
    asm volatile("ldmatrix.sync.aligned.m8n8.x4.shared.b16 {%0,%1,%2,%3}, [%4];"
        :"=r"(r0),"=r"(r1),"=r"(r2),"=r"(r3):"r"(a));
}
__device__ __forceinline__ void ldsm_x4_t(uint32_t&r0,uint32_t&r1,uint32_t&r2,uint32_t&r3,uint32_t a){
    asm volatile("ldmatrix.sync.aligned.m8n8.x4.trans.shared.b16 {%0,%1,%2,%3}, [%4];"
        :"=r"(r0),"=r"(r1),"=r"(r2),"=r"(r3):"r"(a));
}
__device__ __forceinline__ void mma16816(float* c, uint32_t a0,uint32_t a1,uint32_t a2,uint32_t a3,
                                         uint32_t b0,uint32_t b1){
    asm volatile("mma.sync.aligned.m16n8k16.row.col.f32.f16.f16.f32 "
        "{%0,%1,%2,%3}, {%4,%5,%6,%7}, {%8,%9}, {%0,%1,%2,%3};"
        : "+f"(c[0]),"+f"(c[1]),"+f"(c[2]),"+f"(c[3])
        : "r"(a0),"r"(a1),"r"(a2),"r"(a3),"r"(b0),"r"(b1));
}
__device__ __forceinline__ void cp_async16(uint32_t smem_addr, const void* gptr){
    asm volatile("cp.async.ca.shared.global [%0], [%1], 16;" :: "r"(smem_addr), "l"(gptr));
}
__device__ __forceinline__ void cp_commit(){ asm volatile("cp.async.commit_group;" ::: "memory"); }
template<int N> __device__ __forceinline__ void cp_wait(){ asm volatile("cp.async.wait_group %0;" :: "n"(N) : "memory"); }

// ---------------- kernels ----------------
__global__ void zero_kernel(){
    int t = blockIdx.x*256 + threadIdx.x;
    int stride = gridDim.x*256;
    for(int i=t;i<BB;i+=stride){ g_tda[i]=0.f; g_vol[i]=0.f; g_den2[i]=0.f; }
    for(int i=t;i<BB*NN;i+=stride) g_dflat[i]=0.f;
    for(int i=t;i<BB*KC*KC;i+=stride) g_ss[i]=0.f;
    for(int i=t;i<BB*16*64;i+=stride) g_red[i]=0.f;
}

// Fused: x1 = x@W1+b1 ; s = tanh(x1@Wp+bp) (fp16 out); qn; ss += s^T s (atomics)
__global__ __launch_bounds__(128) void lin1pool_kernel(
        const float* __restrict__ x, const float* __restrict__ W1, const float* __restrict__ b1,
        const float* __restrict__ Wp, const float* __restrict__ bp){
    __shared__ float Ws[FIN][36];
    __shared__ float xt[2][32][68];
    __shared__ float Wps[HH][68];
    __shared__ float bps[KC];
    __shared__ float x1s[64][33];
    __shared__ float sS[64][68];
    int tid = threadIdx.x;                 // 128
    int colg = tid & 7, rowg = tid >> 3;
    int rowbase = blockIdx.x*64;
    int b = rowbase >> 10;
    for(int i=tid;i<FIN*32;i+=128){ int k=i>>5,c=i&31; Ws[k][c]=W1[i]; }
    for(int i=tid;i<HH*KC;i+=128){ int k=i>>6,c=i&63; Wps[k][c]=Wp[i]; }
    if(tid<KC) bps[tid]=bp[tid];
    for(int i=tid;i<2048;i+=128){ int r=i>>5,k=i&31; xt[0][k][r]=x[(size_t)(rowbase+r)*FIN + k]; }
    float acc[4][4] = {};
    #pragma unroll
    for(int kc=0;kc<4;kc++){
        __syncthreads();
        if(kc<3){
            int nb=(kc+1)&1;
            for(int i=tid;i<2048;i+=128){ int r=i>>5,k=i&31; xt[nb][k][r]=x[(size_t)(rowbase+r)*FIN + (kc+1)*32 + k]; }
        }
        int cb=kc&1;
        #pragma unroll
        for(int k=0;k<32;k++){
            float4 a = *(const float4*)&xt[cb][k][rowg*4];
            float4 w = *(const float4*)&Ws[kc*32+k][colg*4];
            float av[4]={a.x,a.y,a.z,a.w}, wv[4]={w.x,w.y,w.z,w.w};
            #pragma unroll
            for(int i=0;i<4;i++)
                #pragma unroll
                for(int j=0;j<4;j++) acc[i][j] += av[i]*wv[j];
        }
    }
    float4 bb = *(const float4*)&b1[colg*4];
    float bv[4]={bb.x,bb.y,bb.z,bb.w};
    #pragma unroll
    for(int i=0;i<4;i++){
        int lr = rowg*4+i;
        float4 res = make_float4(acc[i][0]+bv[0],acc[i][1]+bv[1],acc[i][2]+bv[2],acc[i][3]+bv[3]);
        *(float4*)&g_x1[(rowbase+lr)*HH + colg*4] = res;
        __align__(8) __half2 hh[2];
        hh[0]=__floats2half2_rn(res.x,res.y); hh[1]=__floats2half2_rn(res.z,res.w);
        *(uint2*)&g_x1h[(rowbase+lr)*HH + colg*4] = *(uint2*)hh;
        x1s[lr][colg*4+0]=res.x; x1s[lr][colg*4+1]=res.y;
        x1s[lr][colg*4+2]=res.z; x1s[lr][colg*4+3]=res.w;
    }
    __syncthreads();
    // pool phase
    {
        int r = tid>>1, half = tid&1;
        int cb2 = half*32;
        float sv[32];
        #pragma unroll
        for(int c=0;c<32;c++) sv[c]=bps[cb2+c];
        #pragma unroll
        for(int k=0;k<32;k++){
            float xk = x1s[r][k];
            #pragma unroll
            for(int c4=0;c4<8;c4++){
                float4 w = *(const float4*)&Wps[k][cb2+c4*4];
                sv[c4*4+0] += xk*w.x; sv[c4*4+1] += xk*w.y;
                sv[c4*4+2] += xk*w.z; sv[c4*4+3] += xk*w.w;
            }
        }
        float q = 0.f;
        int grow = rowbase + r;
        #pragma unroll
        for(int c=0;c<32;c++){ float s=tanhf(sv[c]); sv[c]=s; q += s*s; }
        #pragma unroll
        for(int c4=0;c4<8;c4++){
            float4 res = make_float4(sv[c4*4],sv[c4*4+1],sv[c4*4+2],sv[c4*4+3]);
            __align__(8) __half2 hh[2];
            hh[0]=__floats2half2_rn(res.x,res.y); hh[1]=__floats2half2_rn(res.z,res.w);
            *(uint2*)&g_sh[grow*KC + cb2 + c4*4] = *(uint2*)hh;
            *(float4*)&sS[r][cb2 + c4*4] = res;
        }
        q += __shfl_xor_sync(0xffffffffu, q, 1);
        if(half==0) g_qn[grow] = q;
    }
    __syncthreads();
    // ss phase (fp32)
    {
        int kg = tid>>3, lg = tid&7;
        float accs[4][8] = {};
        #pragma unroll 4
        for(int r=0;r<64;r++){
            float4 a  = *(const float4*)&sS[r][kg*4];
            float4 c0 = *(const float4*)&sS[r][lg*4];
            float4 c1 = *(const float4*)&sS[r][lg*4+32];
            float av[4]={a.x,a.y,a.z,a.w};
            float cv[8]={c0.x,c0.y,c0.z,c0.w,c1.x,c1.y,c1.z,c1.w};
            #pragma unroll
            for(int i=0;i<4;i++)
                #pragma unroll
                for(int j=0;j<8;j++) accs[i][j] += av[i]*cv[j];
        }
        #pragma unroll
        for(int i=0;i<4;i++)
            #pragma unroll
            for(int j=0;j<8;j++){
                int col = (j<4) ? lg*4+j : lg*4+32+(j-4);
                atomicAdd(&g_ss[(b*KC + kg*4+i)*KC + col], accs[i][j]);
            }
    }
}

// ct_main: per-block 128x128 tile. fp16 MMA Gram -> cdist -> T(fp16)
// accumulates tda, dflat, vol. grid (8,8,BB), 256 thr (8 warps: 2 row x 4 col)
__global__ __launch_bounds__(256,2) void ct_main_kernel(const float* __restrict__ adj){
    __shared__ __align__(16) __half Srow[128][72];
    __shared__ __align__(16) __half Scol[128][72];
    __shared__ float qa[128], qb[128];
    int b = blockIdx.z;
    int rowbase = blockIdx.y*128, colbase = blockIdx.x*128;
    int tid = threadIdx.x, w = tid>>5, lane = tid&31;
    int wr = (w>>2)*64, wc = (w&3)*32;
    const __half* Sh = g_sh + b*NN*KC;
    uint32_t sr_base = smem_u32(&Srow[0][0]);
    uint32_t sc_base = smem_u32(&Scol[0][0]);
    for(int i=tid;i<1024;i+=256){
        int r=i>>3, q=i&7;
        cp_async16(sr_base + (r*72+q*8)*2, &Sh[(rowbase+r)*KC + q*8]);
        cp_async16(sc_base + (r*72+q*8)*2, &Sh[(colbase+r)*KC + q*8]);
    }
    cp_commit();
    if(tid<128) qa[tid] = g_qn[b*NN+rowbase+tid];
    else qb[tid-128] = g_qn[b*NN+colbase+(tid-128)];
    cp_wait<0>();
    __syncthreads();
    // MMA phase: warp tile 64x32, 4 m-tiles x 4 n8-tiles x 4 k-steps
    float c[4][4][4] = {};
    int a_row = lane & 15, a_half = lane >> 4;
    int b_row = (lane&7) + ((lane>>4)&1)*8;
    int b_koff = ((lane>>3)&1)*8;
    #pragma unroll
    for(int kk=0;kk<4;kk++){
        uint32_t a[4][4];
        #pragma unroll
        for(int mt=0;mt<4;mt++)
            ldsm_x4(a[mt][0],a[mt][1],a[mt][2],a[mt][3],
                sr_base + ((wr + mt*16 + a_row)*72 + kk*16 + a_half*8)*2);
        #pragma unroll
        for(int ng=0;ng<2;ng++){
            uint32_t b0,b1,b2,b3;
            ldsm_x4(b0,b1,b2,b3,
                sc_base + ((wc + ng*16 + b_row)*72 + kk*16 + b_koff)*2);
            #pragma unroll
            for(int mt=0;mt<4;mt++){
                mma16816(c[mt][ng*2],   a[mt][0],a[mt][1],a[mt][2],a[mt][3], b0,b1);
                mma16816(c[mt][ng*2+1], a[mt][0],a[mt][1],a[mt][2],a[mt][3], b2,b3);
            }
        }
    }
    // epilogue
    float tda = 0.f, volp = 0.f;
    const float* Ap = adj + (size_t)b*NN*NN;
    __half* Tp = g_T + (size_t)b*NN*NN;
    int r_in = lane>>2, c_in = (lane&3)*2;
    #pragma unroll
    for(int mt=0;mt<4;mt++){
        #pragma unroll
        for(int h=0;h<2;h++){
            int lrow = wr + mt*16 + r_in + h*8;
            int row = rowbase + lrow;
            size_t ro = (size_t)row*NN + colbase + wc;
            float qai = qa[lrow];
            float rp = 0.f;
            #pragma unroll
            for(int nt=0;nt<4;nt++){
                int lc = wc + nt*8 + c_in;
                float2 aj = *(const float2*)&Ap[ro + nt*8 + c_in];
                float g0 = c[mt][nt][h*2+0];
                float g1 = c[mt][nt][h*2+1];
                float d0 = qai + qb[lc]   - 2.0f*g0;
                float d1 = qai + qb[lc+1] - 2.0f*g1;
                float r0 = sqrtf(fmaxf(d0, 0.f))*aj.x;
                float r1 = sqrtf(fmaxf(d1, 0.f))*aj.y;
                tda += aj.x*g0 + aj.y*g1;
                rp  += aj.x + aj.y;
                *(__half2*)&Tp[ro + nt*8 + c_in] = __floats2half2_rn(r0, r1);
            }
            volp += rp;
            rp += __shfl_down_sync(0xffffffffu, rp, 1, 4);
            rp += __shfl_down_sync(0xffffffffu, rp, 2, 4);
            if((lane&3)==0) atomicAdd(&g_dflat[b*NN + row], rp);
        }
    }
    volp = blockReduceSum(volp);
    if(tid==0) atomicAdd(&g_vol[b], volp);
    tda = blockReduceSum(tda);
    if(tid==0) atomicAdd(&g_tda[b], tda);
}

// O[b] = invvol * (T[b] @ Xh[b]) via mma.m16n8k16 + cp.async 3-stage pipeline
#define BST 3
__device__ __forceinline__ void bmm_mma(const __half* __restrict__ Xh, float* __restrict__ O){
    __shared__ __align__(16) __half At[BST][64][72];
    __shared__ __align__(16) __half Xs[BST][64][40];
    int b = blockIdx.y, rowbase = blockIdx.x*64;
    int tid = threadIdx.x;
    int w = tid>>5, lane = tid&31;
    int wr = (w&3)*16, wc = (w>>2)*16;
    const __half* Ab = g_T + (size_t)b*NN*NN;
    const __half* Xb = Xh + (size_t)b*NN*32;
    float c[2][4] = {};
    uint32_t at_base = smem_u32(&At[0][0][0]);
    uint32_t xs_base = smem_u32(&Xs[0][0][0]);
    int tr0 = tid>>3,        tq0 = tid&7;
    int tr1 = (tid+256)>>3,  tq1 = (tid+256)&7;
    int xr  = tid>>2,        xq  = tid&3;
    #pragma unroll
    for(int s=0;s<BST;s++){
        size_t ko = (size_t)s*64;
        cp_async16(at_base + (s*64*72 + tr0*72 + tq0*8)*2, &Ab[(size_t)(rowbase+tr0)*NN + ko + tq0*8]);
        cp_async16(at_base + (s*64*72 + tr1*72 + tq1*8)*2, &Ab[(size_t)(rowbase+tr1)*NN + ko + tq1*8]);
        cp_async16(xs_base + (s*64*40 + xr*40 + xq*8)*2,   &Xb[(ko+xr)*32 + xq*8]);
        cp_commit();
    }
    int a_row = lane & 15, a_half = lane >> 4;
    int b_t = lane >> 3, b_row = lane & 7;
    for(int kt=0;kt<16;kt++){
        cp_wait<BST-1>();
        __syncthreads();
        int cs = kt%BST;
        uint32_t atb = at_base + cs*(64*72*2);
        uint32_t xsb = xs_base + cs*(64*40*2);
        #pragma unroll
        for(int kk=0;kk<4;kk++){
            uint32_t a0,a1,a2,a3;
            ldsm_x4(a0,a1,a2,a3, atb + ((wr + a_row)*72 + kk*16 + a_half*8)*2);
            uint32_t b0,b1,b2,b3;
            ldsm_x4_t(b0,b1,b2,b3, xsb + ((kk*16 + b_row + (b_t&1)*8)*40 + wc + (b_t>>1)*8)*2);
            mma16816(c[0], a0,a1,a2,a3, b0,b1);
            mma16816(c[1], a0,a1,a2,a3, b2,b3);
        }
        __syncthreads();
        if(kt+BST<16){
            int s = (kt+BST)%BST;
            size_t ko = (size_t)(kt+BST)*64;
            cp_async16(at_base + (s*64*72 + tr0*72 + tq0*8)*2, &Ab[(size_t)(rowbase+tr0)*NN + ko + tq0*8]);
            cp_async16(at_base + (s*64*72 + tr1*72 + tq1*8)*2, &Ab[(size_t)(rowbase+tr1)*NN + ko + tq1*8]);
            cp_async16(xs_base + (s*64*40 + xr*40 + xq*8)*2,   &Xb[(ko+xr)*32 + xq*8]);
            cp_commit();
        }
    }
    float iv = 1.0f/(g_vol[b] + (float)NN*EPSF);
    float* Ob = O + (size_t)b*NN*32;
    int row0 = rowbase + wr + (lane>>2);
    int col0 = wc + (lane&3)*2;
    #pragma unroll
    for(int t=0;t<2;t++){
        *(float2*)&Ob[(size_t)row0*32 + t*8 + col0]     = make_float2(c[t][0]*iv, c[t][1]*iv);
        *(float2*)&Ob[(size_t)(row0+8)*32 + t*8 + col0] = make_float2(c[t][2]*iv, c[t][3]*iv);
    }
}

__global__ __launch_bounds__(256) void bmm_Y_kernel(){ bmm_mma(g_x1h, g_Y); }
__global__ __launch_bounds__(256) void bmm_P_kernel(){ bmm_mma(g_s2eh, g_P); }

// x2 = (Y@Wrel + brel) + x1@Wroot ; s2 = softmax(x2@Wp2+bp2); qs2; s2eh
__global__ __launch_bounds__(256) void k4_kernel(
        const float* __restrict__ Wrel, const float* __restrict__ brel,
        const float* __restrict__ Wroot, const float* __restrict__ Wp2,
        const float* __restrict__ bp2){
    __shared__ float Wr[32][33], Wo[32][33], Wp[32][17];
    __shared__ float brs[32], bps[16];
    __shared__ float Ys[64][33], Xs[64][33], x2s[64][33], lgS[64][17];
    int tid = threadIdx.x;
    for(int i=tid;i<1024;i+=256){ int k=i>>5,c=i&31; Wr[k][c]=Wrel[i]; Wo[k][c]=Wroot[i]; }
    for(int i=tid;i<512;i+=256){ int k=i>>4,c=i&15; Wp[k][c]=Wp2[i]; }
    if(tid<32) brs[tid]=brel[tid];
    if(tid<16) bps[tid]=bp2[tid];
    int rowbase = blockIdx.x*64;
    for(int i=tid;i<2048;i+=256){ int r=i>>5,c=i&31;
        Ys[r][c]=g_Y[(rowbase+r)*32+c]; Xs[r][c]=g_x1[(rowbase+r)*32+c]; }
    __syncthreads();
    {
        int col = tid & 31, rg = tid >> 5;
        float a8[8];
        #pragma unroll
        for(int rr=0;rr<8;rr++) a8[rr] = brs[col];
        #pragma unroll
        for(int k=0;k<32;k++){
            float wrv = Wr[k][col], wo = Wo[k][col];
            #pragma unroll
            for(int rr=0;rr<8;rr++){
                int row = rg*8+rr;
                a8[rr] += Ys[row][k]*wrv + Xs[row][k]*wo;
            }
        }
        #pragma unroll
        for(int rr=0;rr<8;rr++){
            int row = rg*8+rr;
            x2s[row][col] = a8[rr];
            g_x2[(rowbase+row)*32+col] = a8[rr];
        }
    }
    __syncthreads();
    {
        int row = tid>>2, cq = tid&3;
        float lg[4];
        #pragma unroll
        for(int c=0;c<4;c++) lg[c]=bps[cq*4+c];
        #pragma unroll
        for(int k=0;k<32;k++){
            float xv = x2s[row][k];
            #pragma unroll
            for(int c=0;c<4;c++) lg[c] += xv*Wp[k][cq*4+c];
        }
        #pragma unroll
        for(int c=0;c<4;c++) lgS[row][cq*4+c]=lg[c];
    }
    __syncthreads();
    if(tid<64){
        int row = tid, grow = rowbase + row;
        float m = lgS[row][0];
        #pragma unroll
        for(int j=1;j<16;j++) m = fmaxf(m, lgS[row][j]);
        float e[16], sum=0.f;
        #pragma unroll
        for(int j=0;j<16;j++){ e[j]=expf(lgS[row][j]-m); sum+=e[j]; }
        float inv = 1.0f/sum, q=0.f;
        #pragma unroll
        for(int j=0;j<16;j++){
            float pv = e[j]*inv;
            g_s2[grow*16+j]=pv;
            g_s2eh[grow*32+j]=__float2half(pv);
            q += pv*pv;
        }
        g_s2eh[grow*32+16]=__float2half(1.0f);
        #pragma unroll
        for(int j=17;j<32;j++) g_s2eh[grow*32+j]=__float2half(0.0f);
        g_qs2[grow]=q;
    }
}

// red += s2^T [P(0:16)|s2|x2] over 128-row slices ; den2 partial folded in
__global__ void k6a_kernel(){
    int b = blockIdx.y, tid = threadIdx.x;      // 256
    int rb = blockIdx.x*128;
    int k = tid >> 4, cg = tid & 15;
    __shared__ float Mc[32][68];
    float acc[4] = {0,0,0,0};
    float dp = 0.f;
    for(int ch=0;ch<4;ch++){
        int base = b*NN + rb + ch*32;
        __syncthreads();
        for(int i=tid;i<32*64;i+=256){
            int r=i>>6, c=i&63;
            int row = base + r;
            float v;
            if(c<16) v = g_P[row*32 + c];
            else if(c<32) v = g_s2[row*16 + (c-16)];
            else v = g_x2[row*32 + (c-32)];
            Mc[r][c] = v;
        }
        __syncthreads();
        if(tid<32) dp += (g_P[(base+tid)*32+16] + EPSF)*g_qs2[base+tid];
        #pragma unroll 4
        for(int r=0;r<32;r++){
            float s2v = Mc[r][16+k];
            float4 m = *(const float4*)&Mc[r][cg*4];
            acc[0] += s2v*m.x; acc[1] += s2v*m.y; acc[2] += s2v*m.z; acc[3] += s2v*m.w;
        }
    }
    #pragma unroll
    for(int j=0;j<4;j++)
        atomicAdd(&g_red[b*1024 + k*64 + cg*4 + j], acc[j]);
    dp = blockReduceSum(dp);
    if(tid==0) atomicAdd(&g_den2[b], dp);
}

// per-batch tail: tdd, ortho1, ortho2, mincut-normalize + conv2 + MLP + log_softmax
__global__ void tail_kernel(const float* __restrict__ Wrel2, const float* __restrict__ brel2,
                            const float* __restrict__ Wroot2,
                            const float* __restrict__ W2, const float* __restrict__ b2,
                            const float* __restrict__ W3, const float* __restrict__ b3,
                            float* __restrict__ out){
    int tid = threadIdx.x;                       // 256
    int b = blockIdx.x;
    float td = 0.f;
    for(int n=tid;n<NN;n+=256) td += g_dflat[b*NN+n]*g_qn[b*NN+n];
    td = blockReduceSum(td);
    if(tid==0) g_tdd[b] = td;
    {
        const float* ssb = g_ss + b*KC*KC;
        float p = 0.f;
        for(int i=tid;i<KC*KC;i+=256){ float x=ssb[i]; p += x*x; }
        float ssn = sqrtf(blockReduceSum(p));
        float inv = 1.0f/ssn;
        p = 0.f;
        for(int i=tid;i<KC*KC;i+=256){
            float d = ssb[i]*inv - ((i%(KC+1))==0 ? 1.0f : 0.0f);
            p += d*d;
        }
        p = blockReduceSum(p);
        if(tid==0) g_o1b[b] = p;
    }
    {
        float x = g_red[b*1024 + (tid>>4)*64 + 16 + (tid&15)];
        float ssn2 = sqrtf(blockReduceSum(x*x));
        float d = x/ssn2 - ((tid%17)==0 ? 0.25f : 0.0f);
        float fb = blockReduceSum(d*d);
        if(tid==0) g_o2b[b] = sqrtf(fb);
    }
    __shared__ float oa[16][17];
    __shared__ float dk[16], ca[16], mS[32], oS[32], xsum[32], hsh[32], lsh[16];
    { int k=tid>>4, l=tid&15; float x=g_red[b*1024 + k*64 + l]; if(k==l) x=0.f; oa[k][l]=x; }
    __syncthreads();
    if(tid<16){
        float rs=0.f; for(int l=0;l<16;l++) rs += oa[tid][l];
        dk[tid] = sqrtf(rs + EPSF) + EPSF;
    }
    __syncthreads();
    { int k=tid>>4, l=tid&15; oa[k][l] = oa[k][l]/(dk[k]*dk[l]); }
    __syncthreads();
    if(tid<16){ float c=0.f; for(int k=0;k<16;k++) c += oa[k][tid]; ca[tid]=c; }
    __syncthreads();
    if(tid<32){
        float m=0.f, o=0.f;
        for(int l=0;l<16;l++){ float ox=g_red[b*1024 + l*64 + 32 + tid]; m += ca[l]*ox; o += ox; }
        mS[tid]=m; oS[tid]=o;
    }
    __syncthreads();
    if(tid<32){
        float x = 16.0f*brel2[tid];
        for(int g=0;g<32;g++) x += mS[g]*Wrel2[g*32+tid] + oS[g]*Wroot2[g*32+tid];
        xsum[tid] = x;
    }
    __syncthreads();
    if(tid<32){
        float h = b2[tid];
        for(int g=0;g<32;g++) h += xsum[g]*W2[g*32+tid];
        hsh[tid] = fmaxf(h, 0.f);
    }
    __syncthreads();
    if(tid<10){
        float lg = b3[tid];
        for(int g=0;g<32;g++) lg += hsh[g]*W3[g*10+tid];
        lsh[tid] = lg;
    }
    __syncthreads();
    if(tid==0){
        float m = lsh[0];
        for(int o=1;o<10;o++) m = fmaxf(m, lsh[o]);
        float s = 0.f;
        for(int o=0;o<10;o++) s += expf(lsh[o]-m);
        float lse = m + logf(s);
        for(int o=0;o<10;o++) out[b*10+o] = lsh[o]-lse;
    }
}

__global__ void loss_kernel(float* __restrict__ out){
    int tid = threadIdx.x;                       // 256
    float v = 0.f;
    if(tid<BB){
        float tddf = g_tdd[tid];
        v = (tddf - g_tda[tid])/(tddf + EPSF);
    }
    float ct_loss = blockReduceSum(v)*(1.0f/BB);
    v = (tid<BB) ? g_o1b[tid] : 0.f;
    float ortho1 = sqrtf(blockReduceSum(v));
    v = 0.f;
    if(tid<BB){
        float num = 0.f;
        for(int k=0;k<K2C;k++) num += g_red[tid*1024 + k*64 + k];
        v = -num/g_den2[tid];
    }
    float mc_loss = blockReduceSum(v)*(1.0f/BB);
    v = (tid<BB) ? g_o2b[tid] : 0.f;
    float ortho2 = blockReduceSum(v)*(1.0f/BB);
    if(tid==0){ out[160] = ct_loss + ortho1; out[161] = mc_loss + ortho2; }
}

// ---------------- launch ----------------
extern "C" void kernel_launch(void* const* d_in, const int* in_sizes, int n_in,
                              void* d_out, int out_size){
    const float* x       = (const float*)d_in[0];
    const float* adj     = (const float*)d_in[1];
    const float* W_lin1  = (const float*)d_in[3];
    const float* b_lin1  = (const float*)d_in[4];
    const float* W_pool1 = (const float*)d_in[5];
    const float* b_pool1 = (const float*)d_in[6];
    const float* W_pool2 = (const float*)d_in[7];
    const float* b_pool2 = (const float*)d_in[8];
    const float* Wrel1   = (const float*)d_in[9];
    const float* brel1   = (const float*)d_in[10];
    const float* Wroot1  = (const float*)d_in[11];
    const float* Wrel2   = (const float*)d_in[12];
    const float* brel2   = (const float*)d_in[13];
    const float* Wroot2  = (const float*)d_in[14];
    const float* W_lin2  = (const float*)d_in[15];
    const float* b_lin2  = (const float*)d_in[16];
    const float* W_lin3  = (const float*)d_in[17];
    const float* b_lin3  = (const float*)d_in[18];
    float* out = (float*)d_out;

    zero_kernel<<<64,256>>>();
    lin1pool_kernel<<<BB*NN/64, 128>>>(x, W_lin1, b_lin1, W_pool1, b_pool1);
    ct_main_kernel<<<dim3(8,8,BB), 256>>>(adj);
    bmm_Y_kernel<<<dim3(16,BB), 256>>>();
    k4_kernel<<<BB*NN/64, 256>>>(Wrel1, brel1, Wroot1, W_pool2, b_pool2);
    bmm_P_kernel<<<dim3(16,BB), 256>>>();
    k6a_kernel<<<dim3(8,BB), 256>>>();
    tail_kernel<<<BB, 256>>>(Wrel2, brel2, Wroot2, W_lin2, b_lin2, W_lin3, b_lin3, out);
    loss_kernel<<<1, 256>>>(out);
}

// round 16
// speedup vs baseline: 3.5505x; 1.0868x over previous
#include <cuda_runtime.h>
#include <cuda_fp16.h>
#include <math.h>
#include <stdint.h>

#define BB 16
#define NN 1024
#define FIN 128
#define HH 32
#define KC 64
#define K2C 16
#define EPSF 1e-15f

// ---------------- device scratch ----------------
__device__ float g_x1[BB*NN*HH];
__device__ __half g_x1h[BB*NN*HH];
__device__ __half g_sh[BB*NN*KC];         // tanh(s1) fp16 (MMA operand)
__device__ float g_qn[BB*NN];
__device__ float g_dflat[BB*NN];          // rowsum(adj), atomic
__device__ float g_vol[BB];               // atomic
__device__ float g_tda[BB];               // atomic
__device__ float g_tdd[BB];
__device__ __half g_T[(size_t)BB*NN*NN];  // cdist*adj (fp16, no /vol)
__device__ float g_Y[BB*NN*HH];
__device__ float g_x2[BB*NN*HH];
__device__ float g_s2[BB*NN*K2C];
__device__ __half g_s2eh[BB*NN*32];       // [s2 | 1 | 0...] fp16
__device__ float g_qs2[BB*NN];
__device__ float g_P[BB*NN*32];
__device__ float g_ss[BB*KC*KC];          // atomic
__device__ float g_red[BB*16*64];         // atomic: c<16 oadj | 16..31 ss2 | 32..63 outx
__device__ float g_den2[BB];              // atomic
__device__ float g_o1b[BB];
__device__ float g_o2b[BB];

// ---------------- helpers ----------------
__device__ __forceinline__ float blockReduceSum(float v){
    __shared__ float sh[32];
    int tid = threadIdx.x;
    int nth = blockDim.x;
    int lane = tid & 31, wid = tid >> 5;
    __syncthreads();
    #pragma unroll
    for(int o=16;o;o>>=1) v += __shfl_down_sync(0xffffffffu, v, o);
    if(lane==0) sh[wid] = v;
    __syncthreads();
    float r = (tid < (nth>>5)) ? sh[tid] : 0.f;
    if(wid==0){
        #pragma unroll
        for(int o=16;o;o>>=1) r += __shfl_down_sync(0xffffffffu, r, o);
        if(lane==0) sh[0] = r;
    }
    __syncthreads();
    return sh[0];
}

__device__ __forceinline__ uint32_t smem_u32(const void* p){
    uint32_t a;
    asm("{ .reg .u64 t; cvta.to.shared.u64 t, %1; cvt.u32.u64 %0, t; }" : "=r"(a) : "l"(p));
    return a;
}
__device__ __forceinline__ void ldsm_x4(uint32_t&r0,uint32_t&r1,uint32_t&r2,uint32_t&r3,uint32_t a){
    asm volatile("ldmatrix.sync.aligned.m8n8.x4.shared.b16 {%0,%1,%2,%3}, [%4];"
        :"=r"(r0),"=r"(r1),"=r"(r2),"=r"(r3):"r"(a));
}
__device__ __forceinline__ void ldsm_x4_t(uint32_t&r0,uint32_t&r1,uint32_t&r2,uint32_t&r3,uint32_t a){
    asm volatile("ldmatrix.sync.aligned.m8n8.x4.trans.shared.b16 {%0,%1,%2,%3}, [%4];"
        :"=r"(r0),"=r"(r1),"=r"(r2),"=r"(r3):"r"(a));
}
__device__ __forceinline__ void mma16816(float* c, uint32_t a0,uint32_t a1,uint32_t a2,uint32_t a3,
                                         uint32_t b0,uint32_t b1){
    asm volatile("mma.sync.aligned.m16n8k16.row.col.f32.f16.f16.f32 "
        "{%0,%1,%2,%3}, {%4,%5,%6,%7}, {%8,%9}, {%0,%1,%2,%3};"
        : "+f"(c[0]),"+f"(c[1]),"+f"(c[2]),"+f"(c[3])
        : "r"(a0),"r"(a1),"r"(a2),"r"(a3),"r"(b0),"r"(b1));
}
__device__ __forceinline__ void cp_async16(uint32_t smem_addr, const void* gptr){
    asm volatile("cp.async.ca.shared.global [%0], [%1], 16;" :: "r"(smem_addr), "l"(gptr));
}
__device__ __forceinline__ void cp_commit(){ asm volatile("cp.async.commit_group;" ::: "memory"); }
template<int N> __device__ __forceinline__ void cp_wait(){ asm volatile("cp.async.wait_group %0;" :: "n"(N) : "memory"); }

// ---------------- kernels ----------------
__global__ void zero_kernel(){
    int t = blockIdx.x*256 + threadIdx.x;
    int stride = gridDim.x*256;
    for(int i=t;i<BB;i+=stride){ g_tda[i]=0.f; g_vol[i]=0.f; g_den2[i]=0.f; }
    for(int i=t;i<BB*NN;i+=stride) g_dflat[i]=0.f;
    for(int i=t;i<BB*KC*KC;i+=stride) g_ss[i]=0.f;
    for(int i=t;i<BB*16*64;i+=stride) g_red[i]=0.f;
}

// Fused: x1 = x@W1+b1 ; s = tanh(x1@Wp+bp) (fp16 out); qn; ss += s^T s (atomics)
__global__ __launch_bounds__(128) void lin1pool_kernel(
        const float* __restrict__ x, const float* __restrict__ W1, const float* __restrict__ b1,
        const float* __restrict__ Wp, const float* __restrict__ bp){
    __shared__ float Ws[FIN][36];
    __shared__ float xt[2][32][68];
    __shared__ float Wps[HH][68];
    __shared__ float bps[KC];
    __shared__ float x1s[64][33];
    __shared__ float sS[64][68];
    int tid = threadIdx.x;                 // 128
    int colg = tid & 7, rowg = tid >> 3;
    int rowbase = blockIdx.x*64;
    int b = rowbase >> 10;
    for(int i=tid;i<FIN*32;i+=128){ int k=i>>5,c=i&31; Ws[k][c]=W1[i]; }
    for(int i=tid;i<HH*KC;i+=128){ int k=i>>6,c=i&63; Wps[k][c]=Wp[i]; }
    if(tid<KC) bps[tid]=bp[tid];
    for(int i=tid;i<2048;i+=128){ int r=i>>5,k=i&31; xt[0][k][r]=x[(size_t)(rowbase+r)*FIN + k]; }
    float acc[4][4] = {};
    #pragma unroll
    for(int kc=0;kc<4;kc++){
        __syncthreads();
        if(kc<3){
            int nb=(kc+1)&1;
            for(int i=tid;i<2048;i+=128){ int r=i>>5,k=i&31; xt[nb][k][r]=x[(size_t)(rowbase+r)*FIN + (kc+1)*32 + k]; }
        }
        int cb=kc&1;
        #pragma unroll
        for(int k=0;k<32;k++){
            float4 a = *(const float4*)&xt[cb][k][rowg*4];
            float4 w = *(const float4*)&Ws[kc*32+k][colg*4];
            float av[4]={a.x,a.y,a.z,a.w}, wv[4]={w.x,w.y,w.z,w.w};
            #pragma unroll
            for(int i=0;i<4;i++)
                #pragma unroll
                for(int j=0;j<4;j++) acc[i][j] += av[i]*wv[j];
        }
    }
    float4 bb = *(const float4*)&b1[colg*4];
    float bv[4]={bb.x,bb.y,bb.z,bb.w};
    #pragma unroll
    for(int i=0;i<4;i++){
        int lr = rowg*4+i;
        float4 res = make_float4(acc[i][0]+bv[0],acc[i][1]+bv[1],acc[i][2]+bv[2],acc[i][3]+bv[3]);
        *(float4*)&g_x1[(rowbase+lr)*HH + colg*4] = res;
        __align__(8) __half2 hh[2];
        hh[0]=__floats2half2_rn(res.x,res.y); hh[1]=__floats2half2_rn(res.z,res.w);
        *(uint2*)&g_x1h[(rowbase+lr)*HH + colg*4] = *(uint2*)hh;
        x1s[lr][colg*4+0]=res.x; x1s[lr][colg*4+1]=res.y;
        x1s[lr][colg*4+2]=res.z; x1s[lr][colg*4+3]=res.w;
    }
    __syncthreads();
    // pool phase
    {
        int r = tid>>1, half = tid&1;
        int cb2 = half*32;
        float sv[32];
        #pragma unroll
        for(int c=0;c<32;c++) sv[c]=bps[cb2+c];
        #pragma unroll
        for(int k=0;k<32;k++){
            float xk = x1s[r][k];
            #pragma unroll
            for(int c4=0;c4<8;c4++){
                float4 w = *(const float4*)&Wps[k][cb2+c4*4];
                sv[c4*4+0] += xk*w.x; sv[c4*4+1] += xk*w.y;
                sv[c4*4+2] += xk*w.z; sv[c4*4+3] += xk*w.w;
            }
        }
        float q = 0.f;
        int grow = rowbase + r;
        #pragma unroll
        for(int c=0;c<32;c++){ float s=tanhf(sv[c]); sv[c]=s; q += s*s; }
        #pragma unroll
        for(int c4=0;c4<8;c4++){
            float4 res = make_float4(sv[c4*4],sv[c4*4+1],sv[c4*4+2],sv[c4*4+3]);
            __align__(8) __half2 hh[2];
            hh[0]=__floats2half2_rn(res.x,res.y); hh[1]=__floats2half2_rn(res.z,res.w);
            *(uint2*)&g_sh[grow*KC + cb2 + c4*4] = *(uint2*)hh;
            *(float4*)&sS[r][cb2 + c4*4] = res;
        }
        q += __shfl_xor_sync(0xffffffffu, q, 1);
        if(half==0) g_qn[grow] = q;
    }
    __syncthreads();
    // ss phase (fp32)
    {
        int kg = tid>>3, lg = tid&7;
        float accs[4][8] = {};
        #pragma unroll 4
        for(int r=0;r<64;r++){
            float4 a  = *(const float4*)&sS[r][kg*4];
            float4 c0 = *(const float4*)&sS[r][lg*4];
            float4 c1 = *(const float4*)&sS[r][lg*4+32];
            float av[4]={a.x,a.y,a.z,a.w};
            float cv[8]={c0.x,c0.y,c0.z,c0.w,c1.x,c1.y,c1.z,c1.w};
            #pragma unroll
            for(int i=0;i<4;i++)
                #pragma unroll
                for(int j=0;j<8;j++) accs[i][j] += av[i]*cv[j];
        }
        #pragma unroll
        for(int i=0;i<4;i++)
            #pragma unroll
            for(int j=0;j<8;j++){
                int col = (j<4) ? lg*4+j : lg*4+32+(j-4);
                atomicAdd(&g_ss[(b*KC + kg*4+i)*KC + col], accs[i][j]);
            }
    }
}

// ct_main: per-block 128x128 tile. fp16 MMA Gram -> cdist -> T(fp16)
// adj consumed via cp.async ping-pong chunks (16 rows); T staged in smem for
// coalesced writes. accumulates tda, dflat, vol. grid (8,8,BB), 256 thr.
__global__ __launch_bounds__(256,2) void ct_main_kernel(const float* __restrict__ adj){
    __shared__ __align__(16) char smbuf[36864];     // Srow|Scol during MMA; adj1|Tst after
    __shared__ __align__(16) float adj0[16][132];   // 8448B
    __shared__ float qa[128], qb[128];
    int b = blockIdx.z;
    int rowbase = blockIdx.y*128, colbase = blockIdx.x*128;
    int tid = threadIdx.x, w = tid>>5, lane = tid&31;
    int wr = (w>>2)*64, wc = (w&3)*32;
    const __half* Sh = g_sh + b*NN*KC;
    uint32_t sr_base = smem_u32(smbuf);             // Srow: 128x72 half
    uint32_t sc_base = sr_base + 18432;             // Scol: 128x72 half
    uint32_t adj1_b  = sr_base;                     // alias: adj1 16x132 float
    uint32_t tst_b   = sc_base;                     // alias: Tst 16x136 half
    uint32_t adj0_b  = smem_u32(&adj0[0][0]);
    // G0: S tiles
    for(int i=tid;i<1024;i+=256){
        int r=i>>3, q=i&7;
        cp_async16(sr_base + (r*72+q*8)*2, &Sh[(rowbase+r)*KC + q*8]);
        cp_async16(sc_base + (r*72+q*8)*2, &Sh[(colbase+r)*KC + q*8]);
    }
    cp_commit();
    const float* Ap = adj + (size_t)b*NN*NN;
    // G1: adj chunk 0 -> adj0 (overlaps MMA)
    #pragma unroll
    for(int j=0;j<2;j++){
        int idx = tid + 256*j;
        int r = idx>>5, q = idx&31;
        cp_async16(adj0_b + (r*132+q*4)*4, &Ap[(size_t)(rowbase+r)*NN + colbase + q*4]);
    }
    cp_commit();
    if(tid<128) qa[tid] = g_qn[b*NN+rowbase+tid];
    else qb[tid-128] = g_qn[b*NN+colbase+(tid-128)];
    cp_wait<1>();          // S tiles ready; chunk0 may still be in flight
    __syncthreads();
    // MMA phase: warp tile 64x32
    float cf[4][4][4] = {};
    int a_row = lane & 15, a_half = lane >> 4;
    int b_row = (lane&7) + ((lane>>4)&1)*8;
    int b_koff = ((lane>>3)&1)*8;
    #pragma unroll
    for(int kk=0;kk<4;kk++){
        uint32_t a[4][4];
        #pragma unroll
        for(int mt=0;mt<4;mt++)
            ldsm_x4(a[mt][0],a[mt][1],a[mt][2],a[mt][3],
                sr_base + ((wr + mt*16 + a_row)*72 + kk*16 + a_half*8)*2);
        #pragma unroll
        for(int ng=0;ng<2;ng++){
            uint32_t b0,b1,b2,b3;
            ldsm_x4(b0,b1,b2,b3,
                sc_base + ((wc + ng*16 + b_row)*72 + kk*16 + b_koff)*2);
            #pragma unroll
            for(int mt=0;mt<4;mt++){
                mma16816(cf[mt][ng*2],   a[mt][0],a[mt][1],a[mt][2],a[mt][3], b0,b1);
                mma16816(cf[mt][ng*2+1], a[mt][0],a[mt][1],a[mt][2],a[mt][3], b2,b3);
            }
        }
    }
    __syncthreads();   // all ldsm reads done: S-tile region reusable (adj1/Tst)
    // epilogue: 8 chunks of 16 rows, ping-pong adj buffers, staged T writes
    float tda = 0.f, volp = 0.f;
    __half* Tp = g_T + (size_t)b*NN*NN;
    int r_in = lane>>2, c_in = (lane&3)*2;
    int rgrp_w = w>>2;
    #pragma unroll
    for(int ch=0;ch<8;ch++){
        if(ch+1<8){
            uint32_t dst = ((ch+1)&1) ? adj1_b : adj0_b;
            #pragma unroll
            for(int j=0;j<2;j++){
                int idx = tid + 256*j;
                int r = idx>>5, q = idx&31;
                cp_async16(dst + (r*132+q*4)*4,
                           &Ap[(size_t)(rowbase+(ch+1)*16+r)*NN + colbase + q*4]);
            }
            cp_commit();
            cp_wait<1>();
        } else {
            cp_wait<0>();
        }
        __syncthreads();
        // process chunk ch (active: warps with w>>2 == ch>>2)
        if(rgrp_w == (ch>>2)){
            int mt = ch&3;
            uint32_t src = (ch&1) ? adj1_b : adj0_b;
            #pragma unroll
            for(int h=0;h<2;h++){
                int lr = r_in + h*8;
                int row = rowbase + ch*16 + lr;
                float qai = qa[ch*16 + lr];
                float rp = 0.f;
                #pragma unroll
                for(int nt=0;nt<4;nt++){
                    int lc = wc + nt*8 + c_in;
                    float2 aj;
                    asm volatile("ld.shared.v2.f32 {%0,%1}, [%2];"
                        : "=f"(aj.x), "=f"(aj.y) : "r"(src + (lr*132+lc)*4));
                    float g0 = cf[mt][nt][h*2+0];
                    float g1 = cf[mt][nt][h*2+1];
                    float d0 = qai + qb[lc]   - 2.0f*g0;
                    float d1 = qai + qb[lc+1] - 2.0f*g1;
                    float r0 = sqrtf(fmaxf(d0, 0.f))*aj.x;
                    float r1 = sqrtf(fmaxf(d1, 0.f))*aj.y;
                    tda += aj.x*g0 + aj.y*g1;
                    rp  += aj.x + aj.y;
                    __half2 hv = __floats2half2_rn(r0, r1);
                    asm volatile("st.shared.b32 [%0], %1;"
                        :: "r"(tst_b + (lr*136+lc)*2), "r"(*(uint32_t*)&hv));
                }
                volp += rp;
                rp += __shfl_down_sync(0xffffffffu, rp, 1, 4);
                rp += __shfl_down_sync(0xffffffffu, rp, 2, 4);
                if((lane&3)==0) atomicAdd(&g_dflat[b*NN + row], rp);
            }
        }
        __syncthreads();
        // coalesced copy Tst -> global (all 256 threads, 16B each)
        {
            int row16 = tid>>4, q = tid&15;
            uint4 v;
            asm volatile("ld.shared.v4.b32 {%0,%1,%2,%3}, [%4];"
                : "=r"(v.x),"=r"(v.y),"=r"(v.z),"=r"(v.w)
                : "r"(tst_b + (row16*136 + q*8)*2));
            *(uint4*)&Tp[(size_t)(rowbase + ch*16 + row16)*NN + colbase + q*8] = v;
        }
        __syncthreads();
    }
    volp = blockReduceSum(volp);
    if(tid==0) atomicAdd(&g_vol[b], volp);
    tda = blockReduceSum(tda);
    if(tid==0) atomicAdd(&g_tda[b], tda);
}

// O[b] = invvol * (T[b] @ Xh[b]) via mma.m16n8k16 + cp.async 3-stage pipeline
#define BST 3
__device__ __forceinline__ void bmm_mma(const __half* __restrict__ Xh, float* __restrict__ O){
    __shared__ __align__(16) __half At[BST][64][72];
    __shared__ __align__(16) __half Xs[BST][64][40];
    int b = blockIdx.y, rowbase = blockIdx.x*64;
    int tid = threadIdx.x;
    int w = tid>>5, lane = tid&31;
    int wr = (w&3)*16, wc = (w>>2)*16;
    const __half* Ab = g_T + (size_t)b*NN*NN;
    const __half* Xb = Xh + (size_t)b*NN*32;
    float c[2][4] = {};
    uint32_t at_base = smem_u32(&At[0][0][0]);
    uint32_t xs_base = smem_u32(&Xs[0][0][0]);
    int tr0 = tid>>3,        tq0 = tid&7;
    int tr1 = (tid+256)>>3,  tq1 = (tid+256)&7;
    int xr  = tid>>2,        xq  = tid&3;
    #pragma unroll
    for(int s=0;s<BST;s++){
        size_t ko = (size_t)s*64;
        cp_async16(at_base + (s*64*72 + tr0*72 + tq0*8)*2, &Ab[(size_t)(rowbase+tr0)*NN + ko + tq0*8]);
        cp_async16(at_base + (s*64*72 + tr1*72 + tq1*8)*2, &Ab[(size_t)(rowbase+tr1)*NN + ko + tq1*8]);
        cp_async16(xs_base + (s*64*40 + xr*40 + xq*8)*2,   &Xb[(ko+xr)*32 + xq*8]);
        cp_commit();
    }
    int a_row = lane & 15, a_half = lane >> 4;
    int b_t = lane >> 3, b_row = lane & 7;
    for(int kt=0;kt<16;kt++){
        cp_wait<BST-1>();
        __syncthreads();
        int cs = kt%BST;
        uint32_t atb = at_base + cs*(64*72*2);
        uint32_t xsb = xs_base + cs*(64*40*2);
        #pragma unroll
        for(int kk=0;kk<4;kk++){
            uint32_t a0,a1,a2,a3;
            ldsm_x4(a0,a1,a2,a3, atb + ((wr + a_row)*72 + kk*16 + a_half*8)*2);
            uint32_t b0,b1,b2,b3;
            ldsm_x4_t(b0,b1,b2,b3, xsb + ((kk*16 + b_row + (b_t&1)*8)*40 + wc + (b_t>>1)*8)*2);
            mma16816(c[0], a0,a1,a2,a3, b0,b1);
            mma16816(c[1], a0,a1,a2,a3, b2,b3);
        }
        __syncthreads();
        if(kt+BST<16){
            int s = (kt+BST)%BST;
            size_t ko = (size_t)(kt+BST)*64;
            cp_async16(at_base + (s*64*72 + tr0*72 + tq0*8)*2, &Ab[(size_t)(rowbase+tr0)*NN + ko + tq0*8]);
            cp_async16(at_base + (s*64*72 + tr1*72 + tq1*8)*2, &Ab[(size_t)(rowbase+tr1)*NN + ko + tq1*8]);
            cp_async16(xs_base + (s*64*40 + xr*40 + xq*8)*2,   &Xb[(ko+xr)*32 + xq*8]);
            cp_commit();
        }
    }
    float iv = 1.0f/(g_vol[b] + (float)NN*EPSF);
    float* Ob = O + (size_t)b*NN*32;
    int row0 = rowbase + wr + (lane>>2);
    int col0 = wc + (lane&3)*2;
    #pragma unroll
    for(int t=0;t<2;t++){
        *(float2*)&Ob[(size_t)row0*32 + t*8 + col0]     = make_float2(c[t][0]*iv, c[t][1]*iv);
        *(float2*)&Ob[(size_t)(row0+8)*32 + t*8 + col0] = make_float2(c[t][2]*iv, c[t][3]*iv);
    }
}

__global__ __launch_bounds__(256) void bmm_Y_kernel(){ bmm_mma(g_x1h, g_Y); }
__global__ __launch_bounds__(256) void bmm_P_kernel(){ bmm_mma(g_s2eh, g_P); }

// x2 = (Y@Wrel + brel) + x1@Wroot ; s2 = softmax(x2@Wp2+bp2); qs2; s2eh
__global__ __launch_bounds__(256) void k4_kernel(
        const float* __restrict__ Wrel, const float* __restrict__ brel,
        const float* __restrict__ Wroot, const float* __restrict__ Wp2,
        const float* __restrict__ bp2){
    __shared__ float Wr[32][33], Wo[32][33], Wp[32][17];
    __shared__ float brs[32], bps[16];
    __shared__ float Ys[64][33], Xs[64][33], x2s[64][33], lgS[64][17];
    int tid = threadIdx.x;
    for(int i=tid;i<1024;i+=256){ int k=i>>5,c=i&31; Wr[k][c]=Wrel[i]; Wo[k][c]=Wroot[i]; }
    for(int i=tid;i<512;i+=256){ int k=i>>4,c=i&15; Wp[k][c]=Wp2[i]; }
    if(tid<32) brs[tid]=brel[tid];
    if(tid<16) bps[tid]=bp2[tid];
    int rowbase = blockIdx.x*64;
    for(int i=tid;i<2048;i+=256){ int r=i>>5,c=i&31;
        Ys[r][c]=g_Y[(rowbase+r)*32+c]; Xs[r][c]=g_x1[(rowbase+r)*32+c]; }
    __syncthreads();
    {
        int col = tid & 31, rg = tid >> 5;
        float a8[8];
        #pragma unroll
        for(int rr=0;rr<8;rr++) a8[rr] = brs[col];
        #pragma unroll
        for(int k=0;k<32;k++){
            float wrv = Wr[k][col], wo = Wo[k][col];
            #pragma unroll
            for(int rr=0;rr<8;rr++){
                int row = rg*8+rr;
                a8[rr] += Ys[row][k]*wrv + Xs[row][k]*wo;
            }
        }
        #pragma unroll
        for(int rr=0;rr<8;rr++){
            int row = rg*8+rr;
            x2s[row][col] = a8[rr];
            g_x2[(rowbase+row)*32+col] = a8[rr];
        }
    }
    __syncthreads();
    {
        int row = tid>>2, cq = tid&3;
        float lg[4];
        #pragma unroll
        for(int c=0;c<4;c++) lg[c]=bps[cq*4+c];
        #pragma unroll
        for(int k=0;k<32;k++){
            float xv = x2s[row][k];
            #pragma unroll
            for(int c=0;c<4;c++) lg[c] += xv*Wp[k][cq*4+c];
        }
        #pragma unroll
        for(int c=0;c<4;c++) lgS[row][cq*4+c]=lg[c];
    }
    __syncthreads();
    if(tid<64){
        int row = tid, grow = rowbase + row;
        float m = lgS[row][0];
        #pragma unroll
        for(int j=1;j<16;j++) m = fmaxf(m, lgS[row][j]);
        float e[16], sum=0.f;
        #pragma unroll
        for(int j=0;j<16;j++){ e[j]=expf(lgS[row][j]-m); sum+=e[j]; }
        float inv = 1.0f/sum, q=0.f;
        #pragma unroll
        for(int j=0;j<16;j++){
            float pv = e[j]*inv;
            g_s2[grow*16+j]=pv;
            g_s2eh[grow*32+j]=__float2half(pv);
            q += pv*pv;
        }
        g_s2eh[grow*32+16]=__float2half(1.0f);
        #pragma unroll
        for(int j=17;j<32;j++) g_s2eh[grow*32+j]=__float2half(0.0f);
        g_qs2[grow]=q;
    }
}

// red += s2^T [P(0:16)|s2|x2] over 64-row slices ; den2 partial folded in
__global__ void k6a_kernel(){
    int b = blockIdx.y, tid = threadIdx.x;      // 256
    int rb = blockIdx.x*64;
    int k = tid >> 4, cg = tid & 15;
    __shared__ float Mc[32][68];
    float acc[4] = {0,0,0,0};
    float dp = 0.f;
    for(int ch=0;ch<2;ch++){
        int base = b*NN + rb + ch*32;
        __syncthreads();
        for(int i=tid;i<32*64;i+=256){
            int r=i>>6, c=i&63;
            int row = base + r;
            float v;
            if(c<16) v = g_P[row*32 + c];
            else if(c<32) v = g_s2[row*16 + (c-16)];
            else v = g_x2[row*32 + (c-32)];
            Mc[r][c] = v;
        }
        __syncthreads();
        if(tid<32) dp += (g_P[(base+tid)*32+16] + EPSF)*g_qs2[base+tid];
        #pragma unroll 4
        for(int r=0;r<32;r++){
            float s2v = Mc[r][16+k];
            float4 m = *(const float4*)&Mc[r][cg*4];
            acc[0] += s2v*m.x; acc[1] += s2v*m.y; acc[2] += s2v*m.z; acc[3] += s2v*m.w;
        }
    }
    #pragma unroll
    for(int j=0;j<4;j++)
        atomicAdd(&g_red[b*1024 + k*64 + cg*4 + j], acc[j]);
    dp = blockReduceSum(dp);
    if(tid==0) atomicAdd(&g_den2[b], dp);
}

// per-batch tail: tdd, ortho1, ortho2, mincut-normalize + conv2 + MLP + log_softmax
__global__ void tail_kernel(const float* __restrict__ Wrel2, const float* __restrict__ brel2,
                            const float* __restrict__ Wroot2,
                            const float* __restrict__ W2, const float* __restrict__ b2,
                            const float* __restrict__ W3, const float* __restrict__ b3,
                            float* __restrict__ out){
    int tid = threadIdx.x;                       // 256
    int b = blockIdx.x;
    float td = 0.f;
    for(int n=tid;n<NN;n+=256) td += g_dflat[b*NN+n]*g_qn[b*NN+n];
    td = blockReduceSum(td);
    if(tid==0) g_tdd[b] = td;
    {
        const float* ssb = g_ss + b*KC*KC;
        float p = 0.f;
        for(int i=tid;i<KC*KC;i+=256){ float x=ssb[i]; p += x*x; }
        float ssn = sqrtf(blockReduceSum(p));
        float inv = 1.0f/ssn;
        p = 0.f;
        for(int i=tid;i<KC*KC;i+=256){
            float d = ssb[i]*inv - ((i%(KC+1))==0 ? 1.0f : 0.0f);
            p += d*d;
        }
        p = blockReduceSum(p);
        if(tid==0) g_o1b[b] = p;
    }
    {
        float x = g_red[b*1024 + (tid>>4)*64 + 16 + (tid&15)];
        float ssn2 = sqrtf(blockReduceSum(x*x));
        float d = x/ssn2 - ((tid%17)==0 ? 0.25f : 0.0f);
        float fb = blockReduceSum(d*d);
        if(tid==0) g_o2b[b] = sqrtf(fb);
    }
    __shared__ float oa[16][17];
    __shared__ float dk[16], ca[16], mS[32], oS[32], xsum[32], hsh[32], lsh[16];
    { int k=tid>>4, l=tid&15; float x=g_red[b*1024 + k*64 + l]; if(k==l) x=0.f; oa[k][l]=x; }
    __syncthreads();
    if(tid<16){
        float rs=0.f; for(int l=0;l<16;l++) rs += oa[tid][l];
        dk[tid] = sqrtf(rs + EPSF) + EPSF;
    }
    __syncthreads();
    { int k=tid>>4, l=tid&15; oa[k][l] = oa[k][l]/(dk[k]*dk[l]); }
    __syncthreads();
    if(tid<16){ float c=0.f; for(int k=0;k<16;k++) c += oa[k][tid]; ca[tid]=c; }
    __syncthreads();
    if(tid<32){
        float m=0.f, o=0.f;
        for(int l=0;l<16;l++){ float ox=g_red[b*1024 + l*64 + 32 + tid]; m += ca[l]*ox; o += ox; }
        mS[tid]=m; oS[tid]=o;
    }
    __syncthreads();
    if(tid<32){
        float x = 16.0f*brel2[tid];
        for(int g=0;g<32;g++) x += mS[g]*Wrel2[g*32+tid] + oS[g]*Wroot2[g*32+tid];
        xsum[tid] = x;
    }
    __syncthreads();
    if(tid<32){
        float h = b2[tid];
        for(int g=0;g<32;g++) h += xsum[g]*W2[g*32+tid];
        hsh[tid] = fmaxf(h, 0.f);
    }
    __syncthreads();
    if(tid<10){
        float lg = b3[tid];
        for(int g=0;g<32;g++) lg += hsh[g]*W3[g*10+tid];
        lsh[tid] = lg;
    }
    __syncthreads();
    if(tid==0){
        float m = lsh[0];
        for(int o=1;o<10;o++) m = fmaxf(m, lsh[o]);
        float s = 0.f;
        for(int o=0;o<10;o++) s += expf(lsh[o]-m);
        float lse = m + logf(s);
        for(int o=0;o<10;o++) out[b*10+o] = lsh[o]-lse;
    }
}

__global__ void loss_kernel(float* __restrict__ out){
    int tid = threadIdx.x;                       // 256
    float v = 0.f;
    if(tid<BB){
        float tddf = g_tdd[tid];
        v = (tddf - g_tda[tid])/(tddf + EPSF);
    }
    float ct_loss = blockReduceSum(v)*(1.0f/BB);
    v = (tid<BB) ? g_o1b[tid] : 0.f;
    float ortho1 = sqrtf(blockReduceSum(v));
    v = 0.f;
    if(tid<BB){
        float num = 0.f;
        for(int k=0;k<K2C;k++) num += g_red[tid*1024 + k*64 + k];
        v = -num/g_den2[tid];
    }
    float mc_loss = blockReduceSum(v)*(1.0f/BB);
    v = (tid<BB) ? g_o2b[tid] : 0.f;
    float ortho2 = blockReduceSum(v)*(1.0f/BB);
    if(tid==0){ out[160] = ct_loss + ortho1; out[161] = mc_loss + ortho2; }
}

// ---------------- launch ----------------
extern "C" void kernel_launch(void* const* d_in, const int* in_sizes, int n_in,
                              void* d_out, int out_size){
    const float* x       = (const float*)d_in[0];
    const float* adj     = (const float*)d_in[1];
    const float* W_lin1  = (const float*)d_in[3];
    const float* b_lin1  = (const float*)d_in[4];
    const float* W_pool1 = (const float*)d_in[5];
    const float* b_pool1 = (const float*)d_in[6];
    const float* W_pool2 = (const float*)d_in[7];
    const float* b_pool2 = (const float*)d_in[8];
    const float* Wrel1   = (const float*)d_in[9];
    const float* brel1   = (const float*)d_in[10];
    const float* Wroot1  = (const float*)d_in[11];
    const float* Wrel2   = (const float*)d_in[12];
    const float* brel2   = (const float*)d_in[13];
    const float* Wroot2  = (const float*)d_in[14];
    const float* W_lin2  = (const float*)d_in[15];
    const float* b_lin2  = (const float*)d_in[16];
    const float* W_lin3  = (const float*)d_in[17];
    const float* b_lin3  = (const float*)d_in[18];
    float* out = (float*)d_out;

    zero_kernel<<<64,256>>>();
    lin1pool_kernel<<<BB*NN/64, 128>>>(x, W_lin1, b_lin1, W_pool1, b_pool1);
    ct_main_kernel<<<dim3(8,8,BB), 256>>>(adj);
    bmm_Y_kernel<<<dim3(16,BB), 256>>>();
    k4_kernel<<<BB*NN/64, 256>>>(Wrel1, brel1, Wroot1, W_pool2, b_pool2);
    bmm_P_kernel<<<dim3(16,BB), 256>>>();
    k6a_kernel<<<dim3(16,BB), 256>>>();
    tail_kernel<<<BB, 256>>>(Wrel2, brel2, Wroot2, W_lin2, b_lin2, W_lin3, b_lin3, out);
    loss_kernel<<<1, 256>>>(out);
}